// round 3
// baseline (speedup 1.0000x reference)
#include <cuda_runtime.h>

#define BB 8
#define CIN 768
#define NP 4096
#define IC 128
#define MID 256
#define OC 20

typedef unsigned long long u64;

__device__ float g_wtpg[3*IC*CIN];
__device__ float g_C[OC*CIN];
__device__ float g_A[OC*IC];
__device__ float g_cvec[OC];
__device__ float g_thT[BB*NP*IC];
__device__ float g_phT[BB*NP*IC];
__device__ float g_gT [BB*NP*IC];

__device__ __forceinline__ void ffma2(u64& d, u64 a, u64 b){
    asm("fma.rn.f32x2 %0, %1, %2, %0;" : "+l"(d) : "l"(a), "l"(b));
}
__device__ __forceinline__ void fmul2(u64& d, u64 a){
    asm("mul.rn.f32x2 %0, %0, %1;" : "+l"(d) : "l"(a));
}
__device__ __forceinline__ float2 u2f(u64 v){
    float2 r; asm("mov.b64 {%0,%1}, %2;" : "=f"(r.x), "=f"(r.y) : "l"(v)); return r;
}
__device__ __forceinline__ u64 f2u(float x, float y){
    u64 r; asm("mov.b64 %0, {%1,%2};" : "=l"(r) : "f"(x), "f"(y)); return r;
}

__device__ __forceinline__ float fexp(float x){
    x = fmaxf(x, -80.f);
    float t = x * 1.4426950408889634f;
    float f = t + 12582912.f;
    float k = f - 12582912.f;
    float r = t - k;
    float p = 1.3333558e-3f;
    p = fmaf(p, r, 9.6181291e-3f);
    p = fmaf(p, r, 5.5504109e-2f);
    p = fmaf(p, r, 2.4022651e-1f);
    p = fmaf(p, r, 6.9314718e-1f);
    p = fmaf(p, r, 1.f);
    int ki = (int)k;
    return p * __int_as_float((ki + 127) << 23);
}

// ---------- prep: fold all weight algebra ----------
__global__ void __launch_bounds__(256) prep_kernel(
    const float* __restrict__ wc, const float* __restrict__ wt,
    const float* __restrict__ wp, const float* __restrict__ wg,
    const float* __restrict__ wW, const float* __restrict__ bW,
    const float* __restrict__ gam, const float* __restrict__ bet,
    const float* __restrict__ mean, const float* __restrict__ var,
    const float* __restrict__ wo, const float* __restrict__ bo)
{
    int gid = blockIdx.x*256 + threadIdx.x;
    if (gid < 3*IC*CIN) {
        int r = gid / CIN, k = gid % CIN;
        const float* ws = (r < IC) ? wt : (r < 2*IC) ? wp : wg;
        int rr = r & (IC-1);
        float acc = 0.f;
        for (int m = 0; m < MID; m++) acc = fmaf(ws[rr*MID+m], wc[m*CIN+k], acc);
        g_wtpg[gid] = acc;
        return;
    }
    int idx = gid - 3*IC*CIN;
    if (idx < OC*CIN) {
        int o = idx / CIN, k = idx % CIN;
        float acc = 0.f;
        for (int m = 0; m < MID; m++) acc = fmaf(wo[o*MID+m], wc[m*CIN+k], acc);
        g_C[idx] = acc;
        return;
    }
    idx -= OC*CIN;
    if (idx < OC*IC) {
        int o = idx / IC, i = idx % IC;
        float acc = 0.f;
        for (int m = 0; m < MID; m++) {
            float inv = gam[m] * rsqrtf(var[m] + 1e-5f);
            acc = fmaf(wo[o*MID+m]*inv, wW[m*IC+i], acc);
        }
        g_A[idx] = acc;
        return;
    }
    idx -= OC*IC;
    if (idx < OC) {
        float acc = bo[idx];
        for (int m = 0; m < MID; m++) {
            float inv = gam[m] * rsqrtf(var[m] + 1e-5f);
            acc += wo[idx*MID+m] * (bW[m]*inv + bet[m] - mean[m]*inv);
        }
        g_cvec[idx] = acc;
    }
}

// ---------- projections: theta/phi/g = Wfold @ x, stored [n][c] transposed ----------
__global__ void __launch_bounds__(256) proj_kernel(const float* __restrict__ x1,
                                                   const float* __restrict__ x2)
{
    __shared__ float Asd[128*36];
    __shared__ float Bs[16*128];
    int t = threadIdx.x, tx = t & 15, ty = t >> 4;
    int n0 = blockIdx.x * 128;
    int which = blockIdx.y;
    int b = blockIdx.z;
    const float* xb = (which == 0 ? x1 : x2) + (size_t)b * CIN * NP;
    int wrow0 = which * IC;
    float* dst = (which == 0 ? g_thT : which == 1 ? g_phT : g_gT) + (size_t)b * NP * IC;

    u64 acc[8][4];
    #pragma unroll
    for (int i=0;i<8;i++)
        #pragma unroll
        for (int j=0;j<4;j++) acc[i][j] = 0ull;

    for (int k0 = 0; k0 < CIN; k0 += 16) {
        #pragma unroll
        for (int i = 0; i < 8; i++) {
            int e = t + i*256;
            int row = e >> 4, kk = e & 15;
            float w = g_wtpg[(wrow0+row)*CIN + k0 + kk];
            Asd[row*36 + 2*kk]     = w;
            Asd[row*36 + 2*kk + 1] = w;
        }
        #pragma unroll
        for (int i = 0; i < 8; i++) {
            int e = t + i*256;
            int kk = e >> 7, n = e & 127;
            Bs[kk*128 + n] = xb[(size_t)(k0+kk)*NP + n0 + n];
        }
        __syncthreads();
        #pragma unroll
        for (int kk = 0; kk < 16; kk++) {
            u64 a2[8];
            #pragma unroll
            for (int i=0;i<8;i++) a2[i] = *(const u64*)&Asd[(ty*8+i)*36 + 2*kk];
            ulonglong2 b01 = *(const ulonglong2*)&Bs[kk*128 + tx*8];
            ulonglong2 b23 = *(const ulonglong2*)&Bs[kk*128 + tx*8 + 4];
            u64 bb[4] = { b01.x, b01.y, b23.x, b23.y };
            #pragma unroll
            for (int i=0;i<8;i++)
                #pragma unroll
                for (int j=0;j<4;j++) ffma2(acc[i][j], a2[i], bb[j]);
        }
        __syncthreads();
    }
    #pragma unroll
    for (int j = 0; j < 8; j++) {
        int col = n0 + tx*8 + j;
        float vals[8];
        #pragma unroll
        for (int i = 0; i < 8; i++) {
            float2 p = u2f(acc[i][j>>1]);
            vals[i] = (j & 1) ? p.y : p.x;
        }
        *(float4*)&dst[(size_t)col*IC + ty*8]     = make_float4(vals[0],vals[1],vals[2],vals[3]);
        *(float4*)&dst[(size_t)col*IC + ty*8 + 4] = make_float4(vals[4],vals[5],vals[6],vals[7]);
    }
}

// ---------- residual path: out = C @ x1 + cvec ----------
__global__ void __launch_bounds__(256) resid_kernel(const float* __restrict__ x1,
                                                    float* __restrict__ out)
{
    extern __shared__ float Cs[];
    int b = blockIdx.y;
    int n = blockIdx.x*256 + threadIdx.x;
    for (int i = threadIdx.x; i < OC*CIN; i += 256) Cs[i] = g_C[i];
    __syncthreads();
    const float* xb = x1 + (size_t)b*CIN*NP + n;
    float acc[OC];
    #pragma unroll
    for (int o=0;o<OC;o++) acc[o] = g_cvec[o];
    for (int k = 0; k < CIN; k++) {
        float xv = xb[(size_t)k*NP];
        #pragma unroll
        for (int o=0;o<OC;o++) acc[o] = fmaf(Cs[o*CIN+k], xv, acc[o]);
    }
    float* ob = out + (size_t)b*OC*NP + n;
    #pragma unroll
    for (int o=0;o<OC;o++) ob[(size_t)o*NP] = acc[o];
}

// ---------- flash attention + A@y epilogue ----------
#define SM_TH 0
#define SM_PH 16896
#define SM_GS 25344
#define SM_SS 33536
#define SM_AS 50176
#define SM_M  52736
#define SM_L  52864
#define SM_SC 52992
#define SM_TOT_B (53120*4)

__global__ void __launch_bounds__(256) attn_kernel(float* __restrict__ out)
{
    extern __shared__ float sm[];
    float* th   = sm + SM_TH;   // [q][132]
    float* ph   = sm + SM_PH;   // [j][132]
    float* gs   = sm + SM_GS;   // [j][128]
    float* ss   = sm + SM_SS;   // [q][130] (p duplicated in pairs)
    float* As   = sm + SM_AS;   // [20*128]
    float* mrow = sm + SM_M;
    float* lrow = sm + SM_L;
    float* srow = sm + SM_SC;

    int t = threadIdx.x, lane = t & 31, wid = t >> 5;
    int b = blockIdx.y;
    int n0 = blockIdx.x * 128;

    const float* thg = g_thT + ((size_t)b*NP + n0)*IC;
    #pragma unroll
    for (int i = 0; i < 16; i++) {
        int e = t + i*256;
        int cf = e & 31, q = e >> 5;
        *(float4*)&th[q*132 + cf*4] = *(const float4*)&thg[(size_t)q*IC + cf*4];
    }
    for (int i = t; i < OC*IC; i += 256) As[i] = g_A[i];
    if (t < 128) { mrow[t] = -1e30f; lrow[t] = 0.f; }

    u64 y2[4][8];
    #pragma unroll
    for (int a=0;a<4;a++)
        #pragma unroll
        for (int k=0;k<8;k++) y2[a][k] = 0ull;

    const float* phg = g_phT + (size_t)b*NP*IC;
    const float* gg  = g_gT  + (size_t)b*NP*IC;

    for (int j0 = 0; j0 < NP; j0 += 64) {
        __syncthreads();
        #pragma unroll
        for (int i = 0; i < 8; i++) {
            int e = t + i*256;
            int cf = e & 31, j = e >> 5;
            *(float4*)&ph[j*132 + cf*4] = *(const float4*)&phg[(size_t)(j0+j)*IC + cf*4];
            *(float4*)&gs[j*128 + cf*4] = *(const float4*)&gg [(size_t)(j0+j)*IC + cf*4];
        }
        __syncthreads();

        // ---- S = theta^T phi (f32x2, c-pair contraction) ----
        u64 s2[4][8];
        #pragma unroll
        for (int a=0;a<4;a++)
            #pragma unroll
            for (int jj=0;jj<8;jj++) s2[a][jj] = 0ull;
        const float* phb = ph + (wid*8)*132;
        #pragma unroll 2
        for (int c = 0; c < IC; c += 4) {
            u64 av[4][2];
            #pragma unroll
            for (int a=0;a<4;a++) {
                ulonglong2 v = *(const ulonglong2*)&th[(a*32+lane)*132 + c];
                av[a][0] = v.x; av[a][1] = v.y;
            }
            #pragma unroll
            for (int jj=0;jj<8;jj++) {
                ulonglong2 w = *(const ulonglong2*)&phb[jj*132 + c];
                #pragma unroll
                for (int a=0;a<4;a++) { ffma2(s2[a][jj], av[a][0], w.x); ffma2(s2[a][jj], av[a][1], w.y); }
            }
        }
        #pragma unroll
        for (int a=0;a<4;a++)
            #pragma unroll
            for (int jj=0;jj<8;jj++) {
                float2 sp = u2f(s2[a][jj]);
                ss[(a*32+lane)*130 + 2*(wid*8+jj)] = sp.x + sp.y;
            }
        __syncthreads();

        // ---- online softmax (2 threads per row, FMA-pipe exp) ----
        {
            int r = t >> 1, h = t & 1;
            float* row = ss + r*130 + h*64;
            float tmax = -1e30f;
            #pragma unroll 8
            for (int j=0;j<32;j++) tmax = fmaxf(tmax, row[2*j]);
            tmax = fmaxf(tmax, __shfl_xor_sync(0xffffffffu, tmax, 1));
            float nm = fmaxf(mrow[r], tmax);
            float sum = 0.f;
            #pragma unroll 8
            for (int j=0;j<32;j++) {
                float p = fexp(row[2*j] - nm);
                row[2*j] = p; row[2*j+1] = p;   // duplicate for pair loads in PV
                sum += p;
            }
            sum += __shfl_xor_sync(0xffffffffu, sum, 1);
            if (h == 0) {
                float sc = fexp(mrow[r] - nm);
                lrow[r] = lrow[r]*sc + sum;
                mrow[r] = nm;
                srow[r] = sc;
            }
        }
        __syncthreads();

        // ---- PV (f32x2, c-pair outputs, duplicated p pairs) ----
        #pragma unroll
        for (int a=0;a<4;a++) {
            float sc = srow[a*32+lane];
            u64 sc2 = f2u(sc, sc);
            #pragma unroll
            for (int k=0;k<8;k++) fmul2(y2[a][k], sc2);
        }
        const float* gsb = gs + wid*16;
        for (int j = 0; j < 64; j++) {
            ulonglong2 ga = *(const ulonglong2*)&gsb[j*128];
            ulonglong2 gb = *(const ulonglong2*)&gsb[j*128 + 4];
            ulonglong2 gc = *(const ulonglong2*)&gsb[j*128 + 8];
            ulonglong2 gd = *(const ulonglong2*)&gsb[j*128 + 12];
            u64 g2[8] = { ga.x, ga.y, gb.x, gb.y, gc.x, gc.y, gd.x, gd.y };
            #pragma unroll
            for (int a=0;a<4;a++) {
                u64 p2 = *(const u64*)&ss[(a*32+lane)*130 + 2*j];
                #pragma unroll
                for (int k=0;k<8;k++) ffma2(y2[a][k], p2, g2[k]);
            }
        }
    }

    __syncthreads();
    // normalize into ys (reuse th region, stride 129 = conflict-free)
    float* ys = sm;
    #pragma unroll
    for (int a=0;a<4;a++) {
        float inv = 1.f / lrow[a*32+lane];
        #pragma unroll
        for (int k=0;k<8;k++) {
            float2 yv = u2f(y2[a][k]);
            ys[(a*32+lane)*129 + wid*16 + 2*k]   = yv.x * inv;
            ys[(a*32+lane)*129 + wid*16 + 2*k+1] = yv.y * inv;
        }
    }
    __syncthreads();
    // out += A @ y
    float* ob = out + (size_t)b*OC*NP + n0;
    #pragma unroll
    for (int i = 0; i < 10; i++) {
        int idx = t + i*256;
        int q = idx & 127, o = idx >> 7;
        float acc = 0.f;
        #pragma unroll 8
        for (int c = 0; c < IC; c++) acc = fmaf(As[o*IC+c], ys[q*129+c], acc);
        ob[(size_t)o*NP + q] += acc;
    }
}

extern "C" void kernel_launch(void* const* d_in, const int* in_sizes, int n_in,
                              void* d_out, int out_size)
{
    const float* x1     = (const float*)d_in[0];
    const float* x2     = (const float*)d_in[1];
    const float* w_conv = (const float*)d_in[2];
    const float* w_th   = (const float*)d_in[3];
    const float* w_ph   = (const float*)d_in[4];
    const float* w_g    = (const float*)d_in[5];
    const float* w_W    = (const float*)d_in[6];
    const float* b_W    = (const float*)d_in[7];
    const float* gam    = (const float*)d_in[8];
    const float* bet    = (const float*)d_in[9];
    const float* mean   = (const float*)d_in[10];
    const float* var    = (const float*)d_in[11];
    const float* w_out  = (const float*)d_in[12];
    const float* b_out  = (const float*)d_in[13];
    float* out = (float*)d_out;

    cudaFuncSetAttribute(attn_kernel, cudaFuncAttributeMaxDynamicSharedMemorySize, SM_TOT_B);
    cudaFuncSetAttribute(resid_kernel, cudaFuncAttributeMaxDynamicSharedMemorySize, OC*CIN*4);

    prep_kernel<<<1223, 256>>>(w_conv, w_th, w_ph, w_g, w_W, b_W, gam, bet, mean, var, w_out, b_out);
    proj_kernel<<<dim3(32, 3, BB), 256>>>(x1, x2);
    resid_kernel<<<dim3(16, BB), 256, OC*CIN*4>>>(x1, out);
    attn_kernel<<<dim3(32, BB), 256, SM_TOT_B>>>(out);
}

// round 5
// speedup vs baseline: 1.1801x; 1.1801x over previous
#include <cuda_runtime.h>
#include <cstdint>

typedef unsigned int u32;
typedef unsigned long long u64;

#define BB 8
#define CIN 768
#define NP 4096
#define IC 128
#define MID 256
#define OC 20

// folded weights
__device__ float g_wtpg[3*IC*CIN];
__device__ float g_C[OC*CIN];
__device__ float g_A[OC*IC];
__device__ float g_cvec[OC];
// projections as bf16 hi/lo planes, [b][n][c] packed bf16x2 (64 u32 per row)
__device__ u32 g_th_h[BB*NP*64];
__device__ u32 g_th_l[BB*NP*64];
__device__ u32 g_ph_h[BB*NP*64];
__device__ u32 g_ph_l[BB*NP*64];
__device__ u32 g_g_h [BB*NP*64];
__device__ u32 g_g_l [BB*NP*64];

// ---------------- f32x2 helpers (projection kernel) ----------------
__device__ __forceinline__ void ffma2(u64& d, u64 a, u64 b){
    asm("fma.rn.f32x2 %0, %1, %2, %0;" : "+l"(d) : "l"(a), "l"(b));
}
__device__ __forceinline__ float2 u2f(u64 v){
    float2 r; asm("mov.b64 {%0,%1}, %2;" : "=f"(r.x), "=f"(r.y) : "l"(v)); return r;
}

__device__ __forceinline__ float fexp(float x){
    x = fmaxf(x, -80.f);
    float t = x * 1.4426950408889634f;
    float f = t + 12582912.f;
    float k = f - 12582912.f;
    float r = t - k;
    float p = 1.3333558e-3f;
    p = fmaf(p, r, 9.6181291e-3f);
    p = fmaf(p, r, 5.5504109e-2f);
    p = fmaf(p, r, 2.4022651e-1f);
    p = fmaf(p, r, 6.9314718e-1f);
    p = fmaf(p, r, 1.f);
    int ki = (int)k;
    return p * __int_as_float((ki + 127) << 23);
}

// bf16 pack/split helpers: u32 = (lo16 = first elem, hi16 = second elem)
__device__ __forceinline__ u32 cvtbf2(float a, float b){
    u32 r; asm("cvt.rn.bf16x2.f32 %0, %1, %2;" : "=r"(r) : "f"(b), "f"(a)); return r;
}
__device__ __forceinline__ float blo(u32 u){ return __uint_as_float(u << 16); }
__device__ __forceinline__ float bhi(u32 u){ return __uint_as_float(u & 0xffff0000u); }

__device__ __forceinline__ u32 smem_u32(const void* p){
    u32 a; asm("{ .reg .u64 t; cvta.to.shared.u64 t, %1; cvt.u32.u64 %0, t; }" : "=r"(a) : "l"(p)); return a;
}

// ---------------- mma / ldmatrix ----------------
__device__ __forceinline__ void mma16816(float* d, const u32* a, u32 b0, u32 b1){
    asm volatile("mma.sync.aligned.m16n8k16.row.col.f32.bf16.bf16.f32 "
        "{%0,%1,%2,%3}, {%4,%5,%6,%7}, {%8,%9}, {%0,%1,%2,%3};"
        : "+f"(d[0]), "+f"(d[1]), "+f"(d[2]), "+f"(d[3])
        : "r"(a[0]), "r"(a[1]), "r"(a[2]), "r"(a[3]), "r"(b0), "r"(b1));
}
__device__ __forceinline__ void ldsm4(u32* r, u32 addr){
    asm volatile("ldmatrix.sync.aligned.m8n8.x4.shared.b16 {%0,%1,%2,%3}, [%4];"
        : "=r"(r[0]), "=r"(r[1]), "=r"(r[2]), "=r"(r[3]) : "r"(addr));
}
__device__ __forceinline__ void ldsm4t(u32* r, u32 addr){
    asm volatile("ldmatrix.sync.aligned.m8n8.x4.trans.shared.b16 {%0,%1,%2,%3}, [%4];"
        : "=r"(r[0]), "=r"(r[1]), "=r"(r[2]), "=r"(r[3]) : "r"(addr));
}

// row of 128 bf16 = 256B = 16 chunks of 16B; swizzle chunk ^= (row&7)
__device__ __forceinline__ u32 swaddr(u32 base, int row, int ch){
    return base + (u32)row*256u + (u32)((ch ^ (row & 7)) * 16);
}

// ---------------- prep: fold all weight algebra ----------------
__global__ void __launch_bounds__(256) prep_kernel(
    const float* __restrict__ wc, const float* __restrict__ wt,
    const float* __restrict__ wp, const float* __restrict__ wg,
    const float* __restrict__ wW, const float* __restrict__ bW,
    const float* __restrict__ gam, const float* __restrict__ bet,
    const float* __restrict__ mean, const float* __restrict__ var,
    const float* __restrict__ wo, const float* __restrict__ bo)
{
    int gid = blockIdx.x*256 + threadIdx.x;
    if (gid < 3*IC*CIN) {
        int r = gid / CIN, k = gid % CIN;
        const float* ws = (r < IC) ? wt : (r < 2*IC) ? wp : wg;
        int rr = r & (IC-1);
        float acc = 0.f;
        for (int m = 0; m < MID; m++) acc = fmaf(ws[rr*MID+m], wc[m*CIN+k], acc);
        g_wtpg[gid] = acc;
        return;
    }
    int idx = gid - 3*IC*CIN;
    if (idx < OC*CIN) {
        int o = idx / CIN, k = idx % CIN;
        float acc = 0.f;
        for (int m = 0; m < MID; m++) acc = fmaf(wo[o*MID+m], wc[m*CIN+k], acc);
        g_C[idx] = acc;
        return;
    }
    idx -= OC*CIN;
    if (idx < OC*IC) {
        int o = idx / IC, i = idx % IC;
        float acc = 0.f;
        for (int m = 0; m < MID; m++) {
            float inv = gam[m] * rsqrtf(var[m] + 1e-5f);
            acc = fmaf(wo[o*MID+m]*inv, wW[m*IC+i], acc);
        }
        g_A[idx] = acc;
        return;
    }
    idx -= OC*IC;
    if (idx < OC) {
        float acc = bo[idx];
        for (int m = 0; m < MID; m++) {
            float inv = gam[m] * rsqrtf(var[m] + 1e-5f);
            acc += wo[idx*MID+m] * (bW[m]*inv + bet[m] - mean[m]*inv);
        }
        g_cvec[idx] = acc;
    }
}

// ---------------- projections -> bf16 hi/lo planes [n][c] ----------------
__global__ void __launch_bounds__(256) proj_kernel(const float* __restrict__ x1,
                                                   const float* __restrict__ x2)
{
    __shared__ float Asd[128*36];
    __shared__ float Bs[16*128];
    int t = threadIdx.x, tx = t & 15, ty = t >> 4;
    int n0 = blockIdx.x * 128;
    int which = blockIdx.y;
    int b = blockIdx.z;
    const float* xb = (which == 0 ? x1 : x2) + (size_t)b * CIN * NP;
    int wrow0 = which * IC;

    u64 acc[8][4];
    #pragma unroll
    for (int i=0;i<8;i++)
        #pragma unroll
        for (int j=0;j<4;j++) acc[i][j] = 0ull;

    for (int k0 = 0; k0 < CIN; k0 += 16) {
        #pragma unroll
        for (int i = 0; i < 8; i++) {
            int e = t + i*256;
            int row = e >> 4, kk = e & 15;
            float w = g_wtpg[(wrow0+row)*CIN + k0 + kk];
            Asd[row*36 + 2*kk]     = w;
            Asd[row*36 + 2*kk + 1] = w;
        }
        #pragma unroll
        for (int i = 0; i < 8; i++) {
            int e = t + i*256;
            int kk = e >> 7, n = e & 127;
            Bs[kk*128 + n] = xb[(size_t)(k0+kk)*NP + n0 + n];
        }
        __syncthreads();
        #pragma unroll
        for (int kk = 0; kk < 16; kk++) {
            u64 a2[8];
            #pragma unroll
            for (int i=0;i<8;i++) a2[i] = *(const u64*)&Asd[(ty*8+i)*36 + 2*kk];
            ulonglong2 b01 = *(const ulonglong2*)&Bs[kk*128 + tx*8];
            ulonglong2 b23 = *(const ulonglong2*)&Bs[kk*128 + tx*8 + 4];
            u64 bb[4] = { b01.x, b01.y, b23.x, b23.y };
            #pragma unroll
            for (int i=0;i<8;i++)
                #pragma unroll
                for (int j=0;j<4;j++) ffma2(acc[i][j], a2[i], bb[j]);
        }
        __syncthreads();
    }
    u32* dh = (which==0 ? g_th_h : which==1 ? g_ph_h : g_g_h) + (size_t)b*NP*64;
    u32* dl = (which==0 ? g_th_l : which==1 ? g_ph_l : g_g_l) + (size_t)b*NP*64;
    #pragma unroll
    for (int j = 0; j < 8; j++) {
        int col = n0 + tx*8 + j;
        float vals[8];
        #pragma unroll
        for (int i = 0; i < 8; i++) {
            float2 p = u2f(acc[i][j>>1]);
            vals[i] = (j & 1) ? p.y : p.x;
        }
        u32 h[4], lo[4];
        #pragma unroll
        for (int p = 0; p < 4; p++) {
            h[p]  = cvtbf2(vals[2*p], vals[2*p+1]);
            lo[p] = cvtbf2(vals[2*p] - blo(h[p]), vals[2*p+1] - bhi(h[p]));
        }
        *(uint4*)&dh[(size_t)col*64 + ty*4] = make_uint4(h[0],h[1],h[2],h[3]);
        *(uint4*)&dl[(size_t)col*64 + ty*4] = make_uint4(lo[0],lo[1],lo[2],lo[3]);
    }
}

// ---------------- residual path: out = C @ x1 + cvec ----------------
__global__ void __launch_bounds__(256) resid_kernel(const float* __restrict__ x1,
                                                    float* __restrict__ out)
{
    extern __shared__ float Cs[];
    int b = blockIdx.y;
    int n = blockIdx.x*256 + threadIdx.x;
    for (int i = threadIdx.x; i < OC*CIN; i += 256) Cs[i] = g_C[i];
    __syncthreads();
    const float* xb = x1 + (size_t)b*CIN*NP + n;
    float acc[OC];
    #pragma unroll
    for (int o=0;o<OC;o++) acc[o] = g_cvec[o];
    for (int k = 0; k < CIN; k++) {
        float xv = xb[(size_t)k*NP];
        #pragma unroll
        for (int o=0;o<OC;o++) acc[o] = fmaf(Cs[o*CIN+k], xv, acc[o]);
    }
    float* ob = out + (size_t)b*OC*NP + n;
    #pragma unroll
    for (int o=0;o<OC;o++) ob[(size_t)o*NP] = acc[o];
}

// ---------------- warp-MMA flash attention ----------------
// smem byte offsets
#define S_TH_H 0
#define S_TH_L 32768
#define S_PH_H 65536
#define S_PH_L 81920
#define S_G_H  98304
#define S_G_L  114688
#define S_AS   131072
#define S_YS   141312
#define S_TOTAL (141312 + 128*129*4)

__device__ __forceinline__ void stage_tile(char* smc, int smoff, const u32* src, int rows, int t){
    for (int idx = t; idx < rows*16; idx += 256) {
        int r = idx >> 4, ch = idx & 15;
        uint4 v = *(const uint4*)(src + (size_t)r*64 + ch*4);
        *(uint4*)(smc + smoff + r*256 + ((ch ^ (r & 7)) * 16)) = v;
    }
}

__global__ void __launch_bounds__(256) attn_mma_kernel(float* __restrict__ out)
{
    extern __shared__ char smc[];
    u32 sb = smem_u32(smc);
    int t = threadIdx.x, lane = t & 31, w = t >> 5;
    int b = blockIdx.y;
    int n0 = blockIdx.x * 128;
    size_t bn = (size_t)b * NP;

    float* As = (float*)(smc + S_AS);
    for (int i = t; i < OC*IC; i += 256) As[i] = g_A[i];

    // stage theta (persistent, 128 rows)
    stage_tile(smc, S_TH_H, g_th_h + (bn + n0)*64, 128, t);
    stage_tile(smc, S_TH_L, g_th_l + (bn + n0)*64, 128, t);

    const u32* phh = g_ph_h + bn*64;
    const u32* phl = g_ph_l + bn*64;
    const u32* ggh = g_g_h  + bn*64;
    const u32* ggl = g_g_l  + bn*64;

    float y[16][4];
    #pragma unroll
    for (int n = 0; n < 16; n++)
        #pragma unroll
        for (int i = 0; i < 4; i++) y[n][i] = 0.f;
    float m0 = -1e30f, m1 = -1e30f, l0 = 0.f, l1 = 0.f;

    // ldmatrix lane addressing precompute
    int la15 = lane & 15, la7 = lane & 7;
    int lahalf = (lane >> 3) & 1, laq = lane >> 4;

    for (int j0 = 0; j0 < NP; j0 += 64) {
        __syncthreads();
        stage_tile(smc, S_PH_H, phh + (size_t)(j0)*64, 64, t);
        stage_tile(smc, S_PH_L, phl + (size_t)(j0)*64, 64, t);
        stage_tile(smc, S_G_H,  ggh + (size_t)(j0)*64, 64, t);
        stage_tile(smc, S_G_L,  ggl + (size_t)(j0)*64, 64, t);
        __syncthreads();

        // ---- QK: S[16q x 64j] ----
        float S[8][4];
        #pragma unroll
        for (int n = 0; n < 8; n++)
            #pragma unroll
            for (int i = 0; i < 4; i++) S[n][i] = 0.f;

        #pragma unroll
        for (int k = 0; k < 8; k++) {
            // A frags (theta hi/lo): rows w*16 + (lane&15), chunk 2k + (lane>>4)
            u32 ah[4], al[4];
            {
                int row = w*16 + la15, ch = 2*k + laq;
                ldsm4(ah, swaddr(sb + S_TH_H, row, ch));
                ldsm4(al, swaddr(sb + S_TH_L, row, ch));
            }
            #pragma unroll
            for (int n4 = 0; n4 < 4; n4++) {
                int row = (n4*2 + laq)*8 + la7;
                int ch = 2*k + lahalf;
                u32 bh[4], bl[4];
                ldsm4(bh, swaddr(sb + S_PH_H, row, ch));
                mma16816(S[2*n4],   ah, bh[0], bh[1]);
                mma16816(S[2*n4+1], ah, bh[2], bh[3]);
                mma16816(S[2*n4],   al, bh[0], bh[1]);
                mma16816(S[2*n4+1], al, bh[2], bh[3]);
                ldsm4(bl, swaddr(sb + S_PH_L, row, ch));
                mma16816(S[2*n4],   ah, bl[0], bl[1]);
                mma16816(S[2*n4+1], ah, bl[2], bl[3]);
            }
        }

        // ---- online softmax ----
        float tm0 = -1e30f, tm1 = -1e30f;
        #pragma unroll
        for (int n = 0; n < 8; n++) {
            tm0 = fmaxf(tm0, fmaxf(S[n][0], S[n][1]));
            tm1 = fmaxf(tm1, fmaxf(S[n][2], S[n][3]));
        }
        tm0 = fmaxf(tm0, __shfl_xor_sync(0xffffffffu, tm0, 1));
        tm0 = fmaxf(tm0, __shfl_xor_sync(0xffffffffu, tm0, 2));
        tm1 = fmaxf(tm1, __shfl_xor_sync(0xffffffffu, tm1, 1));
        tm1 = fmaxf(tm1, __shfl_xor_sync(0xffffffffu, tm1, 2));
        float nm0 = fmaxf(m0, tm0), nm1 = fmaxf(m1, tm1);
        float sc0 = fexp(m0 - nm0), sc1 = fexp(m1 - nm1);
        float sum0 = 0.f, sum1 = 0.f;
        #pragma unroll
        for (int n = 0; n < 8; n++) {
            S[n][0] = fexp(S[n][0] - nm0);
            S[n][1] = fexp(S[n][1] - nm0);
            S[n][2] = fexp(S[n][2] - nm1);
            S[n][3] = fexp(S[n][3] - nm1);
            sum0 += S[n][0] + S[n][1];
            sum1 += S[n][2] + S[n][3];
        }
        sum0 += __shfl_xor_sync(0xffffffffu, sum0, 1);
        sum0 += __shfl_xor_sync(0xffffffffu, sum0, 2);
        sum1 += __shfl_xor_sync(0xffffffffu, sum1, 1);
        sum1 += __shfl_xor_sync(0xffffffffu, sum1, 2);
        l0 = l0*sc0 + sum0;  m0 = nm0;
        l1 = l1*sc1 + sum1;  m1 = nm1;

        // P -> bf16 hi/lo A-fragments (4 ksteps)
        u32 ph_[4][4], pl_[4][4];
        #pragma unroll
        for (int kp = 0; kp < 4; kp++) {
            float* sa = S[2*kp];
            float* sb2 = S[2*kp+1];
            u32 h0 = cvtbf2(sa[0], sa[1]);
            u32 h1 = cvtbf2(sa[2], sa[3]);
            u32 h2 = cvtbf2(sb2[0], sb2[1]);
            u32 h3 = cvtbf2(sb2[2], sb2[3]);
            ph_[kp][0] = h0; ph_[kp][1] = h1; ph_[kp][2] = h2; ph_[kp][3] = h3;
            pl_[kp][0] = cvtbf2(sa[0]-blo(h0), sa[1]-bhi(h0));
            pl_[kp][1] = cvtbf2(sa[2]-blo(h1), sa[3]-bhi(h1));
            pl_[kp][2] = cvtbf2(sb2[0]-blo(h2), sb2[1]-bhi(h2));
            pl_[kp][3] = cvtbf2(sb2[2]-blo(h3), sb2[3]-bhi(h3));
        }

        // rescale y
        #pragma unroll
        for (int n = 0; n < 16; n++) {
            y[n][0] *= sc0; y[n][1] *= sc0;
            y[n][2] *= sc1; y[n][3] *= sc1;
        }

        // ---- PV: y[16q x 128c] += P @ g ----
        #pragma unroll
        for (int kp = 0; kp < 4; kp++) {
            #pragma unroll
            for (int n8 = 0; n8 < 8; n8++) {
                int row = kp*16 + lahalf*8 + la7;
                int ch = 2*n8 + laq;
                u32 gh[4], gl[4];
                ldsm4t(gh, swaddr(sb + S_G_H, row, ch));
                mma16816(y[2*n8],   ph_[kp], gh[0], gh[1]);
                mma16816(y[2*n8+1], ph_[kp], gh[2], gh[3]);
                mma16816(y[2*n8],   pl_[kp], gh[0], gh[1]);
                mma16816(y[2*n8+1], pl_[kp], gh[2], gh[3]);
                ldsm4t(gl, swaddr(sb + S_G_L, row, ch));
                mma16816(y[2*n8],   ph_[kp], gl[0], gl[1]);
                mma16816(y[2*n8+1], ph_[kp], gl[2], gl[3]);
            }
        }
    }

    // ---- epilogue: ys = y / l, then out += A @ ys ----
    __syncthreads();
    float* ys = (float*)(smc + S_YS);
    {
        float inv0 = 1.f / l0, inv1 = 1.f / l1;
        int r0 = w*16 + (lane >> 2), r1 = r0 + 8;
        int cb = 2*(lane & 3);
        #pragma unroll
        for (int n = 0; n < 16; n++) {
            int c = n*8 + cb;
            ys[r0*129 + c]     = y[n][0] * inv0;
            ys[r0*129 + c + 1] = y[n][1] * inv0;
            ys[r1*129 + c]     = y[n][2] * inv1;
            ys[r1*129 + c + 1] = y[n][3] * inv1;
        }
    }
    __syncthreads();
    float* ob = out + (size_t)b*OC*NP + n0;
    #pragma unroll
    for (int i = 0; i < 10; i++) {
        int idx = t + i*256;
        int q = idx & 127, o = idx >> 7;
        float acc = 0.f;
        #pragma unroll 8
        for (int c = 0; c < IC; c++) acc = fmaf(As[o*IC+c], ys[q*129+c], acc);
        ob[(size_t)o*NP + q] += acc;
    }
}

extern "C" void kernel_launch(void* const* d_in, const int* in_sizes, int n_in,
                              void* d_out, int out_size)
{
    const float* x1     = (const float*)d_in[0];
    const float* x2     = (const float*)d_in[1];
    const float* w_conv = (const float*)d_in[2];
    const float* w_th   = (const float*)d_in[3];
    const float* w_ph   = (const float*)d_in[4];
    const float* w_g    = (const float*)d_in[5];
    const float* w_W    = (const float*)d_in[6];
    const float* b_W    = (const float*)d_in[7];
    const float* gam    = (const float*)d_in[8];
    const float* bet    = (const float*)d_in[9];
    const float* mean   = (const float*)d_in[10];
    const float* var    = (const float*)d_in[11];
    const float* w_out  = (const float*)d_in[12];
    const float* b_out  = (const float*)d_in[13];
    float* out = (float*)d_out;

    cudaFuncSetAttribute(attn_mma_kernel, cudaFuncAttributeMaxDynamicSharedMemorySize, S_TOTAL);
    cudaFuncSetAttribute(resid_kernel, cudaFuncAttributeMaxDynamicSharedMemorySize, OC*CIN*4);

    prep_kernel<<<1223, 256>>>(w_conv, w_th, w_ph, w_g, w_W, b_W, gam, bet, mean, var, w_out, b_out);
    proj_kernel<<<dim3(32, 3, BB), 256>>>(x1, x2);
    resid_kernel<<<dim3(16, BB), 256, OC*CIN*4>>>(x1, out);
    attn_mma_kernel<<<dim3(32, BB), 256, S_TOTAL>>>(out);
}

// round 6
// speedup vs baseline: 1.4206x; 1.2037x over previous
#include <cuda_runtime.h>
#include <cstdint>

typedef unsigned int u32;
typedef unsigned long long u64;

#define BB 8
#define CIN 768
#define NP 4096
#define IC 128
#define MID 256
#define OC 20

// folded weights
__device__ float g_wtpg[3*IC*CIN];
__device__ float g_C[OC*CIN];
__device__ float g_A[OC*IC];
__device__ float g_cvec[OC];
// projections as bf16 hi/lo planes, [b][n][c] packed bf16x2 (64 u32 per row)
__device__ u32 g_th_h[BB*NP*64];
__device__ u32 g_th_l[BB*NP*64];
__device__ u32 g_ph_h[BB*NP*64];
__device__ u32 g_ph_l[BB*NP*64];
__device__ u32 g_g_h [BB*NP*64];
__device__ u32 g_g_l [BB*NP*64];

// ---------------- f32x2 helpers ----------------
__device__ __forceinline__ void ffma2(u64& d, u64 a, u64 b){
    asm("fma.rn.f32x2 %0, %1, %2, %0;" : "+l"(d) : "l"(a), "l"(b));
}
__device__ __forceinline__ float2 u2f(u64 v){
    float2 r; asm("mov.b64 {%0,%1}, %2;" : "=f"(r.x), "=f"(r.y) : "l"(v)); return r;
}

__device__ __forceinline__ float fexp(float x){
    x = fmaxf(x, -80.f);
    float t = x * 1.4426950408889634f;
    float f = t + 12582912.f;
    float k = f - 12582912.f;
    float r = t - k;
    float p = 1.3333558e-3f;
    p = fmaf(p, r, 9.6181291e-3f);
    p = fmaf(p, r, 5.5504109e-2f);
    p = fmaf(p, r, 2.4022651e-1f);
    p = fmaf(p, r, 6.9314718e-1f);
    p = fmaf(p, r, 1.f);
    int ki = (int)k;
    return p * __int_as_float((ki + 127) << 23);
}

__device__ __forceinline__ u32 cvtbf2(float a, float b){
    u32 r; asm("cvt.rn.bf16x2.f32 %0, %1, %2;" : "=r"(r) : "f"(b), "f"(a)); return r;
}
__device__ __forceinline__ float blo(u32 u){ return __uint_as_float(u << 16); }
__device__ __forceinline__ float bhi(u32 u){ return __uint_as_float(u & 0xffff0000u); }

__device__ __forceinline__ u32 smem_u32(const void* p){
    u32 a; asm("{ .reg .u64 t; cvta.to.shared.u64 t, %1; cvt.u32.u64 %0, t; }" : "=r"(a) : "l"(p)); return a;
}

// ---------------- mma / ldmatrix ----------------
__device__ __forceinline__ void mma16816(float* d, const u32* a, u32 b0, u32 b1){
    asm volatile("mma.sync.aligned.m16n8k16.row.col.f32.bf16.bf16.f32 "
        "{%0,%1,%2,%3}, {%4,%5,%6,%7}, {%8,%9}, {%0,%1,%2,%3};"
        : "+f"(d[0]), "+f"(d[1]), "+f"(d[2]), "+f"(d[3])
        : "r"(a[0]), "r"(a[1]), "r"(a[2]), "r"(a[3]), "r"(b0), "r"(b1));
}
__device__ __forceinline__ void ldsm4(u32* r, u32 addr){
    asm volatile("ldmatrix.sync.aligned.m8n8.x4.shared.b16 {%0,%1,%2,%3}, [%4];"
        : "=r"(r[0]), "=r"(r[1]), "=r"(r[2]), "=r"(r[3]) : "r"(addr));
}
__device__ __forceinline__ void ldsm4t(u32* r, u32 addr){
    asm volatile("ldmatrix.sync.aligned.m8n8.x4.trans.shared.b16 {%0,%1,%2,%3}, [%4];"
        : "=r"(r[0]), "=r"(r[1]), "=r"(r[2]), "=r"(r[3]) : "r"(addr));
}

// 256B rows (16 chunks of 16B), swizzle chunk ^= (row&7)
__device__ __forceinline__ u32 sw16(u32 base, int row, int ch){
    return base + (u32)row*256u + (u32)((ch ^ (row & 7)) * 16);
}
// 128B rows (8 chunks of 16B)
__device__ __forceinline__ u32 sw8(u32 base, int row, int ch){
    return base + (u32)row*128u + (u32)((ch ^ (row & 7)) * 16);
}

// ---------------- prep ----------------
__global__ void __launch_bounds__(256) prep_kernel(
    const float* __restrict__ wc, const float* __restrict__ wt,
    const float* __restrict__ wp, const float* __restrict__ wg,
    const float* __restrict__ wW, const float* __restrict__ bW,
    const float* __restrict__ gam, const float* __restrict__ bet,
    const float* __restrict__ mean, const float* __restrict__ var,
    const float* __restrict__ wo, const float* __restrict__ bo)
{
    int gid = blockIdx.x*256 + threadIdx.x;
    if (gid < 3*IC*CIN) {
        int r = gid / CIN, k = gid % CIN;
        const float* ws = (r < IC) ? wt : (r < 2*IC) ? wp : wg;
        int rr = r & (IC-1);
        float acc = 0.f;
        for (int m = 0; m < MID; m++) acc = fmaf(ws[rr*MID+m], wc[m*CIN+k], acc);
        g_wtpg[gid] = acc;
        return;
    }
    int idx = gid - 3*IC*CIN;
    if (idx < OC*CIN) {
        int o = idx / CIN, k = idx % CIN;
        float acc = 0.f;
        for (int m = 0; m < MID; m++) acc = fmaf(wo[o*MID+m], wc[m*CIN+k], acc);
        g_C[idx] = acc;
        return;
    }
    idx -= OC*CIN;
    if (idx < OC*IC) {
        int o = idx / IC, i = idx % IC;
        float acc = 0.f;
        for (int m = 0; m < MID; m++) {
            float inv = gam[m] * rsqrtf(var[m] + 1e-5f);
            acc = fmaf(wo[o*MID+m]*inv, wW[m*IC+i], acc);
        }
        g_A[idx] = acc;
        return;
    }
    idx -= OC*IC;
    if (idx < OC) {
        float acc = bo[idx];
        for (int m = 0; m < MID; m++) {
            float inv = gam[m] * rsqrtf(var[m] + 1e-5f);
            acc += wo[idx*MID+m] * (bW[m]*inv + bet[m] - mean[m]*inv);
        }
        g_cvec[idx] = acc;
    }
}

// ---------------- projections -> bf16 hi/lo planes [n][c] ----------------
__global__ void __launch_bounds__(256) proj_kernel(const float* __restrict__ x1,
                                                   const float* __restrict__ x2)
{
    __shared__ float Asd[128*36];
    __shared__ float Bs[16*128];
    int t = threadIdx.x, tx = t & 15, ty = t >> 4;
    int n0 = blockIdx.x * 128;
    int which = blockIdx.y;
    int b = blockIdx.z;
    const float* xb = (which == 0 ? x1 : x2) + (size_t)b * CIN * NP;
    int wrow0 = which * IC;

    u64 acc[8][4];
    #pragma unroll
    for (int i=0;i<8;i++)
        #pragma unroll
        for (int j=0;j<4;j++) acc[i][j] = 0ull;

    for (int k0 = 0; k0 < CIN; k0 += 16) {
        #pragma unroll
        for (int i = 0; i < 8; i++) {
            int e = t + i*256;
            int row = e >> 4, kk = e & 15;
            float w = g_wtpg[(wrow0+row)*CIN + k0 + kk];
            Asd[row*36 + 2*kk]     = w;
            Asd[row*36 + 2*kk + 1] = w;
        }
        #pragma unroll
        for (int i = 0; i < 8; i++) {
            int e = t + i*256;
            int kk = e >> 7, n = e & 127;
            Bs[kk*128 + n] = xb[(size_t)(k0+kk)*NP + n0 + n];
        }
        __syncthreads();
        #pragma unroll
        for (int kk = 0; kk < 16; kk++) {
            u64 a2[8];
            #pragma unroll
            for (int i=0;i<8;i++) a2[i] = *(const u64*)&Asd[(ty*8+i)*36 + 2*kk];
            ulonglong2 b01 = *(const ulonglong2*)&Bs[kk*128 + tx*8];
            ulonglong2 b23 = *(const ulonglong2*)&Bs[kk*128 + tx*8 + 4];
            u64 bb[4] = { b01.x, b01.y, b23.x, b23.y };
            #pragma unroll
            for (int i=0;i<8;i++)
                #pragma unroll
                for (int j=0;j<4;j++) ffma2(acc[i][j], a2[i], bb[j]);
        }
        __syncthreads();
    }
    u32* dh = (which==0 ? g_th_h : which==1 ? g_ph_h : g_g_h) + (size_t)b*NP*64;
    u32* dl = (which==0 ? g_th_l : which==1 ? g_ph_l : g_g_l) + (size_t)b*NP*64;
    #pragma unroll
    for (int j = 0; j < 8; j++) {
        int col = n0 + tx*8 + j;
        float vals[8];
        #pragma unroll
        for (int i = 0; i < 8; i++) {
            float2 p = u2f(acc[i][j>>1]);
            vals[i] = (j & 1) ? p.y : p.x;
        }
        u32 h[4], lo[4];
        #pragma unroll
        for (int p = 0; p < 4; p++) {
            h[p]  = cvtbf2(vals[2*p], vals[2*p+1]);
            lo[p] = cvtbf2(vals[2*p] - blo(h[p]), vals[2*p+1] - bhi(h[p]));
        }
        *(uint4*)&dh[(size_t)col*64 + ty*4] = make_uint4(h[0],h[1],h[2],h[3]);
        *(uint4*)&dl[(size_t)col*64 + ty*4] = make_uint4(lo[0],lo[1],lo[2],lo[3]);
    }
}

// ---------------- residual path ----------------
__global__ void __launch_bounds__(256) resid_kernel(const float* __restrict__ x1,
                                                    float* __restrict__ out)
{
    extern __shared__ float Cs[];
    int b = blockIdx.y;
    int n = blockIdx.x*256 + threadIdx.x;
    for (int i = threadIdx.x; i < OC*CIN; i += 256) Cs[i] = g_C[i];
    __syncthreads();
    const float* xb = x1 + (size_t)b*CIN*NP + n;
    float acc[OC];
    #pragma unroll
    for (int o=0;o<OC;o++) acc[o] = g_cvec[o];
    for (int k = 0; k < CIN; k++) {
        float xv = xb[(size_t)k*NP];
        #pragma unroll
        for (int o=0;o<OC;o++) acc[o] = fmaf(Cs[o*CIN+k], xv, acc[o]);
    }
    float* ob = out + (size_t)b*OC*NP + n;
    #pragma unroll
    for (int o=0;o<OC;o++) ob[(size_t)o*NP] = acc[o];
}

// ---------------- warp-pair MMA flash attention (512 thr, 16 warps) ----------------
#define S_TH_H 0
#define S_TH_L 32768
#define S_PH_H 65536
#define S_PH_L 81920
#define S_G_H  98304
#define S_G_L  114688
#define S_P_H  131072
#define S_P_L  147456
#define S_PM   163840
#define S_PS   164864
#define S_AS   165888
#define S_TOTAL (165888 + OC*IC*4)

__device__ __forceinline__ void stage_tile(char* smc, int smoff, const u32* src, int rows, int t, int nthr){
    for (int idx = t; idx < rows*16; idx += nthr) {
        int r = idx >> 4, ch = idx & 15;
        uint4 v = *(const uint4*)(src + (size_t)r*64 + ch*4);
        *(uint4*)(smc + smoff + r*256 + ((ch ^ (r & 7)) * 16)) = v;
    }
}

__global__ void __launch_bounds__(512) attn_mma_kernel(float* __restrict__ out)
{
    extern __shared__ char smc[];
    u32 sb = smem_u32(smc);
    int t = threadIdx.x, lane = t & 31, w = t >> 5;
    int wp = w >> 1, h = w & 1;
    int b = blockIdx.y;
    int n0 = blockIdx.x * 128;
    size_t bn = (size_t)b * NP;

    float* As = (float*)(smc + S_AS);
    float* pm = (float*)(smc + S_PM);
    float* ps = (float*)(smc + S_PS);
    for (int i = t; i < OC*IC; i += 512) As[i] = g_A[i];

    stage_tile(smc, S_TH_H, g_th_h + (bn + n0)*64, 128, t, 512);
    stage_tile(smc, S_TH_L, g_th_l + (bn + n0)*64, 128, t, 512);

    const u32* phh = g_ph_h + bn*64;
    const u32* phl = g_ph_l + bn*64;
    const u32* ggh = g_g_h  + bn*64;
    const u32* ggl = g_g_l  + bn*64;

    float y[8][4];
    #pragma unroll
    for (int n = 0; n < 8; n++)
        #pragma unroll
        for (int i = 0; i < 4; i++) y[n][i] = 0.f;
    float m0 = -1e30f, m1 = -1e30f, l0 = 0.f, l1 = 0.f;

    int la15 = lane & 15, la7 = lane & 7;
    int lahalf = (lane >> 3) & 1, laq = lane >> 4;
    int r0 = lane >> 2;
    int qg0 = wp*16 + r0, qg1 = qg0 + 8;

    for (int j0 = 0; j0 < NP; j0 += 64) {
        __syncthreads();   // prior PV reads done
        stage_tile(smc, S_PH_H, phh + (size_t)j0*64, 64, t, 512);
        stage_tile(smc, S_PH_L, phl + (size_t)j0*64, 64, t, 512);
        stage_tile(smc, S_G_H,  ggh + (size_t)j0*64, 64, t, 512);
        stage_tile(smc, S_G_L,  ggl + (size_t)j0*64, 64, t, 512);
        __syncthreads();

        // ---- QK: S[16q x 32j] (warp's j-half) ----
        float S[4][4];
        #pragma unroll
        for (int n = 0; n < 4; n++)
            #pragma unroll
            for (int i = 0; i < 4; i++) S[n][i] = 0.f;

        #pragma unroll
        for (int k = 0; k < 8; k++) {
            u32 ah[4], al[4];
            int ar = wp*16 + la15, ach = 2*k + laq;
            ldsm4(ah, sw16(sb + S_TH_H, ar, ach));
            ldsm4(al, sw16(sb + S_TH_L, ar, ach));
            #pragma unroll
            for (int n4 = 0; n4 < 2; n4++) {
                int br = h*32 + (n4*2 + laq)*8 + la7;
                int bch = 2*k + lahalf;
                u32 bh[4], bl[4];
                ldsm4(bh, sw16(sb + S_PH_H, br, bch));
                mma16816(S[2*n4],   ah, bh[0], bh[1]);
                mma16816(S[2*n4+1], ah, bh[2], bh[3]);
                mma16816(S[2*n4],   al, bh[0], bh[1]);
                mma16816(S[2*n4+1], al, bh[2], bh[3]);
                ldsm4(bl, sw16(sb + S_PH_L, br, bch));
                mma16816(S[2*n4],   ah, bl[0], bl[1]);
                mma16816(S[2*n4+1], ah, bl[2], bl[3]);
            }
        }

        // ---- partial max exchange ----
        float tm0 = -1e30f, tm1 = -1e30f;
        #pragma unroll
        for (int n = 0; n < 4; n++) {
            tm0 = fmaxf(tm0, fmaxf(S[n][0], S[n][1]));
            tm1 = fmaxf(tm1, fmaxf(S[n][2], S[n][3]));
        }
        tm0 = fmaxf(tm0, __shfl_xor_sync(0xffffffffu, tm0, 1));
        tm0 = fmaxf(tm0, __shfl_xor_sync(0xffffffffu, tm0, 2));
        tm1 = fmaxf(tm1, __shfl_xor_sync(0xffffffffu, tm1, 1));
        tm1 = fmaxf(tm1, __shfl_xor_sync(0xffffffffu, tm1, 2));
        if ((lane & 3) == 0) { pm[h*128 + qg0] = tm0; pm[h*128 + qg1] = tm1; }
        __syncthreads();

        float nm0 = fmaxf(m0, fmaxf(pm[qg0], pm[128 + qg0]));
        float nm1 = fmaxf(m1, fmaxf(pm[qg1], pm[128 + qg1]));
        float sc0 = fexp(m0 - nm0), sc1 = fexp(m1 - nm1);
        m0 = nm0; m1 = nm1;

        float sum0 = 0.f, sum1 = 0.f;
        #pragma unroll
        for (int n = 0; n < 4; n++) {
            S[n][0] = fexp(S[n][0] - nm0);
            S[n][1] = fexp(S[n][1] - nm0);
            S[n][2] = fexp(S[n][2] - nm1);
            S[n][3] = fexp(S[n][3] - nm1);
            sum0 += S[n][0] + S[n][1];
            sum1 += S[n][2] + S[n][3];
        }
        sum0 += __shfl_xor_sync(0xffffffffu, sum0, 1);
        sum0 += __shfl_xor_sync(0xffffffffu, sum0, 2);
        sum1 += __shfl_xor_sync(0xffffffffu, sum1, 1);
        sum1 += __shfl_xor_sync(0xffffffffu, sum1, 2);
        if ((lane & 3) == 0) { ps[h*128 + qg0] = sum0; ps[h*128 + qg1] = sum1; }

        // ---- P -> bf16 hi/lo: own frags + smem for partner ----
        u32 ph_own[2][4], pl_own[2][4];
        #pragma unroll
        for (int kp = 0; kp < 2; kp++) {
            float* sa  = S[2*kp];
            float* sb2 = S[2*kp+1];
            u32 h0 = cvtbf2(sa[0], sa[1]);
            u32 h1 = cvtbf2(sa[2], sa[3]);
            u32 h2 = cvtbf2(sb2[0], sb2[1]);
            u32 h3 = cvtbf2(sb2[2], sb2[3]);
            u32 q0 = cvtbf2(sa[0]-blo(h0), sa[1]-bhi(h0));
            u32 q1 = cvtbf2(sa[2]-blo(h1), sa[3]-bhi(h1));
            u32 q2 = cvtbf2(sb2[0]-blo(h2), sb2[1]-bhi(h2));
            u32 q3 = cvtbf2(sb2[2]-blo(h3), sb2[3]-bhi(h3));
            ph_own[kp][0]=h0; ph_own[kp][1]=h1; ph_own[kp][2]=h2; ph_own[kp][3]=h3;
            pl_own[kp][0]=q0; pl_own[kp][1]=q1; pl_own[kp][2]=q2; pl_own[kp][3]=q3;
            int jA = h*32 + kp*16 + 2*(lane & 3);
            int jB = jA + 8;
            u32 a00 = (u32)qg0*128u + (u32)(((jA>>3) ^ (qg0&7))*16) + (u32)((jA&7)*2);
            u32 a10 = (u32)qg1*128u + (u32)(((jA>>3) ^ (qg1&7))*16) + (u32)((jA&7)*2);
            u32 a01 = (u32)qg0*128u + (u32)(((jB>>3) ^ (qg0&7))*16) + (u32)((jB&7)*2);
            u32 a11 = (u32)qg1*128u + (u32)(((jB>>3) ^ (qg1&7))*16) + (u32)((jB&7)*2);
            *(u32*)(smc + S_P_H + a00) = h0;  *(u32*)(smc + S_P_L + a00) = q0;
            *(u32*)(smc + S_P_H + a10) = h1;  *(u32*)(smc + S_P_L + a10) = q1;
            *(u32*)(smc + S_P_H + a01) = h2;  *(u32*)(smc + S_P_L + a01) = q2;
            *(u32*)(smc + S_P_H + a11) = h3;  *(u32*)(smc + S_P_L + a11) = q3;
        }
        __syncthreads();

        l0 = l0*sc0 + ps[qg0] + ps[128 + qg0];
        l1 = l1*sc1 + ps[qg1] + ps[128 + qg1];
        #pragma unroll
        for (int n = 0; n < 8; n++) {
            y[n][0] *= sc0; y[n][1] *= sc0;
            y[n][2] *= sc1; y[n][3] *= sc1;
        }

        // ---- PV: y[16q x 64c] (warp's c-half), all 64 j ----
        #pragma unroll
        for (int kp = 0; kp < 4; kp++) {
            u32 pa[4], pb[4];
            if ((kp >> 1) == h) {
                #pragma unroll
                for (int i = 0; i < 4; i++) { pa[i] = ph_own[kp & 1][i]; pb[i] = pl_own[kp & 1][i]; }
            } else {
                int pr = wp*16 + la15, pch = 2*kp + laq;
                ldsm4(pa, sw8(sb + S_P_H, pr, pch));
                ldsm4(pb, sw8(sb + S_P_L, pr, pch));
            }
            #pragma unroll
            for (int n8 = 0; n8 < 4; n8++) {
                int gr = kp*16 + lahalf*8 + la7;
                int gch = h*8 + 2*n8 + laq;
                u32 gh[4], gl[4];
                ldsm4t(gh, sw16(sb + S_G_H, gr, gch));
                mma16816(y[2*n8],   pa, gh[0], gh[1]);
                mma16816(y[2*n8+1], pa, gh[2], gh[3]);
                mma16816(y[2*n8],   pb, gh[0], gh[1]);
                mma16816(y[2*n8+1], pb, gh[2], gh[3]);
                ldsm4t(gl, sw16(sb + S_G_L, gr, gch));
                mma16816(y[2*n8],   pa, gl[0], gl[1]);
                mma16816(y[2*n8+1], pa, gl[2], gl[3]);
            }
        }
    }

    // ---- epilogue: ys = y/l (reuse dead smem), out += A @ ys ----
    __syncthreads();
    float* ys = (float*)smc;
    {
        float inv0 = 1.f / l0, inv1 = 1.f / l1;
        #pragma unroll
        for (int n = 0; n < 8; n++) {
            int c = h*64 + (n>>1)*16 + (n&1)*8 + 2*(lane & 3);
            ys[qg0*129 + c]     = y[n][0] * inv0;
            ys[qg0*129 + c + 1] = y[n][1] * inv0;
            ys[qg1*129 + c]     = y[n][2] * inv1;
            ys[qg1*129 + c + 1] = y[n][3] * inv1;
        }
    }
    __syncthreads();
    float* ob = out + (size_t)b*OC*NP + n0;
    #pragma unroll
    for (int i = 0; i < 5; i++) {
        int idx = t + i*512;
        int q = idx & 127, o = idx >> 7;
        float acc = 0.f;
        #pragma unroll 8
        for (int c = 0; c < IC; c++) acc = fmaf(As[o*IC+c], ys[q*129+c], acc);
        ob[(size_t)o*NP + q] += acc;
    }
}

extern "C" void kernel_launch(void* const* d_in, const int* in_sizes, int n_in,
                              void* d_out, int out_size)
{
    const float* x1     = (const float*)d_in[0];
    const float* x2     = (const float*)d_in[1];
    const float* w_conv = (const float*)d_in[2];
    const float* w_th   = (const float*)d_in[3];
    const float* w_ph   = (const float*)d_in[4];
    const float* w_g    = (const float*)d_in[5];
    const float* w_W    = (const float*)d_in[6];
    const float* b_W    = (const float*)d_in[7];
    const float* gam    = (const float*)d_in[8];
    const float* bet    = (const float*)d_in[9];
    const float* mean   = (const float*)d_in[10];
    const float* var    = (const float*)d_in[11];
    const float* w_out  = (const float*)d_in[12];
    const float* b_out  = (const float*)d_in[13];
    float* out = (float*)d_out;

    cudaFuncSetAttribute(attn_mma_kernel, cudaFuncAttributeMaxDynamicSharedMemorySize, S_TOTAL);
    cudaFuncSetAttribute(resid_kernel, cudaFuncAttributeMaxDynamicSharedMemorySize, OC*CIN*4);

    prep_kernel<<<1223, 256>>>(w_conv, w_th, w_ph, w_g, w_W, b_W, gam, bet, mean, var, w_out, b_out);
    proj_kernel<<<dim3(32, 3, BB), 256>>>(x1, x2);
    resid_kernel<<<dim3(16, BB), 256, OC*CIN*4>>>(x1, out);
    attn_mma_kernel<<<dim3(32, BB), 512, S_TOTAL>>>(out);
}

// round 7
// speedup vs baseline: 2.5032x; 1.7621x over previous
#include <cuda_runtime.h>
#include <cstdint>

typedef unsigned int u32;
typedef unsigned long long u64;

#define BB 8
#define CIN 768
#define NP 4096
#define IC 128
#define MID 256
#define OC 20

// folded weights
__device__ float g_wtpg[3*IC*CIN];
__device__ float g_C[OC*CIN];
__device__ float g_A[OC*IC];
__device__ float g_cvec[OC];
// projections as bf16 hi/lo planes, [b][n][c] packed bf16x2 (64 u32 per row)
__device__ u32 g_th_h[BB*NP*64];
__device__ u32 g_th_l[BB*NP*64];
__device__ u32 g_ph_h[BB*NP*64];
__device__ u32 g_ph_l[BB*NP*64];
__device__ u32 g_g_h [BB*NP*64];
__device__ u32 g_g_l [BB*NP*64];

__device__ __forceinline__ float fexp(float x){
    x = fmaxf(x, -80.f);
    float t = x * 1.4426950408889634f;
    float f = t + 12582912.f;
    float k = f - 12582912.f;
    float r = t - k;
    float p = 1.3333558e-3f;
    p = fmaf(p, r, 9.6181291e-3f);
    p = fmaf(p, r, 5.5504109e-2f);
    p = fmaf(p, r, 2.4022651e-1f);
    p = fmaf(p, r, 6.9314718e-1f);
    p = fmaf(p, r, 1.f);
    int ki = (int)k;
    return p * __int_as_float((ki + 127) << 23);
}

__device__ __forceinline__ u32 cvtbf2(float a, float b){
    u32 r; asm("cvt.rn.bf16x2.f32 %0, %1, %2;" : "=r"(r) : "f"(b), "f"(a)); return r;
}
__device__ __forceinline__ float blo(u32 u){ return __uint_as_float(u << 16); }
__device__ __forceinline__ float bhi(u32 u){ return __uint_as_float(u & 0xffff0000u); }

__device__ __forceinline__ u32 smem_u32(const void* p){
    u32 a; asm("{ .reg .u64 t; cvta.to.shared.u64 t, %1; cvt.u32.u64 %0, t; }" : "=r"(a) : "l"(p)); return a;
}

// ---------------- mma / ldmatrix ----------------
__device__ __forceinline__ void mma16816(float* d, const u32* a, u32 b0, u32 b1){
    asm volatile("mma.sync.aligned.m16n8k16.row.col.f32.bf16.bf16.f32 "
        "{%0,%1,%2,%3}, {%4,%5,%6,%7}, {%8,%9}, {%0,%1,%2,%3};"
        : "+f"(d[0]), "+f"(d[1]), "+f"(d[2]), "+f"(d[3])
        : "r"(a[0]), "r"(a[1]), "r"(a[2]), "r"(a[3]), "r"(b0), "r"(b1));
}
__device__ __forceinline__ void ldsm4(u32* r, u32 addr){
    asm volatile("ldmatrix.sync.aligned.m8n8.x4.shared.b16 {%0,%1,%2,%3}, [%4];"
        : "=r"(r[0]), "=r"(r[1]), "=r"(r[2]), "=r"(r[3]) : "r"(addr));
}
__device__ __forceinline__ void ldsm4t(u32* r, u32 addr){
    asm volatile("ldmatrix.sync.aligned.m8n8.x4.trans.shared.b16 {%0,%1,%2,%3}, [%4];"
        : "=r"(r[0]), "=r"(r[1]), "=r"(r[2]), "=r"(r[3]) : "r"(addr));
}

// 256B rows (16 chunks of 16B), swizzle chunk ^= (row&7)
__device__ __forceinline__ u32 sw16(u32 base, int row, int ch){
    return base + (u32)row*256u + (u32)((ch ^ (row & 7)) * 16);
}
// 128B rows (8 chunks of 16B)
__device__ __forceinline__ u32 sw8(u32 base, int row, int ch){
    return base + (u32)row*128u + (u32)((ch ^ (row & 7)) * 16);
}

#define CP16(dst, src) asm volatile("cp.async.cg.shared.global [%0], [%1], 16;" :: "r"(dst), "l"(src) : "memory")
#define CP_COMMIT()    asm volatile("cp.async.commit_group;" ::: "memory")
#define CP_WAIT1()     asm volatile("cp.async.wait_group 1;" ::: "memory")
#define CP_WAIT0()     asm volatile("cp.async.wait_group 0;" ::: "memory")
#define BAR_PAIR(id)   asm volatile("bar.sync %0, 64;" :: "r"(id) : "memory")

// ---------------- prep ----------------
__global__ void __launch_bounds__(256) prep_kernel(
    const float* __restrict__ wc, const float* __restrict__ wt,
    const float* __restrict__ wp, const float* __restrict__ wg,
    const float* __restrict__ wW, const float* __restrict__ bW,
    const float* __restrict__ gam, const float* __restrict__ bet,
    const float* __restrict__ mean, const float* __restrict__ var,
    const float* __restrict__ wo, const float* __restrict__ bo)
{
    int gid = blockIdx.x*256 + threadIdx.x;
    if (gid < 3*IC*CIN) {
        int r = gid / CIN, k = gid % CIN;
        const float* ws = (r < IC) ? wt : (r < 2*IC) ? wp : wg;
        int rr = r & (IC-1);
        float acc = 0.f;
        for (int m = 0; m < MID; m++) acc = fmaf(ws[rr*MID+m], wc[m*CIN+k], acc);
        g_wtpg[gid] = acc;
        return;
    }
    int idx = gid - 3*IC*CIN;
    if (idx < OC*CIN) {
        int o = idx / CIN, k = idx % CIN;
        float acc = 0.f;
        for (int m = 0; m < MID; m++) acc = fmaf(wo[o*MID+m], wc[m*CIN+k], acc);
        g_C[idx] = acc;
        return;
    }
    idx -= OC*CIN;
    if (idx < OC*IC) {
        int o = idx / IC, i = idx % IC;
        float acc = 0.f;
        for (int m = 0; m < MID; m++) {
            float inv = gam[m] * rsqrtf(var[m] + 1e-5f);
            acc = fmaf(wo[o*MID+m]*inv, wW[m*IC+i], acc);
        }
        g_A[idx] = acc;
        return;
    }
    idx -= OC*IC;
    if (idx < OC) {
        float acc = bo[idx];
        for (int m = 0; m < MID; m++) {
            float inv = gam[m] * rsqrtf(var[m] + 1e-5f);
            acc += wo[idx*MID+m] * (bW[m]*inv + bet[m] - mean[m]*inv);
        }
        g_cvec[idx] = acc;
    }
}

// ---------------- tensorized projections ----------------
// out[128 ch x 128 n] = Wf[128x768] @ x[768 x n-tile], split-bf16 3-term MMA.
#define PJ_WH 0
#define PJ_WL 16384
#define PJ_XH 32768
#define PJ_XL 49152
#define PJ_TOTAL 67584   // also holds 128x132 fp32 out tile at the end

__global__ void __launch_bounds__(256) proj_kernel(const float* __restrict__ x1,
                                                   const float* __restrict__ x2)
{
    extern __shared__ char smc[];
    u32 sb = smem_u32(smc);
    int t = threadIdx.x, lane = t & 31, w = t >> 5;
    int n0 = blockIdx.x * 128;
    int which = blockIdx.y;
    int b = blockIdx.z;
    const float* xb = (which == 0 ? x1 : x2) + (size_t)b * CIN * NP;
    const float* wf = g_wtpg + (size_t)which * IC * CIN;

    int la15 = lane & 15, la7 = lane & 7;
    int lahalf = (lane >> 3) & 1, laq = lane >> 4;

    float acc[16][4];
    #pragma unroll
    for (int n = 0; n < 16; n++)
        #pragma unroll
        for (int i = 0; i < 4; i++) acc[n][i] = 0.f;

    for (int k0 = 0; k0 < CIN; k0 += 64) {
        __syncthreads();
        // stage W chunk [128 ch x 64 k] -> bf16 hi/lo (sw8 rows)
        #pragma unroll
        for (int i = 0; i < 8; i++) {
            int e = t + i*256;
            int ch = e >> 4, kq = e & 15;
            float4 v = *(const float4*)&wf[(size_t)ch*CIN + k0 + kq*4];
            u32 h0 = cvtbf2(v.x, v.y), h1 = cvtbf2(v.z, v.w);
            u32 l0 = cvtbf2(v.x - blo(h0), v.y - bhi(h0));
            u32 l1 = cvtbf2(v.z - blo(h1), v.w - bhi(h1));
            u32 off = (u32)ch*128u + (u32)((((kq>>1) ^ (ch&7)))*16) + (u32)((kq&1)*8);
            *(uint2*)(smc + PJ_WH + off) = make_uint2(h0, h1);
            *(uint2*)(smc + PJ_WL + off) = make_uint2(l0, l1);
        }
        // stage x chunk [64 k x 128 n] -> bf16 hi/lo (sw16 rows)
        #pragma unroll
        for (int i = 0; i < 8; i++) {
            int e = t + i*256;
            int k = e >> 5, nq = e & 31;
            float4 v = *(const float4*)&xb[(size_t)(k0+k)*NP + n0 + nq*4];
            u32 h0 = cvtbf2(v.x, v.y), h1 = cvtbf2(v.z, v.w);
            u32 l0 = cvtbf2(v.x - blo(h0), v.y - bhi(h0));
            u32 l1 = cvtbf2(v.z - blo(h1), v.w - bhi(h1));
            u32 off = (u32)k*256u + (u32)((((nq>>1) ^ (k&7)))*16) + (u32)((nq&1)*8);
            *(uint2*)(smc + PJ_XH + off) = make_uint2(h0, h1);
            *(uint2*)(smc + PJ_XL + off) = make_uint2(l0, l1);
        }
        __syncthreads();

        #pragma unroll
        for (int ks = 0; ks < 4; ks++) {
            u32 ah[4], al[4];
            int ar = w*16 + la15, ach = 2*ks + laq;
            ldsm4(ah, sw8(sb + PJ_WH, ar, ach));
            ldsm4(al, sw8(sb + PJ_WL, ar, ach));
            int kr = ks*16 + lahalf*8 + la7;
            #pragma unroll
            for (int nn = 0; nn < 8; nn++) {
                int bch = 2*nn + laq;
                u32 bh[4], bl[4];
                ldsm4t(bh, sw16(sb + PJ_XH, kr, bch));
                mma16816(acc[2*nn],   ah, bh[0], bh[1]);
                mma16816(acc[2*nn+1], ah, bh[2], bh[3]);
                mma16816(acc[2*nn],   al, bh[0], bh[1]);
                mma16816(acc[2*nn+1], al, bh[2], bh[3]);
                ldsm4t(bl, sw16(sb + PJ_XL, kr, bch));
                mma16816(acc[2*nn],   ah, bl[0], bl[1]);
                mma16816(acc[2*nn+1], ah, bl[2], bl[3]);
            }
        }
    }

    // dump fp32 out tile [ch][n], stride 132
    __syncthreads();
    float* outS = (float*)smc;
    {
        int r = w*16 + (lane >> 2);
        #pragma unroll
        for (int nn = 0; nn < 16; nn++) {
            int n = nn*8 + 2*(lane & 3);
            outS[r*132 + n]       = acc[nn][0];
            outS[r*132 + n + 1]   = acc[nn][1];
            outS[(r+8)*132 + n]     = acc[nn][2];
            outS[(r+8)*132 + n + 1] = acc[nn][3];
        }
    }
    __syncthreads();

    // transposed write: [n][c] bf16 hi/lo planes
    u32* dh = (which==0 ? g_th_h : which==1 ? g_ph_h : g_g_h) + (size_t)b*NP*64;
    u32* dl = (which==0 ? g_th_l : which==1 ? g_ph_l : g_g_l) + (size_t)b*NP*64;
    {
        int n = t >> 1, half = t & 1;
        u32 hb[32], lb[32];
        #pragma unroll
        for (int p = 0; p < 32; p++) {
            int c = half*64 + 2*p;
            float f0 = outS[c*132 + n];
            float f1 = outS[(c+1)*132 + n];
            u32 h = cvtbf2(f0, f1);
            hb[p] = h;
            lb[p] = cvtbf2(f0 - blo(h), f1 - bhi(h));
        }
        u32* ph_ = dh + (size_t)(n0 + n)*64 + half*32;
        u32* pl_ = dl + (size_t)(n0 + n)*64 + half*32;
        #pragma unroll
        for (int q = 0; q < 8; q++) {
            *(uint4*)(ph_ + q*4) = make_uint4(hb[4*q], hb[4*q+1], hb[4*q+2], hb[4*q+3]);
            *(uint4*)(pl_ + q*4) = make_uint4(lb[4*q], lb[4*q+1], lb[4*q+2], lb[4*q+3]);
        }
    }
}

// ---------------- residual path ----------------
__global__ void __launch_bounds__(256) resid_kernel(const float* __restrict__ x1,
                                                    float* __restrict__ out)
{
    extern __shared__ float Cs[];
    int b = blockIdx.y;
    int n = blockIdx.x*256 + threadIdx.x;
    for (int i = threadIdx.x; i < OC*CIN; i += 256) Cs[i] = g_C[i];
    __syncthreads();
    const float* xb = x1 + (size_t)b*CIN*NP + n;
    float acc[OC];
    #pragma unroll
    for (int o=0;o<OC;o++) acc[o] = g_cvec[o];
    for (int k = 0; k < CIN; k++) {
        float xv = xb[(size_t)k*NP];
        #pragma unroll
        for (int o=0;o<OC;o++) acc[o] = fmaf(Cs[o*CIN+k], xv, acc[o]);
    }
    float* ob = out + (size_t)b*OC*NP + n;
    #pragma unroll
    for (int o=0;o<OC;o++) ob[(size_t)o*NP] = acc[o];
}

// ---------------- warp-pair MMA flash attention, cp.async double-buffered ----------------
// per-buffer sub-offsets
#define PH_H 0
#define PH_L 16384
#define G_H  32768
#define G_L  49152
#define BUFSZ 65536
// fixed regions
#define S_TH_H 131072
#define S_TH_L 163840
#define S_P_H  196608
#define S_P_L  212992
#define S_PM   229376
#define S_PS   230400
#define S_TOTAL 231424

__device__ __forceinline__ void stage_plane_async(u32 sdst, const u32* __restrict__ src,
                                                  int rows, int t, int nthr){
    for (int idx = t; idx < rows*16; idx += nthr) {
        int r = idx >> 4, ch = idx & 15;
        CP16(sdst + (u32)r*256u + (u32)((ch ^ (r & 7)) * 16), src + (size_t)r*64 + ch*4);
    }
}

__global__ void __launch_bounds__(512) attn_mma_kernel(float* __restrict__ out)
{
    extern __shared__ char smc[];
    u32 sb = smem_u32(smc);
    int t = threadIdx.x, lane = t & 31, w = t >> 5;
    int wp = w >> 1, h = w & 1;
    int b = blockIdx.y;
    int n0 = blockIdx.x * 128;
    size_t bn = (size_t)b * NP;

    float* pm = (float*)(smc + S_PM);
    float* ps = (float*)(smc + S_PS);

    const u32* phh = g_ph_h + bn*64;
    const u32* phl = g_ph_l + bn*64;
    const u32* ggh = g_g_h  + bn*64;
    const u32* ggl = g_g_l  + bn*64;

    // prologue: theta (persistent) + tile 0 into buf0, one cp.async group
    stage_plane_async(sb + S_TH_H, g_th_h + (bn + n0)*64, 128, t, 512);
    stage_plane_async(sb + S_TH_L, g_th_l + (bn + n0)*64, 128, t, 512);
    stage_plane_async(sb + PH_H, phh, 64, t, 512);
    stage_plane_async(sb + PH_L, phl, 64, t, 512);
    stage_plane_async(sb + G_H,  ggh, 64, t, 512);
    stage_plane_async(sb + G_L,  ggl, 64, t, 512);
    CP_COMMIT();

    float y[8][4];
    #pragma unroll
    for (int n = 0; n < 8; n++)
        #pragma unroll
        for (int i = 0; i < 4; i++) y[n][i] = 0.f;
    float m0 = -1e30f, m1 = -1e30f, l0 = 0.f, l1 = 0.f;

    int la15 = lane & 15, la7 = lane & 7;
    int lahalf = (lane >> 3) & 1, laq = lane >> 4;
    int r0 = lane >> 2;
    int qg0 = wp*16 + r0, qg1 = qg0 + 8;
    int barid = wp + 1;

    for (int jt = 0; jt < 64; jt++) {
        int cur = jt & 1;
        u32 buf = sb + (u32)cur * BUFSZ;
        if (jt < 63) {
            u32 nbuf = sb + (u32)(1 - cur) * BUFSZ;
            size_t jn = (size_t)(jt + 1) * 64 * 64;
            stage_plane_async(nbuf + PH_H, phh + jn, 64, t, 512);
            stage_plane_async(nbuf + PH_L, phl + jn, 64, t, 512);
            stage_plane_async(nbuf + G_H,  ggh + jn, 64, t, 512);
            stage_plane_async(nbuf + G_L,  ggl + jn, 64, t, 512);
            CP_COMMIT();
            CP_WAIT1();
        } else {
            CP_WAIT0();
        }
        __syncthreads();

        // ---- QK: S[16q x 32j] (warp's j-half) ----
        float S[4][4];
        #pragma unroll
        for (int n = 0; n < 4; n++)
            #pragma unroll
            for (int i = 0; i < 4; i++) S[n][i] = 0.f;

        #pragma unroll
        for (int k = 0; k < 8; k++) {
            u32 ah[4], al[4];
            int ar = wp*16 + la15, ach = 2*k + laq;
            ldsm4(ah, sw16(sb + S_TH_H, ar, ach));
            ldsm4(al, sw16(sb + S_TH_L, ar, ach));
            #pragma unroll
            for (int n4 = 0; n4 < 2; n4++) {
                int br = h*32 + (n4*2 + laq)*8 + la7;
                int bch = 2*k + lahalf;
                u32 bh[4], bl[4];
                ldsm4(bh, sw16(buf + PH_H, br, bch));
                mma16816(S[2*n4],   ah, bh[0], bh[1]);
                mma16816(S[2*n4+1], ah, bh[2], bh[3]);
                mma16816(S[2*n4],   al, bh[0], bh[1]);
                mma16816(S[2*n4+1], al, bh[2], bh[3]);
                ldsm4(bl, sw16(buf + PH_L, br, bch));
                mma16816(S[2*n4],   ah, bl[0], bl[1]);
                mma16816(S[2*n4+1], ah, bl[2], bl[3]);
            }
        }

        // ---- partial max exchange (pair-local) ----
        float tm0 = -1e30f, tm1 = -1e30f;
        #pragma unroll
        for (int n = 0; n < 4; n++) {
            tm0 = fmaxf(tm0, fmaxf(S[n][0], S[n][1]));
            tm1 = fmaxf(tm1, fmaxf(S[n][2], S[n][3]));
        }
        tm0 = fmaxf(tm0, __shfl_xor_sync(0xffffffffu, tm0, 1));
        tm0 = fmaxf(tm0, __shfl_xor_sync(0xffffffffu, tm0, 2));
        tm1 = fmaxf(tm1, __shfl_xor_sync(0xffffffffu, tm1, 1));
        tm1 = fmaxf(tm1, __shfl_xor_sync(0xffffffffu, tm1, 2));
        if ((lane & 3) == 0) { pm[h*128 + qg0] = tm0; pm[h*128 + qg1] = tm1; }
        BAR_PAIR(barid);

        float nm0 = fmaxf(m0, fmaxf(pm[qg0], pm[128 + qg0]));
        float nm1 = fmaxf(m1, fmaxf(pm[qg1], pm[128 + qg1]));
        float sc0 = fexp(m0 - nm0), sc1 = fexp(m1 - nm1);
        m0 = nm0; m1 = nm1;

        float sum0 = 0.f, sum1 = 0.f;
        #pragma unroll
        for (int n = 0; n < 4; n++) {
            S[n][0] = fexp(S[n][0] - nm0);
            S[n][1] = fexp(S[n][1] - nm0);
            S[n][2] = fexp(S[n][2] - nm1);
            S[n][3] = fexp(S[n][3] - nm1);
            sum0 += S[n][0] + S[n][1];
            sum1 += S[n][2] + S[n][3];
        }
        sum0 += __shfl_xor_sync(0xffffffffu, sum0, 1);
        sum0 += __shfl_xor_sync(0xffffffffu, sum0, 2);
        sum1 += __shfl_xor_sync(0xffffffffu, sum1, 1);
        sum1 += __shfl_xor_sync(0xffffffffu, sum1, 2);
        if ((lane & 3) == 0) { ps[h*128 + qg0] = sum0; ps[h*128 + qg1] = sum1; }

        // ---- P -> bf16 hi/lo: own frags + smem for partner ----
        u32 ph_own[2][4], pl_own[2][4];
        #pragma unroll
        for (int kp = 0; kp < 2; kp++) {
            float* sa  = S[2*kp];
            float* sb2 = S[2*kp+1];
            u32 h0 = cvtbf2(sa[0], sa[1]);
            u32 h1 = cvtbf2(sa[2], sa[3]);
            u32 h2 = cvtbf2(sb2[0], sb2[1]);
            u32 h3 = cvtbf2(sb2[2], sb2[3]);
            u32 q0 = cvtbf2(sa[0]-blo(h0), sa[1]-bhi(h0));
            u32 q1 = cvtbf2(sa[2]-blo(h1), sa[3]-bhi(h1));
            u32 q2 = cvtbf2(sb2[0]-blo(h2), sb2[1]-bhi(h2));
            u32 q3 = cvtbf2(sb2[2]-blo(h3), sb2[3]-bhi(h3));
            ph_own[kp][0]=h0; ph_own[kp][1]=h1; ph_own[kp][2]=h2; ph_own[kp][3]=h3;
            pl_own[kp][0]=q0; pl_own[kp][1]=q1; pl_own[kp][2]=q2; pl_own[kp][3]=q3;
            int jA = h*32 + kp*16 + 2*(lane & 3);
            int jB = jA + 8;
            u32 a00 = (u32)qg0*128u + (u32)(((jA>>3) ^ (qg0&7))*16) + (u32)((jA&7)*2);
            u32 a10 = (u32)qg1*128u + (u32)(((jA>>3) ^ (qg1&7))*16) + (u32)((jA&7)*2);
            u32 a01 = (u32)qg0*128u + (u32)(((jB>>3) ^ (qg0&7))*16) + (u32)((jB&7)*2);
            u32 a11 = (u32)qg1*128u + (u32)(((jB>>3) ^ (qg1&7))*16) + (u32)((jB&7)*2);
            *(u32*)(smc + S_P_H + a00) = h0;  *(u32*)(smc + S_P_L + a00) = q0;
            *(u32*)(smc + S_P_H + a10) = h1;  *(u32*)(smc + S_P_L + a10) = q1;
            *(u32*)(smc + S_P_H + a01) = h2;  *(u32*)(smc + S_P_L + a01) = q2;
            *(u32*)(smc + S_P_H + a11) = h3;  *(u32*)(smc + S_P_L + a11) = q3;
        }
        BAR_PAIR(barid);

        l0 = l0*sc0 + ps[qg0] + ps[128 + qg0];
        l1 = l1*sc1 + ps[qg1] + ps[128 + qg1];
        #pragma unroll
        for (int n = 0; n < 8; n++) {
            y[n][0] *= sc0; y[n][1] *= sc0;
            y[n][2] *= sc1; y[n][3] *= sc1;
        }

        // ---- PV: y[16q x 64c] (warp's c-half), all 64 j ----
        #pragma unroll
        for (int kp = 0; kp < 4; kp++) {
            u32 pa[4], pb[4];
            if ((kp >> 1) == h) {
                #pragma unroll
                for (int i = 0; i < 4; i++) { pa[i] = ph_own[kp & 1][i]; pb[i] = pl_own[kp & 1][i]; }
            } else {
                int pr = wp*16 + la15, pch = 2*kp + laq;
                ldsm4(pa, sw8(sb + S_P_H, pr, pch));
                ldsm4(pb, sw8(sb + S_P_L, pr, pch));
            }
            #pragma unroll
            for (int n8 = 0; n8 < 4; n8++) {
                int gr = kp*16 + lahalf*8 + la7;
                int gch = h*8 + 2*n8 + laq;
                u32 gh[4], gl[4];
                ldsm4t(gh, sw16(buf + G_H, gr, gch));
                mma16816(y[2*n8],   pa, gh[0], gh[1]);
                mma16816(y[2*n8+1], pa, gh[2], gh[3]);
                mma16816(y[2*n8],   pb, gh[0], gh[1]);
                mma16816(y[2*n8+1], pb, gh[2], gh[3]);
                ldsm4t(gl, sw16(buf + G_L, gr, gch));
                mma16816(y[2*n8],   pa, gl[0], gl[1]);
                mma16816(y[2*n8+1], pa, gl[2], gl[3]);
            }
        }
        __syncthreads();
    }

    // ---- epilogue: ys = y/l (reuse buf smem), As into dead P region ----
    float* ys = (float*)smc;
    float* As = (float*)(smc + S_P_H);
    for (int i = t; i < OC*IC; i += 512) As[i] = g_A[i];
    {
        float inv0 = 1.f / l0, inv1 = 1.f / l1;
        #pragma unroll
        for (int n = 0; n < 8; n++) {
            int c = h*64 + (n>>1)*16 + (n&1)*8 + 2*(lane & 3);
            ys[qg0*129 + c]     = y[n][0] * inv0;
            ys[qg0*129 + c + 1] = y[n][1] * inv0;
            ys[qg1*129 + c]     = y[n][2] * inv1;
            ys[qg1*129 + c + 1] = y[n][3] * inv1;
        }
    }
    __syncthreads();
    float* ob = out + (size_t)b*OC*NP + n0;
    #pragma unroll
    for (int i = 0; i < 5; i++) {
        int idx = t + i*512;
        int q = idx & 127, o = idx >> 7;
        float acc = 0.f;
        #pragma unroll 8
        for (int c = 0; c < IC; c++) acc = fmaf(As[o*IC+c], ys[q*129+c], acc);
        ob[(size_t)o*NP + q] += acc;
    }
}

extern "C" void kernel_launch(void* const* d_in, const int* in_sizes, int n_in,
                              void* d_out, int out_size)
{
    const float* x1     = (const float*)d_in[0];
    const float* x2     = (const float*)d_in[1];
    const float* w_conv = (const float*)d_in[2];
    const float* w_th   = (const float*)d_in[3];
    const float* w_ph   = (const float*)d_in[4];
    const float* w_g    = (const float*)d_in[5];
    const float* w_W    = (const float*)d_in[6];
    const float* b_W    = (const float*)d_in[7];
    const float* gam    = (const float*)d_in[8];
    const float* bet    = (const float*)d_in[9];
    const float* mean   = (const float*)d_in[10];
    const float* var    = (const float*)d_in[11];
    const float* w_out  = (const float*)d_in[12];
    const float* b_out  = (const float*)d_in[13];
    float* out = (float*)d_out;

    cudaFuncSetAttribute(attn_mma_kernel, cudaFuncAttributeMaxDynamicSharedMemorySize, S_TOTAL);
    cudaFuncSetAttribute(proj_kernel, cudaFuncAttributeMaxDynamicSharedMemorySize, PJ_TOTAL);
    cudaFuncSetAttribute(resid_kernel, cudaFuncAttributeMaxDynamicSharedMemorySize, OC*CIN*4);

    prep_kernel<<<1223, 256>>>(w_conv, w_th, w_ph, w_g, w_W, b_W, gam, bet, mean, var, w_out, b_out);
    proj_kernel<<<dim3(32, 3, BB), 256, PJ_TOTAL>>>(x1, x2);
    resid_kernel<<<dim3(16, BB), 256, OC*CIN*4>>>(x1, out);
    attn_mma_kernel<<<dim3(32, BB), 512, S_TOTAL>>>(out);
}

// round 9
// speedup vs baseline: 2.5369x; 1.0135x over previous
#include <cuda_runtime.h>
#include <cstdint>

typedef unsigned int u32;
typedef unsigned long long u64;

#define BB 8
#define CIN 768
#define NP 4096
#define IC 128
#define MID 256
#define OC 20

// folded weights
__device__ float g_wtpg[3*IC*CIN];
__device__ float g_C[OC*CIN];
__device__ float g_A[OC*IC];
__device__ float g_cvec[OC];
// pre-split folded weights, bf16 hi/lo planes [3*IC][384] (u32 = bf16x2)
__device__ u32 g_w_h[3*IC*384];
__device__ u32 g_w_l[3*IC*384];
// projections as bf16 hi/lo planes, [b][n][c] packed bf16x2 (64 u32 per row)
__device__ u32 g_th_h[BB*NP*64];
__device__ u32 g_th_l[BB*NP*64];
__device__ u32 g_ph_h[BB*NP*64];
__device__ u32 g_ph_l[BB*NP*64];
__device__ u32 g_g_h [BB*NP*64];
__device__ u32 g_g_l [BB*NP*64];

__device__ __forceinline__ float fexp(float x){
    x = fmaxf(x, -80.f);
    float t = x * 1.4426950408889634f;
    float f = t + 12582912.f;
    float k = f - 12582912.f;
    float r = t - k;
    float p = 1.3333558e-3f;
    p = fmaf(p, r, 9.6181291e-3f);
    p = fmaf(p, r, 5.5504109e-2f);
    p = fmaf(p, r, 2.4022651e-1f);
    p = fmaf(p, r, 6.9314718e-1f);
    p = fmaf(p, r, 1.f);
    int ki = (int)k;
    return p * __int_as_float((ki + 127) << 23);
}

__device__ __forceinline__ u32 cvtbf2(float a, float b){
    u32 r; asm("cvt.rn.bf16x2.f32 %0, %1, %2;" : "=r"(r) : "f"(b), "f"(a)); return r;
}
__device__ __forceinline__ float blo(u32 u){ return __uint_as_float(u << 16); }
__device__ __forceinline__ float bhi(u32 u){ return __uint_as_float(u & 0xffff0000u); }

__device__ __forceinline__ u32 smem_u32(const void* p){
    u32 a; asm("{ .reg .u64 t; cvta.to.shared.u64 t, %1; cvt.u32.u64 %0, t; }" : "=r"(a) : "l"(p)); return a;
}

// ---------------- mma / ldmatrix ----------------
__device__ __forceinline__ void mma16816(float* d, const u32* a, u32 b0, u32 b1){
    asm volatile("mma.sync.aligned.m16n8k16.row.col.f32.bf16.bf16.f32 "
        "{%0,%1,%2,%3}, {%4,%5,%6,%7}, {%8,%9}, {%0,%1,%2,%3};"
        : "+f"(d[0]), "+f"(d[1]), "+f"(d[2]), "+f"(d[3])
        : "r"(a[0]), "r"(a[1]), "r"(a[2]), "r"(a[3]), "r"(b0), "r"(b1));
}
__device__ __forceinline__ void ldsm4(u32* r, u32 addr){
    asm volatile("ldmatrix.sync.aligned.m8n8.x4.shared.b16 {%0,%1,%2,%3}, [%4];"
        : "=r"(r[0]), "=r"(r[1]), "=r"(r[2]), "=r"(r[3]) : "r"(addr));
}
__device__ __forceinline__ void ldsm4t(u32* r, u32 addr){
    asm volatile("ldmatrix.sync.aligned.m8n8.x4.trans.shared.b16 {%0,%1,%2,%3}, [%4];"
        : "=r"(r[0]), "=r"(r[1]), "=r"(r[2]), "=r"(r[3]) : "r"(addr));
}

// 256B rows (16 chunks of 16B), swizzle chunk ^= (row&7)
__device__ __forceinline__ u32 sw16(u32 base, int row, int ch){
    return base + (u32)row*256u + (u32)((ch ^ (row & 7)) * 16);
}
// 128B rows (8 chunks of 16B)
__device__ __forceinline__ u32 sw8(u32 base, int row, int ch){
    return base + (u32)row*128u + (u32)((ch ^ (row & 7)) * 16);
}

#define CP16(dst, src) asm volatile("cp.async.cg.shared.global [%0], [%1], 16;" :: "r"(dst), "l"(src) : "memory")
#define CP_COMMIT()    asm volatile("cp.async.commit_group;" ::: "memory")
#define CP_WAIT1()     asm volatile("cp.async.wait_group 1;" ::: "memory")
#define CP_WAIT0()     asm volatile("cp.async.wait_group 0;" ::: "memory")
#define BAR_PAIR(id)   asm volatile("bar.sync %0, 64;" :: "r"(id) : "memory")

// ---------------- prep ----------------
__global__ void __launch_bounds__(256) prep_kernel(
    const float* __restrict__ wc, const float* __restrict__ wt,
    const float* __restrict__ wp, const float* __restrict__ wg,
    const float* __restrict__ wW, const float* __restrict__ bW,
    const float* __restrict__ gam, const float* __restrict__ bet,
    const float* __restrict__ mean, const float* __restrict__ var,
    const float* __restrict__ wo, const float* __restrict__ bo)
{
    int gid = blockIdx.x*256 + threadIdx.x;
    if (gid < 3*IC*CIN) {
        int r = gid / CIN, k = gid % CIN;
        const float* ws = (r < IC) ? wt : (r < 2*IC) ? wp : wg;
        int rr = r & (IC-1);
        float acc = 0.f;
        for (int m = 0; m < MID; m++) acc = fmaf(ws[rr*MID+m], wc[m*CIN+k], acc);
        g_wtpg[gid] = acc;
        return;
    }
    int idx = gid - 3*IC*CIN;
    if (idx < OC*CIN) {
        int o = idx / CIN, k = idx % CIN;
        float acc = 0.f;
        for (int m = 0; m < MID; m++) acc = fmaf(wo[o*MID+m], wc[m*CIN+k], acc);
        g_C[idx] = acc;
        return;
    }
    idx -= OC*CIN;
    if (idx < OC*IC) {
        int o = idx / IC, i = idx % IC;
        float acc = 0.f;
        for (int m = 0; m < MID; m++) {
            float inv = gam[m] * rsqrtf(var[m] + 1e-5f);
            acc = fmaf(wo[o*MID+m]*inv, wW[m*IC+i], acc);
        }
        g_A[idx] = acc;
        return;
    }
    idx -= OC*IC;
    if (idx < OC) {
        float acc = bo[idx];
        for (int m = 0; m < MID; m++) {
            float inv = gam[m] * rsqrtf(var[m] + 1e-5f);
            acc += wo[idx*MID+m] * (bW[m]*inv + bet[m] - mean[m]*inv);
        }
        g_cvec[idx] = acc;
    }
}

// pack folded weights into bf16 hi/lo planes
__global__ void __launch_bounds__(256) prep2_kernel()
{
    int gid = blockIdx.x*256 + threadIdx.x;
    if (gid >= 3*IC*384) return;
    int r = gid / 384, kk = gid % 384;
    float f0 = g_wtpg[r*CIN + 2*kk];
    float f1 = g_wtpg[r*CIN + 2*kk + 1];
    u32 h = cvtbf2(f0, f1);
    g_w_h[gid] = h;
    g_w_l[gid] = cvtbf2(f0 - blo(h), f1 - bhi(h));
}

// ---------------- tensorized projections, cp.async pipelined (race-free) ----------------
// smem map (bytes):
//  [0, 65536)        W bufs: 2 x (hi 16K + lo 16K)
//  [65536, 131072)   x raw fp32: 2 x 32K
//  [131072, 196608)  XH0/XL0/XH1/XL1 16K each
#define PJ_XRAW 65536
#define PJ_XH0  131072
#define PJ_TOTAL 196608

__global__ void __launch_bounds__(256) proj_kernel(const float* __restrict__ x1,
                                                   const float* __restrict__ x2)
{
    extern __shared__ char smc[];
    u32 sb = smem_u32(smc);
    int t = threadIdx.x, lane = t & 31, w = t >> 5;
    int n0 = blockIdx.x * 128;
    int which = blockIdx.y;
    int b = blockIdx.z;
    const float* xb = (which == 0 ? x1 : x2) + (size_t)b * CIN * NP;
    const u32* wbase_h = g_w_h + (size_t)which * IC * 384;
    const u32* wbase_l = g_w_l + (size_t)which * IC * 384;

    int la15 = lane & 15, la7 = lane & 7;
    int lahalf = (lane >> 3) & 1, laq = lane >> 4;

    float acc[16][4];
    #pragma unroll
    for (int n = 0; n < 16; n++)
        #pragma unroll
        for (int i = 0; i < 4; i++) acc[n][i] = 0.f;

    #define PJ_STAGE(c_) do { \
        int cur_ = (c_) & 1; int k0_ = (c_) * 64; \
        _Pragma("unroll") \
        for (int i = 0; i < 8; i++) { \
            int e = t + i*256; \
            int p = e >> 10, rest = e & 1023; \
            int ch = rest >> 3, q = rest & 7; \
            u32 dst = sb + (u32)cur_*32768u + (u32)p*16384u + (u32)ch*128u + (u32)(((q ^ (ch & 7)))*16); \
            const u32* src = (p ? wbase_l : wbase_h) + (size_t)ch*384 + (k0_ >> 1) + q*4; \
            CP16(dst, src); \
        } \
        _Pragma("unroll") \
        for (int i = 0; i < 8; i++) { \
            int e = t + i*256; \
            int r = e >> 5, cc = e & 31; \
            u32 dst = sb + PJ_XRAW + (u32)cur_*32768u + (u32)r*512u + (u32)cc*16u; \
            const float* src = xb + (size_t)(k0_ + r)*NP + n0 + cc*4; \
            CP16(dst, src); \
        } \
        CP_COMMIT(); \
    } while(0)

    PJ_STAGE(0);
    for (int c = 0; c < 12; c++) {
        int cur = c & 1;
        CP_WAIT0();          // tile c landed (single group in flight)
        __syncthreads();     // ALSO orders all warps' MMA(c-1) before any overwrite below
        if (c < 11) PJ_STAGE(c + 1);   // safe: MMA(c-1) readers of buffer (c+1)&1 are done

        // convert raw fp32 -> bf16 hi/lo (parity buffers)
        u32 xh = sb + PJ_XH0 + (u32)cur*32768u;
        u32 xl = xh + 16384u;
        #pragma unroll
        for (int i = 0; i < 8; i++) {
            int e = t + i*256;
            int k = e >> 5, nq = e & 31;
            float4 v = *(const float4*)(smc + PJ_XRAW + cur*32768 + k*512 + nq*16);
            u32 h0 = cvtbf2(v.x, v.y), h1 = cvtbf2(v.z, v.w);
            u32 l0 = cvtbf2(v.x - blo(h0), v.y - bhi(h0));
            u32 l1 = cvtbf2(v.z - blo(h1), v.w - bhi(h1));
            u32 off = (u32)k*256u + (u32)((((nq>>1) ^ (k&7)))*16) + (u32)((nq&1)*8);
            *(uint2*)(smc + (xh - sb) + off) = make_uint2(h0, h1);
            *(uint2*)(smc + (xl - sb) + off) = make_uint2(l0, l1);
        }
        __syncthreads();

        u32 wh = sb + (u32)cur*32768u, wl = wh + 16384u;
        #pragma unroll
        for (int ks = 0; ks < 4; ks++) {
            u32 ah[4], al[4];
            int ar = w*16 + la15, ach = 2*ks + laq;
            ldsm4(ah, sw8(wh, ar, ach));
            ldsm4(al, sw8(wl, ar, ach));
            int kr = ks*16 + lahalf*8 + la7;
            #pragma unroll
            for (int nn = 0; nn < 8; nn++) {
                int bch = 2*nn + laq;
                u32 bh[4], bl[4];
                ldsm4t(bh, sw16(xh, kr, bch));
                mma16816(acc[2*nn],   ah, bh[0], bh[1]);
                mma16816(acc[2*nn+1], ah, bh[2], bh[3]);
                mma16816(acc[2*nn],   al, bh[0], bh[1]);
                mma16816(acc[2*nn+1], al, bh[2], bh[3]);
                ldsm4t(bl, sw16(xl, kr, bch));
                mma16816(acc[2*nn],   ah, bl[0], bl[1]);
                mma16816(acc[2*nn+1], ah, bl[2], bl[3]);
            }
        }
    }
    #undef PJ_STAGE

    // dump fp32 out tile [ch][n], stride 133 (conflict-free transpose)
    __syncthreads();
    float* outS = (float*)smc;
    {
        int r = w*16 + (lane >> 2);
        #pragma unroll
        for (int nn = 0; nn < 16; nn++) {
            int n = nn*8 + 2*(lane & 3);
            outS[r*133 + n]         = acc[nn][0];
            outS[r*133 + n + 1]     = acc[nn][1];
            outS[(r+8)*133 + n]     = acc[nn][2];
            outS[(r+8)*133 + n + 1] = acc[nn][3];
        }
    }
    __syncthreads();

    // transposed write: [n][c] bf16 hi/lo planes
    u32* dh = (which==0 ? g_th_h : which==1 ? g_ph_h : g_g_h) + (size_t)b*NP*64;
    u32* dl = (which==0 ? g_th_l : which==1 ? g_ph_l : g_g_l) + (size_t)b*NP*64;
    {
        int n = t >> 1, half = t & 1;
        u32 hb[32], lb[32];
        #pragma unroll
        for (int p = 0; p < 32; p++) {
            int c = half*64 + 2*p;
            float f0 = outS[c*133 + n];
            float f1 = outS[(c+1)*133 + n];
            u32 h = cvtbf2(f0, f1);
            hb[p] = h;
            lb[p] = cvtbf2(f0 - blo(h), f1 - bhi(h));
        }
        u32* ph_ = dh + (size_t)(n0 + n)*64 + half*32;
        u32* pl_ = dl + (size_t)(n0 + n)*64 + half*32;
        #pragma unroll
        for (int q = 0; q < 8; q++) {
            *(uint4*)(ph_ + q*4) = make_uint4(hb[4*q], hb[4*q+1], hb[4*q+2], hb[4*q+3]);
            *(uint4*)(pl_ + q*4) = make_uint4(lb[4*q], lb[4*q+1], lb[4*q+2], lb[4*q+3]);
        }
    }
}

// ---------------- residual path ----------------
__global__ void __launch_bounds__(256) resid_kernel(const float* __restrict__ x1,
                                                    float* __restrict__ out)
{
    extern __shared__ float Cs[];
    int b = blockIdx.y;
    int n = blockIdx.x*256 + threadIdx.x;
    for (int i = threadIdx.x; i < OC*CIN; i += 256) Cs[i] = g_C[i];
    __syncthreads();
    const float* xb = x1 + (size_t)b*CIN*NP + n;
    float acc[OC];
    #pragma unroll
    for (int o=0;o<OC;o++) acc[o] = g_cvec[o];
    for (int k = 0; k < CIN; k++) {
        float xv = xb[(size_t)k*NP];
        #pragma unroll
        for (int o=0;o<OC;o++) acc[o] = fmaf(Cs[o*CIN+k], xv, acc[o]);
    }
    float* ob = out + (size_t)b*OC*NP + n;
    #pragma unroll
    for (int o=0;o<OC;o++) ob[(size_t)o*NP] = acc[o];
}

// ---------------- warp-pair MMA flash attention, j-split PV ----------------
#define PH_H 0
#define PH_L 16384
#define G_H  32768
#define G_L  49152
#define BUFSZ 65536
#define S_TH_H 131072
#define S_TH_L 163840
#define S_PM   196608
#define S_PS   197632
#define S_TOTAL 198656

__device__ __forceinline__ void stage_plane_async(u32 sdst, const u32* __restrict__ src,
                                                  int rows, int t, int nthr){
    for (int idx = t; idx < rows*16; idx += nthr) {
        int r = idx >> 4, ch = idx & 15;
        CP16(sdst + (u32)r*256u + (u32)((ch ^ (r & 7)) * 16), src + (size_t)r*64 + ch*4);
    }
}

__global__ void __launch_bounds__(512) attn_mma_kernel(float* __restrict__ out)
{
    extern __shared__ char smc[];
    u32 sb = smem_u32(smc);
    int t = threadIdx.x, lane = t & 31, w = t >> 5;
    int wp = w >> 1, h = w & 1;
    int b = blockIdx.y;
    int n0 = blockIdx.x * 128;
    size_t bn = (size_t)b * NP;

    float* pm = (float*)(smc + S_PM);
    float* ps = (float*)(smc + S_PS);

    const u32* phh = g_ph_h + bn*64;
    const u32* phl = g_ph_l + bn*64;
    const u32* ggh = g_g_h  + bn*64;
    const u32* ggl = g_g_l  + bn*64;

    // prologue: theta + tile0 (group0), tile1 (group1)
    stage_plane_async(sb + S_TH_H, g_th_h + (bn + n0)*64, 128, t, 512);
    stage_plane_async(sb + S_TH_L, g_th_l + (bn + n0)*64, 128, t, 512);
    stage_plane_async(sb + PH_H, phh, 64, t, 512);
    stage_plane_async(sb + PH_L, phl, 64, t, 512);
    stage_plane_async(sb + G_H,  ggh, 64, t, 512);
    stage_plane_async(sb + G_L,  ggl, 64, t, 512);
    CP_COMMIT();
    {
        size_t jn = (size_t)64 * 64;
        stage_plane_async(sb + BUFSZ + PH_H, phh + jn, 64, t, 512);
        stage_plane_async(sb + BUFSZ + PH_L, phl + jn, 64, t, 512);
        stage_plane_async(sb + BUFSZ + G_H,  ggh + jn, 64, t, 512);
        stage_plane_async(sb + BUFSZ + G_L,  ggl + jn, 64, t, 512);
        CP_COMMIT();
    }

    float y[16][4];
    #pragma unroll
    for (int n = 0; n < 16; n++)
        #pragma unroll
        for (int i = 0; i < 4; i++) y[n][i] = 0.f;
    float m0 = -1e30f, m1 = -1e30f, l0 = 0.f, l1 = 0.f;

    int la15 = lane & 15, la7 = lane & 7;
    int lahalf = (lane >> 3) & 1, laq = lane >> 4;
    int r0 = lane >> 2;
    int qg0 = wp*16 + r0, qg1 = qg0 + 8;
    int barid = wp + 1;

    for (int jt = 0; jt < 64; jt++) {
        int cur = jt & 1;
        u32 buf = sb + (u32)cur * BUFSZ;
        if (jt < 63) CP_WAIT1(); else CP_WAIT0();
        __syncthreads();

        // ---- QK: S[16q x 32j] (warp's j-half) ----
        float S[4][4];
        #pragma unroll
        for (int n = 0; n < 4; n++)
            #pragma unroll
            for (int i = 0; i < 4; i++) S[n][i] = 0.f;

        #pragma unroll
        for (int k = 0; k < 8; k++) {
            u32 ah[4], al[4];
            int ar = wp*16 + la15, ach = 2*k + laq;
            ldsm4(ah, sw16(sb + S_TH_H, ar, ach));
            ldsm4(al, sw16(sb + S_TH_L, ar, ach));
            #pragma unroll
            for (int n4 = 0; n4 < 2; n4++) {
                int br = h*32 + (n4*2 + laq)*8 + la7;
                int bch = 2*k + lahalf;
                u32 bh[4], bl[4];
                ldsm4(bh, sw16(buf + PH_H, br, bch));
                mma16816(S[2*n4],   ah, bh[0], bh[1]);
                mma16816(S[2*n4+1], ah, bh[2], bh[3]);
                mma16816(S[2*n4],   al, bh[0], bh[1]);
                mma16816(S[2*n4+1], al, bh[2], bh[3]);
                ldsm4(bl, sw16(buf + PH_L, br, bch));
                mma16816(S[2*n4],   ah, bl[0], bl[1]);
                mma16816(S[2*n4+1], ah, bl[2], bl[3]);
            }
        }

        // ---- partial max exchange (pair-local) ----
        float tm0 = -1e30f, tm1 = -1e30f;
        #pragma unroll
        for (int n = 0; n < 4; n++) {
            tm0 = fmaxf(tm0, fmaxf(S[n][0], S[n][1]));
            tm1 = fmaxf(tm1, fmaxf(S[n][2], S[n][3]));
        }
        tm0 = fmaxf(tm0, __shfl_xor_sync(0xffffffffu, tm0, 1));
        tm0 = fmaxf(tm0, __shfl_xor_sync(0xffffffffu, tm0, 2));
        tm1 = fmaxf(tm1, __shfl_xor_sync(0xffffffffu, tm1, 1));
        tm1 = fmaxf(tm1, __shfl_xor_sync(0xffffffffu, tm1, 2));
        if ((lane & 3) == 0) { pm[h*128 + qg0] = tm0; pm[h*128 + qg1] = tm1; }
        BAR_PAIR(barid);

        float nm0 = fmaxf(m0, fmaxf(pm[qg0], pm[128 + qg0]));
        float nm1 = fmaxf(m1, fmaxf(pm[qg1], pm[128 + qg1]));
        float sc0 = fexp(m0 - nm0), sc1 = fexp(m1 - nm1);
        m0 = nm0; m1 = nm1;

        float sum0 = 0.f, sum1 = 0.f;
        #pragma unroll
        for (int n = 0; n < 4; n++) {
            S[n][0] = fexp(S[n][0] - nm0);
            S[n][1] = fexp(S[n][1] - nm0);
            S[n][2] = fexp(S[n][2] - nm1);
            S[n][3] = fexp(S[n][3] - nm1);
            sum0 += S[n][0] + S[n][1];
            sum1 += S[n][2] + S[n][3];
        }
        sum0 += __shfl_xor_sync(0xffffffffu, sum0, 1);
        sum0 += __shfl_xor_sync(0xffffffffu, sum0, 2);
        sum1 += __shfl_xor_sync(0xffffffffu, sum1, 1);
        sum1 += __shfl_xor_sync(0xffffffffu, sum1, 2);
        if ((lane & 3) == 0) { ps[h*128 + qg0] = sum0; ps[h*128 + qg1] = sum1; }

        // ---- P -> bf16 hi/lo own fragments (j-split: no smem exchange) ----
        u32 ph_own[2][4], pl_own[2][4];
        #pragma unroll
        for (int kp = 0; kp < 2; kp++) {
            float* sa  = S[2*kp];
            float* sb2 = S[2*kp+1];
            u32 h0 = cvtbf2(sa[0], sa[1]);
            u32 h1 = cvtbf2(sa[2], sa[3]);
            u32 h2 = cvtbf2(sb2[0], sb2[1]);
            u32 h3 = cvtbf2(sb2[2], sb2[3]);
            ph_own[kp][0]=h0; ph_own[kp][1]=h1; ph_own[kp][2]=h2; ph_own[kp][3]=h3;
            pl_own[kp][0] = cvtbf2(sa[0]-blo(h0), sa[1]-bhi(h0));
            pl_own[kp][1] = cvtbf2(sa[2]-blo(h1), sa[3]-bhi(h1));
            pl_own[kp][2] = cvtbf2(sb2[0]-blo(h2), sb2[1]-bhi(h2));
            pl_own[kp][3] = cvtbf2(sb2[2]-blo(h3), sb2[3]-bhi(h3));
        }
        BAR_PAIR(barid);

        l0 = l0*sc0 + ps[qg0] + ps[128 + qg0];
        l1 = l1*sc1 + ps[qg1] + ps[128 + qg1];
        #pragma unroll
        for (int n = 0; n < 16; n++) {
            y[n][0] *= sc0; y[n][1] *= sc0;
            y[n][2] *= sc1; y[n][3] *= sc1;
        }

        // ---- PV: y[16q x 128c], own 32 j only ----
        #pragma unroll
        for (int kp = 0; kp < 2; kp++) {
            int gr = h*32 + kp*16 + lahalf*8 + la7;
            #pragma unroll
            for (int n8 = 0; n8 < 8; n8++) {
                int gch = 2*n8 + laq;
                u32 gh[4], gl[4];
                ldsm4t(gh, sw16(buf + G_H, gr, gch));
                mma16816(y[2*n8],   ph_own[kp], gh[0], gh[1]);
                mma16816(y[2*n8+1], ph_own[kp], gh[2], gh[3]);
                mma16816(y[2*n8],   pl_own[kp], gh[0], gh[1]);
                mma16816(y[2*n8+1], pl_own[kp], gh[2], gh[3]);
                ldsm4t(gl, sw16(buf + G_L, gr, gch));
                mma16816(y[2*n8],   ph_own[kp], gl[0], gl[1]);
                mma16816(y[2*n8+1], ph_own[kp], gl[2], gl[3]);
            }
        }
        __syncthreads();

        if (jt < 62) {
            u32 nbuf = sb + (u32)cur * BUFSZ;
            size_t jn = (size_t)(jt + 2) * 64 * 64;
            stage_plane_async(nbuf + PH_H, phh + jn, 64, t, 512);
            stage_plane_async(nbuf + PH_L, phl + jn, 64, t, 512);
            stage_plane_async(nbuf + G_H,  ggh + jn, 64, t, 512);
            stage_plane_async(nbuf + G_L,  ggl + jn, 64, t, 512);
            CP_COMMIT();
        }
    }

    // ---- epilogue: merge pair halves, ys = y/l, out += A @ ys ----
    float* ys = (float*)smc;
    float* As = (float*)(smc + S_TH_H);
    for (int i = t; i < OC*IC; i += 512) As[i] = g_A[i];
    float inv0 = 1.f / l0, inv1 = 1.f / l1;
    if (h == 0) {
        #pragma unroll
        for (int n = 0; n < 16; n++) {
            int c = n*8 + 2*(lane & 3);
            ys[qg0*129 + c]     = y[n][0] * inv0;
            ys[qg0*129 + c + 1] = y[n][1] * inv0;
            ys[qg1*129 + c]     = y[n][2] * inv1;
            ys[qg1*129 + c + 1] = y[n][3] * inv1;
        }
    }
    __syncthreads();
    if (h == 1) {
        #pragma unroll
        for (int n = 0; n < 16; n++) {
            int c = n*8 + 2*(lane & 3);
            ys[qg0*129 + c]     += y[n][0] * inv0;
            ys[qg0*129 + c + 1] += y[n][1] * inv0;
            ys[qg1*129 + c]     += y[n][2] * inv1;
            ys[qg1*129 + c + 1] += y[n][3] * inv1;
        }
    }
    __syncthreads();
    float* ob = out + (size_t)b*OC*NP + n0;
    #pragma unroll
    for (int i = 0; i < 5; i++) {
        int idx = t + i*512;
        int q = idx & 127, o = idx >> 7;
        float acc = 0.f;
        #pragma unroll 8
        for (int c = 0; c < IC; c++) acc = fmaf(As[o*IC+c], ys[q*129+c], acc);
        ob[(size_t)o*NP + q] += acc;
    }
}

extern "C" void kernel_launch(void* const* d_in, const int* in_sizes, int n_in,
                              void* d_out, int out_size)
{
    const float* x1     = (const float*)d_in[0];
    const float* x2     = (const float*)d_in[1];
    const float* w_conv = (const float*)d_in[2];
    const float* w_th   = (const float*)d_in[3];
    const float* w_ph   = (const float*)d_in[4];
    const float* w_g    = (const float*)d_in[5];
    const float* w_W    = (const float*)d_in[6];
    const float* b_W    = (const float*)d_in[7];
    const float* gam    = (const float*)d_in[8];
    const float* bet    = (const float*)d_in[9];
    const float* mean   = (const float*)d_in[10];
    const float* var    = (const float*)d_in[11];
    const float* w_out  = (const float*)d_in[12];
    const float* b_out  = (const float*)d_in[13];
    float* out = (float*)d_out;

    cudaFuncSetAttribute(attn_mma_kernel, cudaFuncAttributeMaxDynamicSharedMemorySize, S_TOTAL);
    cudaFuncSetAttribute(proj_kernel, cudaFuncAttributeMaxDynamicSharedMemorySize, PJ_TOTAL);
    cudaFuncSetAttribute(resid_kernel, cudaFuncAttributeMaxDynamicSharedMemorySize, OC*CIN*4);

    prep_kernel<<<1223, 256>>>(w_conv, w_th, w_ph, w_g, w_W, b_W, gam, bet, mean, var, w_out, b_out);
    prep2_kernel<<<576, 256>>>();
    proj_kernel<<<dim3(32, 3, BB), 256, PJ_TOTAL>>>(x1, x2);
    resid_kernel<<<dim3(16, BB), 256, OC*CIN*4>>>(x1, out);
    attn_mma_kernel<<<dim3(32, BB), 512, S_TOTAL>>>(out);
}

// round 10
// speedup vs baseline: 2.8115x; 1.1083x over previous
#include <cuda_runtime.h>
#include <cstdint>

typedef unsigned int u32;
typedef unsigned long long u64;

#define BB 8
#define CIN 768
#define NP 4096
#define IC 128
#define MID 256
#define OC 20

// folded weights
__device__ float g_wtpg[3*IC*CIN];
__device__ float g_Ct[CIN*OC];     // transposed residual weights [k][o]
__device__ float g_A[OC*IC];
__device__ float g_cvec[OC];
// pre-split folded weights, bf16 hi/lo planes [3*IC][384] (u32 = bf16x2)
__device__ u32 g_w_h[3*IC*384];
__device__ u32 g_w_l[3*IC*384];
// projections as bf16 hi/lo planes, [b][n][c] packed bf16x2 (64 u32 per row)
__device__ u32 g_th_h[BB*NP*64];
__device__ u32 g_th_l[BB*NP*64];
__device__ u32 g_ph_h[BB*NP*64];
__device__ u32 g_ph_l[BB*NP*64];
__device__ u32 g_g_h [BB*NP*64];
__device__ u32 g_g_l [BB*NP*64];

__device__ __forceinline__ float fexp(float x){
    x = fmaxf(x, -80.f);
    float t = x * 1.4426950408889634f;
    float f = t + 12582912.f;
    float k = f - 12582912.f;
    float r = t - k;
    float p = 1.3333558e-3f;
    p = fmaf(p, r, 9.6181291e-3f);
    p = fmaf(p, r, 5.5504109e-2f);
    p = fmaf(p, r, 2.4022651e-1f);
    p = fmaf(p, r, 6.9314718e-1f);
    p = fmaf(p, r, 1.f);
    int ki = (int)k;
    return p * __int_as_float((ki + 127) << 23);
}

__device__ __forceinline__ u32 cvtbf2(float a, float b){
    u32 r; asm("cvt.rn.bf16x2.f32 %0, %1, %2;" : "=r"(r) : "f"(b), "f"(a)); return r;
}
__device__ __forceinline__ float blo(u32 u){ return __uint_as_float(u << 16); }
__device__ __forceinline__ float bhi(u32 u){ return __uint_as_float(u & 0xffff0000u); }

__device__ __forceinline__ void ffma2(u64& d, u64 a, u64 b){
    asm("fma.rn.f32x2 %0, %1, %2, %0;" : "+l"(d) : "l"(a), "l"(b));
}
__device__ __forceinline__ float2 u2f(u64 v){
    float2 r; asm("mov.b64 {%0,%1}, %2;" : "=f"(r.x), "=f"(r.y) : "l"(v)); return r;
}

__device__ __forceinline__ u32 smem_u32(const void* p){
    u32 a; asm("{ .reg .u64 t; cvta.to.shared.u64 t, %1; cvt.u32.u64 %0, t; }" : "=r"(a) : "l"(p)); return a;
}

// ---------------- mma / ldmatrix ----------------
__device__ __forceinline__ void mma16816(float* d, const u32* a, u32 b0, u32 b1){
    asm volatile("mma.sync.aligned.m16n8k16.row.col.f32.bf16.bf16.f32 "
        "{%0,%1,%2,%3}, {%4,%5,%6,%7}, {%8,%9}, {%0,%1,%2,%3};"
        : "+f"(d[0]), "+f"(d[1]), "+f"(d[2]), "+f"(d[3])
        : "r"(a[0]), "r"(a[1]), "r"(a[2]), "r"(a[3]), "r"(b0), "r"(b1));
}
__device__ __forceinline__ void ldsm4(u32* r, u32 addr){
    asm volatile("ldmatrix.sync.aligned.m8n8.x4.shared.b16 {%0,%1,%2,%3}, [%4];"
        : "=r"(r[0]), "=r"(r[1]), "=r"(r[2]), "=r"(r[3]) : "r"(addr));
}
__device__ __forceinline__ void ldsm4t(u32* r, u32 addr){
    asm volatile("ldmatrix.sync.aligned.m8n8.x4.trans.shared.b16 {%0,%1,%2,%3}, [%4];"
        : "=r"(r[0]), "=r"(r[1]), "=r"(r[2]), "=r"(r[3]) : "r"(addr));
}

// 256B rows (16 chunks of 16B), swizzle chunk ^= (row&7)
__device__ __forceinline__ u32 sw16(u32 base, int row, int ch){
    return base + (u32)row*256u + (u32)((ch ^ (row & 7)) * 16);
}
// 128B rows (8 chunks of 16B)
__device__ __forceinline__ u32 sw8(u32 base, int row, int ch){
    return base + (u32)row*128u + (u32)((ch ^ (row & 7)) * 16);
}

#define CP16(dst, src) asm volatile("cp.async.cg.shared.global [%0], [%1], 16;" :: "r"(dst), "l"(src) : "memory")
#define CP_COMMIT()    asm volatile("cp.async.commit_group;" ::: "memory")
#define CP_WAIT1()     asm volatile("cp.async.wait_group 1;" ::: "memory")
#define CP_WAIT0()     asm volatile("cp.async.wait_group 0;" ::: "memory")

// ---------------- prep ----------------
__global__ void __launch_bounds__(256) prep_kernel(
    const float* __restrict__ wc, const float* __restrict__ wt,
    const float* __restrict__ wp, const float* __restrict__ wg,
    const float* __restrict__ wW, const float* __restrict__ bW,
    const float* __restrict__ gam, const float* __restrict__ bet,
    const float* __restrict__ mean, const float* __restrict__ var,
    const float* __restrict__ wo, const float* __restrict__ bo)
{
    int gid = blockIdx.x*256 + threadIdx.x;
    if (gid < 3*IC*CIN) {
        int r = gid / CIN, k = gid % CIN;
        const float* ws = (r < IC) ? wt : (r < 2*IC) ? wp : wg;
        int rr = r & (IC-1);
        float acc = 0.f;
        for (int m = 0; m < MID; m++) acc = fmaf(ws[rr*MID+m], wc[m*CIN+k], acc);
        g_wtpg[gid] = acc;
        return;
    }
    int idx = gid - 3*IC*CIN;
    if (idx < OC*CIN) {
        int o = idx / CIN, k = idx % CIN;
        float acc = 0.f;
        for (int m = 0; m < MID; m++) acc = fmaf(wo[o*MID+m], wc[m*CIN+k], acc);
        g_Ct[k*OC + o] = acc;
        return;
    }
    idx -= OC*CIN;
    if (idx < OC*IC) {
        int o = idx / IC, i = idx % IC;
        float acc = 0.f;
        for (int m = 0; m < MID; m++) {
            float inv = gam[m] * rsqrtf(var[m] + 1e-5f);
            acc = fmaf(wo[o*MID+m]*inv, wW[m*IC+i], acc);
        }
        g_A[idx] = acc;
        return;
    }
    idx -= OC*IC;
    if (idx < OC) {
        float acc = bo[idx];
        for (int m = 0; m < MID; m++) {
            float inv = gam[m] * rsqrtf(var[m] + 1e-5f);
            acc += wo[idx*MID+m] * (bW[m]*inv + bet[m] - mean[m]*inv);
        }
        g_cvec[idx] = acc;
    }
}

// pack folded weights into bf16 hi/lo planes
__global__ void __launch_bounds__(256) prep2_kernel()
{
    int gid = blockIdx.x*256 + threadIdx.x;
    if (gid >= 3*IC*384) return;
    int r = gid / 384, kk = gid % 384;
    float f0 = g_wtpg[r*CIN + 2*kk];
    float f1 = g_wtpg[r*CIN + 2*kk + 1];
    u32 h = cvtbf2(f0, f1);
    g_w_h[gid] = h;
    g_w_l[gid] = cvtbf2(f0 - blo(h), f1 - bhi(h));
}

// ---------------- tensorized projections, cp.async pipelined (race-free) ----------------
#define PJ_XRAW 65536
#define PJ_XH0  131072
#define PJ_TOTAL 196608

__global__ void __launch_bounds__(256) proj_kernel(const float* __restrict__ x1,
                                                   const float* __restrict__ x2)
{
    extern __shared__ char smc[];
    u32 sb = smem_u32(smc);
    int t = threadIdx.x, lane = t & 31, w = t >> 5;
    int n0 = blockIdx.x * 128;
    int which = blockIdx.y;
    int b = blockIdx.z;
    const float* xb = (which == 0 ? x1 : x2) + (size_t)b * CIN * NP;
    const u32* wbase_h = g_w_h + (size_t)which * IC * 384;
    const u32* wbase_l = g_w_l + (size_t)which * IC * 384;

    int la15 = lane & 15, la7 = lane & 7;
    int lahalf = (lane >> 3) & 1, laq = lane >> 4;

    float acc[16][4];
    #pragma unroll
    for (int n = 0; n < 16; n++)
        #pragma unroll
        for (int i = 0; i < 4; i++) acc[n][i] = 0.f;

    #define PJ_STAGE(c_) do { \
        int cur_ = (c_) & 1; int k0_ = (c_) * 64; \
        _Pragma("unroll") \
        for (int i = 0; i < 8; i++) { \
            int e = t + i*256; \
            int p = e >> 10, rest = e & 1023; \
            int ch = rest >> 3, q = rest & 7; \
            u32 dst = sb + (u32)cur_*32768u + (u32)p*16384u + (u32)ch*128u + (u32)(((q ^ (ch & 7)))*16); \
            const u32* src = (p ? wbase_l : wbase_h) + (size_t)ch*384 + (k0_ >> 1) + q*4; \
            CP16(dst, src); \
        } \
        _Pragma("unroll") \
        for (int i = 0; i < 8; i++) { \
            int e = t + i*256; \
            int r = e >> 5, cc = e & 31; \
            u32 dst = sb + PJ_XRAW + (u32)cur_*32768u + (u32)r*512u + (u32)cc*16u; \
            const float* src = xb + (size_t)(k0_ + r)*NP + n0 + cc*4; \
            CP16(dst, src); \
        } \
        CP_COMMIT(); \
    } while(0)

    PJ_STAGE(0);
    for (int c = 0; c < 12; c++) {
        int cur = c & 1;
        CP_WAIT0();
        __syncthreads();
        if (c < 11) PJ_STAGE(c + 1);

        u32 xh = sb + PJ_XH0 + (u32)cur*32768u;
        u32 xl = xh + 16384u;
        #pragma unroll
        for (int i = 0; i < 8; i++) {
            int e = t + i*256;
            int k = e >> 5, nq = e & 31;
            float4 v = *(const float4*)(smc + PJ_XRAW + cur*32768 + k*512 + nq*16);
            u32 h0 = cvtbf2(v.x, v.y), h1 = cvtbf2(v.z, v.w);
            u32 l0 = cvtbf2(v.x - blo(h0), v.y - bhi(h0));
            u32 l1 = cvtbf2(v.z - blo(h1), v.w - bhi(h1));
            u32 off = (u32)k*256u + (u32)((((nq>>1) ^ (k&7)))*16) + (u32)((nq&1)*8);
            *(uint2*)(smc + (xh - sb) + off) = make_uint2(h0, h1);
            *(uint2*)(smc + (xl - sb) + off) = make_uint2(l0, l1);
        }
        __syncthreads();

        u32 wh = sb + (u32)cur*32768u, wl = wh + 16384u;
        #pragma unroll
        for (int ks = 0; ks < 4; ks++) {
            u32 ah[4], al[4];
            int ar = w*16 + la15, ach = 2*ks + laq;
            ldsm4(ah, sw8(wh, ar, ach));
            ldsm4(al, sw8(wl, ar, ach));
            int kr = ks*16 + lahalf*8 + la7;
            #pragma unroll
            for (int nn = 0; nn < 8; nn++) {
                int bch = 2*nn + laq;
                u32 bh[4], bl[4];
                ldsm4t(bh, sw16(xh, kr, bch));
                mma16816(acc[2*nn],   ah, bh[0], bh[1]);
                mma16816(acc[2*nn+1], ah, bh[2], bh[3]);
                mma16816(acc[2*nn],   al, bh[0], bh[1]);
                mma16816(acc[2*nn+1], al, bh[2], bh[3]);
                ldsm4t(bl, sw16(xl, kr, bch));
                mma16816(acc[2*nn],   ah, bl[0], bl[1]);
                mma16816(acc[2*nn+1], ah, bl[2], bl[3]);
            }
        }
    }
    #undef PJ_STAGE

    __syncthreads();
    float* outS = (float*)smc;
    {
        int r = w*16 + (lane >> 2);
        #pragma unroll
        for (int nn = 0; nn < 16; nn++) {
            int n = nn*8 + 2*(lane & 3);
            outS[r*133 + n]         = acc[nn][0];
            outS[r*133 + n + 1]     = acc[nn][1];
            outS[(r+8)*133 + n]     = acc[nn][2];
            outS[(r+8)*133 + n + 1] = acc[nn][3];
        }
    }
    __syncthreads();

    u32* dh = (which==0 ? g_th_h : which==1 ? g_ph_h : g_g_h) + (size_t)b*NP*64;
    u32* dl = (which==0 ? g_th_l : which==1 ? g_ph_l : g_g_l) + (size_t)b*NP*64;
    {
        int n = t >> 1, half = t & 1;
        u32 hb[32], lb[32];
        #pragma unroll
        for (int p = 0; p < 32; p++) {
            int c = half*64 + 2*p;
            float f0 = outS[c*133 + n];
            float f1 = outS[(c+1)*133 + n];
            u32 h = cvtbf2(f0, f1);
            hb[p] = h;
            lb[p] = cvtbf2(f0 - blo(h), f1 - bhi(h));
        }
        u32* ph_ = dh + (size_t)(n0 + n)*64 + half*32;
        u32* pl_ = dl + (size_t)(n0 + n)*64 + half*32;
        #pragma unroll
        for (int q = 0; q < 8; q++) {
            *(uint4*)(ph_ + q*4) = make_uint4(hb[4*q], hb[4*q+1], hb[4*q+2], hb[4*q+3]);
            *(uint4*)(pl_ + q*4) = make_uint4(lb[4*q], lb[4*q+1], lb[4*q+2], lb[4*q+3]);
        }
    }
}

// ---------------- residual path: f32x2, k-unrolled, Ct transposed ----------------
__global__ void __launch_bounds__(256) resid_kernel(const float* __restrict__ x1,
                                                    float* __restrict__ out)
{
    extern __shared__ float Cs[];   // [k][o] 768 x 20
    int b = blockIdx.y;
    int n = blockIdx.x*256 + threadIdx.x;
    for (int i = threadIdx.x; i < CIN*OC; i += 256) Cs[i] = g_Ct[i];
    __syncthreads();
    const float* xb = x1 + (size_t)b*CIN*NP + n;
    u64 acc2[10];
    #pragma unroll
    for (int i = 0; i < 10; i++) acc2[i] = 0ull;
    for (int k = 0; k < CIN; k += 8) {
        float xv[8];
        #pragma unroll
        for (int j = 0; j < 8; j++) xv[j] = xb[(size_t)(k+j)*NP];
        #pragma unroll
        for (int j = 0; j < 8; j++) {
            u64 xx; asm("mov.b64 %0, {%1,%1};" : "=l"(xx) : "f"(xv[j]));
            const ulonglong2* cp = (const ulonglong2*)&Cs[(k+j)*OC];
            ulonglong2 q0 = cp[0], q1 = cp[1], q2 = cp[2], q3 = cp[3], q4 = cp[4];
            ffma2(acc2[0], q0.x, xx); ffma2(acc2[1], q0.y, xx);
            ffma2(acc2[2], q1.x, xx); ffma2(acc2[3], q1.y, xx);
            ffma2(acc2[4], q2.x, xx); ffma2(acc2[5], q2.y, xx);
            ffma2(acc2[6], q3.x, xx); ffma2(acc2[7], q3.y, xx);
            ffma2(acc2[8], q4.x, xx); ffma2(acc2[9], q4.y, xx);
        }
    }
    float* ob = out + (size_t)b*OC*NP + n;
    #pragma unroll
    for (int i = 0; i < 10; i++) {
        float2 p = u2f(acc2[i]);
        ob[(size_t)(2*i)*NP]   = p.x + g_cvec[2*i];
        ob[(size_t)(2*i+1)*NP] = p.y + g_cvec[2*i+1];
    }
}

// ---------------- warp-pair MMA flash attention, fully warp-independent softmax ----------------
#define PH_H 0
#define PH_L 16384
#define G_H  32768
#define G_L  49152
#define BUFSZ 65536
#define S_TH_H 131072
#define S_TH_L 163840
#define S_PM   196608
#define S_PS   197632
#define S_TOTAL 198656

__device__ __forceinline__ void stage_plane_async(u32 sdst, const u32* __restrict__ src,
                                                  int rows, int t, int nthr){
    for (int idx = t; idx < rows*16; idx += nthr) {
        int r = idx >> 4, ch = idx & 15;
        CP16(sdst + (u32)r*256u + (u32)((ch ^ (r & 7)) * 16), src + (size_t)r*64 + ch*4);
    }
}

__global__ void __launch_bounds__(512) attn_mma_kernel(float* __restrict__ out)
{
    extern __shared__ char smc[];
    u32 sb = smem_u32(smc);
    int t = threadIdx.x, lane = t & 31, w = t >> 5;
    int wp = w >> 1, h = w & 1;
    int b = blockIdx.y;
    int n0 = blockIdx.x * 128;
    size_t bn = (size_t)b * NP;

    float* pm = (float*)(smc + S_PM);
    float* ps = (float*)(smc + S_PS);

    const u32* phh = g_ph_h + bn*64;
    const u32* phl = g_ph_l + bn*64;
    const u32* ggh = g_g_h  + bn*64;
    const u32* ggl = g_g_l  + bn*64;

    stage_plane_async(sb + S_TH_H, g_th_h + (bn + n0)*64, 128, t, 512);
    stage_plane_async(sb + S_TH_L, g_th_l + (bn + n0)*64, 128, t, 512);
    stage_plane_async(sb + PH_H, phh, 64, t, 512);
    stage_plane_async(sb + PH_L, phl, 64, t, 512);
    stage_plane_async(sb + G_H,  ggh, 64, t, 512);
    stage_plane_async(sb + G_L,  ggl, 64, t, 512);
    CP_COMMIT();
    {
        size_t jn = (size_t)64 * 64;
        stage_plane_async(sb + BUFSZ + PH_H, phh + jn, 64, t, 512);
        stage_plane_async(sb + BUFSZ + PH_L, phl + jn, 64, t, 512);
        stage_plane_async(sb + BUFSZ + G_H,  ggh + jn, 64, t, 512);
        stage_plane_async(sb + BUFSZ + G_L,  ggl + jn, 64, t, 512);
        CP_COMMIT();
    }

    float y[16][4];
    #pragma unroll
    for (int n = 0; n < 16; n++)
        #pragma unroll
        for (int i = 0; i < 4; i++) y[n][i] = 0.f;
    float m0 = -1e30f, m1 = -1e30f, l0 = 0.f, l1 = 0.f;

    int la15 = lane & 15, la7 = lane & 7;
    int lahalf = (lane >> 3) & 1, laq = lane >> 4;
    int r0 = lane >> 2;
    int qg0 = wp*16 + r0, qg1 = qg0 + 8;

    for (int jt = 0; jt < 64; jt++) {
        int cur = jt & 1;
        u32 buf = sb + (u32)cur * BUFSZ;
        if (jt < 63) CP_WAIT1(); else CP_WAIT0();
        __syncthreads();

        // ---- QK: S[16q x 32j] (warp's j-half) ----
        float S[4][4];
        #pragma unroll
        for (int n = 0; n < 4; n++)
            #pragma unroll
            for (int i = 0; i < 4; i++) S[n][i] = 0.f;

        #pragma unroll
        for (int k = 0; k < 8; k++) {
            u32 ah[4], al[4];
            int ar = wp*16 + la15, ach = 2*k + laq;
            ldsm4(ah, sw16(sb + S_TH_H, ar, ach));
            ldsm4(al, sw16(sb + S_TH_L, ar, ach));
            #pragma unroll
            for (int n4 = 0; n4 < 2; n4++) {
                int br = h*32 + (n4*2 + laq)*8 + la7;
                int bch = 2*k + lahalf;
                u32 bh[4], bl[4];
                ldsm4(bh, sw16(buf + PH_H, br, bch));
                mma16816(S[2*n4],   ah, bh[0], bh[1]);
                mma16816(S[2*n4+1], ah, bh[2], bh[3]);
                mma16816(S[2*n4],   al, bh[0], bh[1]);
                mma16816(S[2*n4+1], al, bh[2], bh[3]);
                ldsm4(bl, sw16(buf + PH_L, br, bch));
                mma16816(S[2*n4],   ah, bl[0], bl[1]);
                mma16816(S[2*n4+1], ah, bl[2], bl[3]);
            }
        }

        // ---- warp-private online softmax (no cross-pair exchange) ----
        float tm0 = -1e30f, tm1 = -1e30f;
        #pragma unroll
        for (int n = 0; n < 4; n++) {
            tm0 = fmaxf(tm0, fmaxf(S[n][0], S[n][1]));
            tm1 = fmaxf(tm1, fmaxf(S[n][2], S[n][3]));
        }
        tm0 = fmaxf(tm0, __shfl_xor_sync(0xffffffffu, tm0, 1));
        tm0 = fmaxf(tm0, __shfl_xor_sync(0xffffffffu, tm0, 2));
        tm1 = fmaxf(tm1, __shfl_xor_sync(0xffffffffu, tm1, 1));
        tm1 = fmaxf(tm1, __shfl_xor_sync(0xffffffffu, tm1, 2));
        float nm0 = fmaxf(m0, tm0), nm1 = fmaxf(m1, tm1);
        float sc0 = fexp(m0 - nm0), sc1 = fexp(m1 - nm1);
        m0 = nm0; m1 = nm1;

        float sum0 = 0.f, sum1 = 0.f;
        #pragma unroll
        for (int n = 0; n < 4; n++) {
            S[n][0] = fexp(S[n][0] - nm0);
            S[n][1] = fexp(S[n][1] - nm0);
            S[n][2] = fexp(S[n][2] - nm1);
            S[n][3] = fexp(S[n][3] - nm1);
            sum0 += S[n][0] + S[n][1];
            sum1 += S[n][2] + S[n][3];
        }
        sum0 += __shfl_xor_sync(0xffffffffu, sum0, 1);
        sum0 += __shfl_xor_sync(0xffffffffu, sum0, 2);
        sum1 += __shfl_xor_sync(0xffffffffu, sum1, 1);
        sum1 += __shfl_xor_sync(0xffffffffu, sum1, 2);
        l0 = l0*sc0 + sum0;
        l1 = l1*sc1 + sum1;

        // ---- P -> bf16 hi/lo own fragments ----
        u32 ph_own[2][4], pl_own[2][4];
        #pragma unroll
        for (int kp = 0; kp < 2; kp++) {
            float* sa  = S[2*kp];
            float* sb2 = S[2*kp+1];
            u32 h0 = cvtbf2(sa[0], sa[1]);
            u32 h1 = cvtbf2(sa[2], sa[3]);
            u32 h2 = cvtbf2(sb2[0], sb2[1]);
            u32 h3 = cvtbf2(sb2[2], sb2[3]);
            ph_own[kp][0]=h0; ph_own[kp][1]=h1; ph_own[kp][2]=h2; ph_own[kp][3]=h3;
            pl_own[kp][0] = cvtbf2(sa[0]-blo(h0), sa[1]-bhi(h0));
            pl_own[kp][1] = cvtbf2(sa[2]-blo(h1), sa[3]-bhi(h1));
            pl_own[kp][2] = cvtbf2(sb2[0]-blo(h2), sb2[1]-bhi(h2));
            pl_own[kp][3] = cvtbf2(sb2[2]-blo(h3), sb2[3]-bhi(h3));
        }

        #pragma unroll
        for (int n = 0; n < 16; n++) {
            y[n][0] *= sc0; y[n][1] *= sc0;
            y[n][2] *= sc1; y[n][3] *= sc1;
        }

        // ---- PV: y[16q x 128c], own 32 j only ----
        #pragma unroll
        for (int kp = 0; kp < 2; kp++) {
            int gr = h*32 + kp*16 + lahalf*8 + la7;
            #pragma unroll
            for (int n8 = 0; n8 < 8; n8++) {
                int gch = 2*n8 + laq;
                u32 gh[4], gl[4];
                ldsm4t(gh, sw16(buf + G_H, gr, gch));
                mma16816(y[2*n8],   ph_own[kp], gh[0], gh[1]);
                mma16816(y[2*n8+1], ph_own[kp], gh[2], gh[3]);
                mma16816(y[2*n8],   pl_own[kp], gh[0], gh[1]);
                mma16816(y[2*n8+1], pl_own[kp], gh[2], gh[3]);
                ldsm4t(gl, sw16(buf + G_L, gr, gch));
                mma16816(y[2*n8],   ph_own[kp], gl[0], gl[1]);
                mma16816(y[2*n8+1], ph_own[kp], gl[2], gl[3]);
            }
        }
        __syncthreads();

        if (jt < 62) {
            u32 nbuf = sb + (u32)cur * BUFSZ;
            size_t jn = (size_t)(jt + 2) * 64 * 64;
            stage_plane_async(nbuf + PH_H, phh + jn, 64, t, 512);
            stage_plane_async(nbuf + PH_L, phl + jn, 64, t, 512);
            stage_plane_async(nbuf + G_H,  ggh + jn, 64, t, 512);
            stage_plane_async(nbuf + G_L,  ggl + jn, 64, t, 512);
            CP_COMMIT();
        }
    }

    // ---- epilogue: merge the two independent softmax halves exactly ----
    if ((lane & 3) == 0) {
        pm[h*128 + qg0] = m0; pm[h*128 + qg1] = m1;
        ps[h*128 + qg0] = l0; ps[h*128 + qg1] = l1;
    }
    float* ys = (float*)smc;
    float* As = (float*)(smc + S_TH_H);
    for (int i = t; i < OC*IC; i += 512) As[i] = g_A[i];
    __syncthreads();
    float nm0 = fmaxf(pm[qg0], pm[128 + qg0]);
    float nm1 = fmaxf(pm[qg1], pm[128 + qg1]);
    float lt0 = ps[qg0]*fexp(pm[qg0] - nm0) + ps[128 + qg0]*fexp(pm[128 + qg0] - nm0);
    float lt1 = ps[qg1]*fexp(pm[qg1] - nm1) + ps[128 + qg1]*fexp(pm[128 + qg1] - nm1);
    float inv0 = fexp(m0 - nm0) / lt0;
    float inv1 = fexp(m1 - nm1) / lt1;
    if (h == 0) {
        #pragma unroll
        for (int n = 0; n < 16; n++) {
            int c = n*8 + 2*(lane & 3);
            ys[qg0*129 + c]     = y[n][0] * inv0;
            ys[qg0*129 + c + 1] = y[n][1] * inv0;
            ys[qg1*129 + c]     = y[n][2] * inv1;
            ys[qg1*129 + c + 1] = y[n][3] * inv1;
        }
    }
    __syncthreads();
    if (h == 1) {
        #pragma unroll
        for (int n = 0; n < 16; n++) {
            int c = n*8 + 2*(lane & 3);
            ys[qg0*129 + c]     += y[n][0] * inv0;
            ys[qg0*129 + c + 1] += y[n][1] * inv0;
            ys[qg1*129 + c]     += y[n][2] * inv1;
            ys[qg1*129 + c + 1] += y[n][3] * inv1;
        }
    }
    __syncthreads();
    float* ob = out + (size_t)b*OC*NP + n0;
    #pragma unroll
    for (int i = 0; i < 5; i++) {
        int idx = t + i*512;
        int q = idx & 127, o = idx >> 7;
        float acc = 0.f;
        #pragma unroll 8
        for (int c = 0; c < IC; c++) acc = fmaf(As[o*IC+c], ys[q*129+c], acc);
        ob[(size_t)o*NP + q] += acc;
    }
}

extern "C" void kernel_launch(void* const* d_in, const int* in_sizes, int n_in,
                              void* d_out, int out_size)
{
    const float* x1     = (const float*)d_in[0];
    const float* x2     = (const float*)d_in[1];
    const float* w_conv = (const float*)d_in[2];
    const float* w_th   = (const float*)d_in[3];
    const float* w_ph   = (const float*)d_in[4];
    const float* w_g    = (const float*)d_in[5];
    const float* w_W    = (const float*)d_in[6];
    const float* b_W    = (const float*)d_in[7];
    const float* gam    = (const float*)d_in[8];
    const float* bet    = (const float*)d_in[9];
    const float* mean   = (const float*)d_in[10];
    const float* var    = (const float*)d_in[11];
    const float* w_out  = (const float*)d_in[12];
    const float* b_out  = (const float*)d_in[13];
    float* out = (float*)d_out;

    cudaFuncSetAttribute(attn_mma_kernel, cudaFuncAttributeMaxDynamicSharedMemorySize, S_TOTAL);
    cudaFuncSetAttribute(proj_kernel, cudaFuncAttributeMaxDynamicSharedMemorySize, PJ_TOTAL);
    cudaFuncSetAttribute(resid_kernel, cudaFuncAttributeMaxDynamicSharedMemorySize, CIN*OC*4);

    prep_kernel<<<1223, 256>>>(w_conv, w_th, w_ph, w_g, w_W, b_W, gam, bet, mean, var, w_out, b_out);
    prep2_kernel<<<576, 256>>>();
    proj_kernel<<<dim3(32, 3, BB), 256, PJ_TOTAL>>>(x1, x2);
    resid_kernel<<<dim3(16, BB), 256, CIN*OC*4>>>(x1, out);
    attn_mma_kernel<<<dim3(32, BB), 512, S_TOTAL>>>(out);
}

// round 11
// speedup vs baseline: 3.1763x; 1.1297x over previous
#include <cuda_runtime.h>
#include <cstdint>

typedef unsigned int u32;
typedef unsigned long long u64;

#define BB 8
#define CIN 768
#define NP 4096
#define IC 128
#define MID 256
#define OC 20

// folded weights
__device__ float g_wtpg[3*IC*CIN];
__device__ float g_Cf[OC*CIN];     // residual weights [o][k]
__device__ float g_A[OC*IC];
__device__ float g_cvec[OC];
// pre-split folded weights, bf16 hi/lo planes [3][160][384] (u32 = bf16x2)
// rows 0-127: projection weights; which==0 rows 128-147: C; rest zero
__device__ u32 g_w_h[3*160*384];
__device__ u32 g_w_l[3*160*384];
// projections as bf16 hi/lo planes, [b][n][c] packed bf16x2 (64 u32 per row)
__device__ u32 g_th_h[BB*NP*64];
__device__ u32 g_th_l[BB*NP*64];
__device__ u32 g_ph_h[BB*NP*64];
__device__ u32 g_ph_l[BB*NP*64];
__device__ u32 g_g_h [BB*NP*64];
__device__ u32 g_g_l [BB*NP*64];

__device__ __forceinline__ float fexp(float x){
    x = fmaxf(x, -80.f);
    float t = x * 1.4426950408889634f;
    float f = t + 12582912.f;
    float k = f - 12582912.f;
    float r = t - k;
    float p = 1.3333558e-3f;
    p = fmaf(p, r, 9.6181291e-3f);
    p = fmaf(p, r, 5.5504109e-2f);
    p = fmaf(p, r, 2.4022651e-1f);
    p = fmaf(p, r, 6.9314718e-1f);
    p = fmaf(p, r, 1.f);
    int ki = (int)k;
    return p * __int_as_float((ki + 127) << 23);
}

__device__ __forceinline__ u32 cvtbf2(float a, float b){
    u32 r; asm("cvt.rn.bf16x2.f32 %0, %1, %2;" : "=r"(r) : "f"(b), "f"(a)); return r;
}
__device__ __forceinline__ float blo(u32 u){ return __uint_as_float(u << 16); }
__device__ __forceinline__ float bhi(u32 u){ return __uint_as_float(u & 0xffff0000u); }

__device__ __forceinline__ u32 smem_u32(const void* p){
    u32 a; asm("{ .reg .u64 t; cvta.to.shared.u64 t, %1; cvt.u32.u64 %0, t; }" : "=r"(a) : "l"(p)); return a;
}

// ---------------- mma / ldmatrix ----------------
__device__ __forceinline__ void mma16816(float* d, const u32* a, u32 b0, u32 b1){
    asm volatile("mma.sync.aligned.m16n8k16.row.col.f32.bf16.bf16.f32 "
        "{%0,%1,%2,%3}, {%4,%5,%6,%7}, {%8,%9}, {%0,%1,%2,%3};"
        : "+f"(d[0]), "+f"(d[1]), "+f"(d[2]), "+f"(d[3])
        : "r"(a[0]), "r"(a[1]), "r"(a[2]), "r"(a[3]), "r"(b0), "r"(b1));
}
__device__ __forceinline__ void ldsm4(u32* r, u32 addr){
    asm volatile("ldmatrix.sync.aligned.m8n8.x4.shared.b16 {%0,%1,%2,%3}, [%4];"
        : "=r"(r[0]), "=r"(r[1]), "=r"(r[2]), "=r"(r[3]) : "r"(addr));
}
__device__ __forceinline__ void ldsm4t(u32* r, u32 addr){
    asm volatile("ldmatrix.sync.aligned.m8n8.x4.trans.shared.b16 {%0,%1,%2,%3}, [%4];"
        : "=r"(r[0]), "=r"(r[1]), "=r"(r[2]), "=r"(r[3]) : "r"(addr));
}

// 256B rows (16 chunks of 16B), swizzle chunk ^= (row&7)
__device__ __forceinline__ u32 sw16(u32 base, int row, int ch){
    return base + (u32)row*256u + (u32)((ch ^ (row & 7)) * 16);
}
// 128B rows (8 chunks of 16B)
__device__ __forceinline__ u32 sw8(u32 base, int row, int ch){
    return base + (u32)row*128u + (u32)((ch ^ (row & 7)) * 16);
}

#define CP16(dst, src) asm volatile("cp.async.cg.shared.global [%0], [%1], 16;" :: "r"(dst), "l"(src) : "memory")
#define CP_COMMIT()    asm volatile("cp.async.commit_group;" ::: "memory")
#define CP_WAIT1()     asm volatile("cp.async.wait_group 1;" ::: "memory")
#define CP_WAIT0()     asm volatile("cp.async.wait_group 0;" ::: "memory")

// ---------------- prep ----------------
__global__ void __launch_bounds__(256) prep_kernel(
    const float* __restrict__ wc, const float* __restrict__ wt,
    const float* __restrict__ wp, const float* __restrict__ wg,
    const float* __restrict__ wW, const float* __restrict__ bW,
    const float* __restrict__ gam, const float* __restrict__ bet,
    const float* __restrict__ mean, const float* __restrict__ var,
    const float* __restrict__ wo, const float* __restrict__ bo)
{
    int gid = blockIdx.x*256 + threadIdx.x;
    if (gid < 3*IC*CIN) {
        int r = gid / CIN, k = gid % CIN;
        const float* ws = (r < IC) ? wt : (r < 2*IC) ? wp : wg;
        int rr = r & (IC-1);
        float acc = 0.f;
        for (int m = 0; m < MID; m++) acc = fmaf(ws[rr*MID+m], wc[m*CIN+k], acc);
        g_wtpg[gid] = acc;
        return;
    }
    int idx = gid - 3*IC*CIN;
    if (idx < OC*CIN) {
        int o = idx / CIN, k = idx % CIN;
        float acc = 0.f;
        for (int m = 0; m < MID; m++) acc = fmaf(wo[o*MID+m], wc[m*CIN+k], acc);
        g_Cf[o*CIN + k] = acc;
        return;
    }
    idx -= OC*CIN;
    if (idx < OC*IC) {
        int o = idx / IC, i = idx % IC;
        float acc = 0.f;
        for (int m = 0; m < MID; m++) {
            float inv = gam[m] * rsqrtf(var[m] + 1e-5f);
            acc = fmaf(wo[o*MID+m]*inv, wW[m*IC+i], acc);
        }
        g_A[idx] = acc;
        return;
    }
    idx -= OC*IC;
    if (idx < OC) {
        float acc = bo[idx];
        for (int m = 0; m < MID; m++) {
            float inv = gam[m] * rsqrtf(var[m] + 1e-5f);
            acc += wo[idx*MID+m] * (bW[m]*inv + bet[m] - mean[m]*inv);
        }
        g_cvec[idx] = acc;
    }
}

// pack folded weights (+ resid rows for which==0) into bf16 hi/lo planes
__global__ void __launch_bounds__(256) prep2_kernel()
{
    int gid = blockIdx.x*256 + threadIdx.x;
    if (gid >= 3*160*384) return;
    int which = gid / (160*384);
    int rem = gid % (160*384);
    int r = rem / 384, kk = rem % 384;
    float f0 = 0.f, f1 = 0.f;
    if (r < 128) {
        f0 = g_wtpg[(which*IC + r)*CIN + 2*kk];
        f1 = g_wtpg[(which*IC + r)*CIN + 2*kk + 1];
    } else if (which == 0 && r < 148) {
        f0 = g_Cf[(r-128)*CIN + 2*kk];
        f1 = g_Cf[(r-128)*CIN + 2*kk + 1];
    }
    u32 h = cvtbf2(f0, f1);
    g_w_h[gid] = h;
    g_w_l[gid] = cvtbf2(f0 - blo(h), f1 - bhi(h));
}

// ---------------- tensorized projections + fused residual, cp.async pipelined ----------------
// smem map (bytes):
//  [0, 81920)         W bufs: 2 x (hi 20480 + lo 20480), 160 rows
//  [81920, 147456)    x raw fp32: 2 x 32768
//  [147456, 212992)   XH0/XL0/XH1/XL1 16384 each
#define PJ_XRAW 81920
#define PJ_XH0  147456
#define PJ_TOTAL 212992
#define WBUF 40960
#define WPL  20480

__global__ void __launch_bounds__(256) proj_kernel(const float* __restrict__ x1,
                                                   const float* __restrict__ x2,
                                                   float* __restrict__ out)
{
    extern __shared__ char smc[];
    u32 sb = smem_u32(smc);
    int t = threadIdx.x, lane = t & 31, w = t >> 5;
    int n0 = blockIdx.x * 128;
    int which = blockIdx.y;
    int b = blockIdx.z;
    const float* xb = (which == 0 ? x1 : x2) + (size_t)b * CIN * NP;
    const u32* wbase_h = g_w_h + (size_t)which * 160 * 384;
    const u32* wbase_l = g_w_l + (size_t)which * 160 * 384;

    int la15 = lane & 15, la7 = lane & 7;
    int lahalf = (lane >> 3) & 1, laq = lane >> 4;

    float acc[16][4];
    #pragma unroll
    for (int n = 0; n < 16; n++)
        #pragma unroll
        for (int i = 0; i < 4; i++) acc[n][i] = 0.f;
    float accr[2][2][4];
    #pragma unroll
    for (int mt = 0; mt < 2; mt++)
        #pragma unroll
        for (int cp = 0; cp < 2; cp++)
            #pragma unroll
            for (int i = 0; i < 4; i++) accr[mt][cp][i] = 0.f;

    // W: 2 planes x 160 rows x 8 chunks = 2560 cp16; x raw: 2048 cp16
    #define PJ_STAGE(c_) do { \
        int cur_ = (c_) & 1; int k0_ = (c_) * 64; \
        _Pragma("unroll") \
        for (int i = 0; i < 10; i++) { \
            int e = t + i*256; \
            int p = (i >= 5); \
            int rest = e - p*1280; \
            int ch = rest >> 3, q = rest & 7; \
            u32 dst = sb + (u32)cur_*WBUF + (u32)p*WPL + (u32)ch*128u + (u32)(((q ^ (ch & 7)))*16); \
            const u32* src = (p ? wbase_l : wbase_h) + (size_t)ch*384 + (k0_ >> 1) + q*4; \
            CP16(dst, src); \
        } \
        _Pragma("unroll") \
        for (int i = 0; i < 8; i++) { \
            int e = t + i*256; \
            int r = e >> 5, cc = e & 31; \
            u32 dst = sb + PJ_XRAW + (u32)cur_*32768u + (u32)r*512u + (u32)cc*16u; \
            const float* src = xb + (size_t)(k0_ + r)*NP + n0 + cc*4; \
            CP16(dst, src); \
        } \
        CP_COMMIT(); \
    } while(0)

    PJ_STAGE(0);
    for (int c = 0; c < 12; c++) {
        int cur = c & 1;
        CP_WAIT0();
        __syncthreads();
        if (c < 11) PJ_STAGE(c + 1);

        u32 xh = sb + PJ_XH0 + (u32)cur*32768u;
        u32 xl = xh + 16384u;
        #pragma unroll
        for (int i = 0; i < 8; i++) {
            int e = t + i*256;
            int k = e >> 5, nq = e & 31;
            float4 v = *(const float4*)(smc + PJ_XRAW + cur*32768 + k*512 + nq*16);
            u32 h0 = cvtbf2(v.x, v.y), h1 = cvtbf2(v.z, v.w);
            u32 l0 = cvtbf2(v.x - blo(h0), v.y - bhi(h0));
            u32 l1 = cvtbf2(v.z - blo(h1), v.w - bhi(h1));
            u32 off = (u32)k*256u + (u32)((((nq>>1) ^ (k&7)))*16) + (u32)((nq&1)*8);
            *(uint2*)(smc + (xh - sb) + off) = make_uint2(h0, h1);
            *(uint2*)(smc + (xl - sb) + off) = make_uint2(l0, l1);
        }
        __syncthreads();

        u32 wh = sb + (u32)cur*WBUF, wl = wh + WPL;
        #pragma unroll
        for (int ks = 0; ks < 4; ks++) {
            u32 ah[4], al[4];
            int ar = w*16 + la15, ach = 2*ks + laq;
            ldsm4(ah, sw8(wh, ar, ach));
            ldsm4(al, sw8(wl, ar, ach));
            int kr = ks*16 + lahalf*8 + la7;
            #pragma unroll
            for (int nn = 0; nn < 8; nn++) {
                int bch = 2*nn + laq;
                u32 bh[4], bl[4];
                ldsm4t(bh, sw16(xh, kr, bch));
                mma16816(acc[2*nn],   ah, bh[0], bh[1]);
                mma16816(acc[2*nn+1], ah, bh[2], bh[3]);
                mma16816(acc[2*nn],   al, bh[0], bh[1]);
                mma16816(acc[2*nn+1], al, bh[2], bh[3]);
                ldsm4t(bl, sw16(xl, kr, bch));
                mma16816(acc[2*nn],   ah, bl[0], bl[1]);
                mma16816(acc[2*nn+1], ah, bl[2], bl[3]);
            }
            // fused residual rows 128..159, this warp's n-slice (nn = w)
            if (which == 0) {
                u32 bhs[4], bls[4];
                ldsm4t(bhs, sw16(xh, kr, 2*w + laq));
                ldsm4t(bls, sw16(xl, kr, 2*w + laq));
                #pragma unroll
                for (int mt = 0; mt < 2; mt++) {
                    u32 arh[4], arl[4];
                    ldsm4(arh, sw8(wh, 128 + mt*16 + la15, ach));
                    ldsm4(arl, sw8(wl, 128 + mt*16 + la15, ach));
                    mma16816(accr[mt][0], arh, bhs[0], bhs[1]);
                    mma16816(accr[mt][1], arh, bhs[2], bhs[3]);
                    mma16816(accr[mt][0], arl, bhs[0], bhs[1]);
                    mma16816(accr[mt][1], arl, bhs[2], bhs[3]);
                    mma16816(accr[mt][0], arh, bls[0], bls[1]);
                    mma16816(accr[mt][1], arh, bls[2], bls[3]);
                }
            }
        }
    }
    #undef PJ_STAGE

    // fused residual epilogue: out[o][n] = accr + cvec
    if (which == 0) {
        float* ob = out + (size_t)b*OC*NP + n0;
        #pragma unroll
        for (int mt = 0; mt < 2; mt++) {
            #pragma unroll
            for (int cp = 0; cp < 2; cp++) {
                int o0 = mt*16 + (lane >> 2);
                int o1 = o0 + 8;
                int col = w*16 + cp*8 + 2*(lane & 3);
                if (o0 < OC) {
                    ob[(size_t)o0*NP + col]     = accr[mt][cp][0] + g_cvec[o0];
                    ob[(size_t)o0*NP + col + 1] = accr[mt][cp][1] + g_cvec[o0];
                }
                if (o1 < OC) {
                    ob[(size_t)o1*NP + col]     = accr[mt][cp][2] + g_cvec[o1];
                    ob[(size_t)o1*NP + col + 1] = accr[mt][cp][3] + g_cvec[o1];
                }
            }
        }
    }

    __syncthreads();
    float* outS = (float*)smc;
    {
        int r = w*16 + (lane >> 2);
        #pragma unroll
        for (int nn = 0; nn < 16; nn++) {
            int n = nn*8 + 2*(lane & 3);
            outS[r*133 + n]         = acc[nn][0];
            outS[r*133 + n + 1]     = acc[nn][1];
            outS[(r+8)*133 + n]     = acc[nn][2];
            outS[(r+8)*133 + n + 1] = acc[nn][3];
        }
    }
    __syncthreads();

    u32* dh = (which==0 ? g_th_h : which==1 ? g_ph_h : g_g_h) + (size_t)b*NP*64;
    u32* dl = (which==0 ? g_th_l : which==1 ? g_ph_l : g_g_l) + (size_t)b*NP*64;
    {
        int n = t >> 1, half = t & 1;
        u32 hb[32], lb[32];
        #pragma unroll
        for (int p = 0; p < 32; p++) {
            int c = half*64 + 2*p;
            float f0 = outS[c*133 + n];
            float f1 = outS[(c+1)*133 + n];
            u32 h = cvtbf2(f0, f1);
            hb[p] = h;
            lb[p] = cvtbf2(f0 - blo(h), f1 - bhi(h));
        }
        u32* ph_ = dh + (size_t)(n0 + n)*64 + half*32;
        u32* pl_ = dl + (size_t)(n0 + n)*64 + half*32;
        #pragma unroll
        for (int q = 0; q < 8; q++) {
            *(uint4*)(ph_ + q*4) = make_uint4(hb[4*q], hb[4*q+1], hb[4*q+2], hb[4*q+3]);
            *(uint4*)(pl_ + q*4) = make_uint4(lb[4*q], lb[4*q+1], lb[4*q+2], lb[4*q+3]);
        }
    }
}

// ---------------- warp-pair MMA flash attention, fully warp-independent softmax ----------------
#define PH_H 0
#define PH_L 16384
#define G_H  32768
#define G_L  49152
#define BUFSZ 65536
#define S_TH_H 131072
#define S_TH_L 163840
#define S_PM   196608
#define S_PS   197632
#define S_TOTAL 198656

__device__ __forceinline__ void stage_plane_async(u32 sdst, const u32* __restrict__ src,
                                                  int rows, int t, int nthr){
    for (int idx = t; idx < rows*16; idx += nthr) {
        int r = idx >> 4, ch = idx & 15;
        CP16(sdst + (u32)r*256u + (u32)((ch ^ (r & 7)) * 16), src + (size_t)r*64 + ch*4);
    }
}

__global__ void __launch_bounds__(512) attn_mma_kernel(float* __restrict__ out)
{
    extern __shared__ char smc[];
    u32 sb = smem_u32(smc);
    int t = threadIdx.x, lane = t & 31, w = t >> 5;
    int wp = w >> 1, h = w & 1;
    int b = blockIdx.y;
    int n0 = blockIdx.x * 128;
    size_t bn = (size_t)b * NP;

    float* pm = (float*)(smc + S_PM);
    float* ps = (float*)(smc + S_PS);

    const u32* phh = g_ph_h + bn*64;
    const u32* phl = g_ph_l + bn*64;
    const u32* ggh = g_g_h  + bn*64;
    const u32* ggl = g_g_l  + bn*64;

    stage_plane_async(sb + S_TH_H, g_th_h + (bn + n0)*64, 128, t, 512);
    stage_plane_async(sb + S_TH_L, g_th_l + (bn + n0)*64, 128, t, 512);
    stage_plane_async(sb + PH_H, phh, 64, t, 512);
    stage_plane_async(sb + PH_L, phl, 64, t, 512);
    stage_plane_async(sb + G_H,  ggh, 64, t, 512);
    stage_plane_async(sb + G_L,  ggl, 64, t, 512);
    CP_COMMIT();
    {
        size_t jn = (size_t)64 * 64;
        stage_plane_async(sb + BUFSZ + PH_H, phh + jn, 64, t, 512);
        stage_plane_async(sb + BUFSZ + PH_L, phl + jn, 64, t, 512);
        stage_plane_async(sb + BUFSZ + G_H,  ggh + jn, 64, t, 512);
        stage_plane_async(sb + BUFSZ + G_L,  ggl + jn, 64, t, 512);
        CP_COMMIT();
    }

    float y[16][4];
    #pragma unroll
    for (int n = 0; n < 16; n++)
        #pragma unroll
        for (int i = 0; i < 4; i++) y[n][i] = 0.f;
    float m0 = -1e30f, m1 = -1e30f, l0 = 0.f, l1 = 0.f;

    int la15 = lane & 15, la7 = lane & 7;
    int lahalf = (lane >> 3) & 1, laq = lane >> 4;
    int r0 = lane >> 2;
    int qg0 = wp*16 + r0, qg1 = qg0 + 8;

    for (int jt = 0; jt < 64; jt++) {
        int cur = jt & 1;
        u32 buf = sb + (u32)cur * BUFSZ;
        if (jt < 63) CP_WAIT1(); else CP_WAIT0();
        __syncthreads();

        float S[4][4];
        #pragma unroll
        for (int n = 0; n < 4; n++)
            #pragma unroll
            for (int i = 0; i < 4; i++) S[n][i] = 0.f;

        #pragma unroll
        for (int k = 0; k < 8; k++) {
            u32 ah[4], al[4];
            int ar = wp*16 + la15, ach = 2*k + laq;
            ldsm4(ah, sw16(sb + S_TH_H, ar, ach));
            ldsm4(al, sw16(sb + S_TH_L, ar, ach));
            #pragma unroll
            for (int n4 = 0; n4 < 2; n4++) {
                int br = h*32 + (n4*2 + laq)*8 + la7;
                int bch = 2*k + lahalf;
                u32 bh[4], bl[4];
                ldsm4(bh, sw16(buf + PH_H, br, bch));
                mma16816(S[2*n4],   ah, bh[0], bh[1]);
                mma16816(S[2*n4+1], ah, bh[2], bh[3]);
                mma16816(S[2*n4],   al, bh[0], bh[1]);
                mma16816(S[2*n4+1], al, bh[2], bh[3]);
                ldsm4(bl, sw16(buf + PH_L, br, bch));
                mma16816(S[2*n4],   ah, bl[0], bl[1]);
                mma16816(S[2*n4+1], ah, bl[2], bl[3]);
            }
        }

        float tm0 = -1e30f, tm1 = -1e30f;
        #pragma unroll
        for (int n = 0; n < 4; n++) {
            tm0 = fmaxf(tm0, fmaxf(S[n][0], S[n][1]));
            tm1 = fmaxf(tm1, fmaxf(S[n][2], S[n][3]));
        }
        tm0 = fmaxf(tm0, __shfl_xor_sync(0xffffffffu, tm0, 1));
        tm0 = fmaxf(tm0, __shfl_xor_sync(0xffffffffu, tm0, 2));
        tm1 = fmaxf(tm1, __shfl_xor_sync(0xffffffffu, tm1, 1));
        tm1 = fmaxf(tm1, __shfl_xor_sync(0xffffffffu, tm1, 2));
        float nm0 = fmaxf(m0, tm0), nm1 = fmaxf(m1, tm1);
        float sc0 = fexp(m0 - nm0), sc1 = fexp(m1 - nm1);
        m0 = nm0; m1 = nm1;

        float sum0 = 0.f, sum1 = 0.f;
        #pragma unroll
        for (int n = 0; n < 4; n++) {
            S[n][0] = fexp(S[n][0] - nm0);
            S[n][1] = fexp(S[n][1] - nm0);
            S[n][2] = fexp(S[n][2] - nm1);
            S[n][3] = fexp(S[n][3] - nm1);
            sum0 += S[n][0] + S[n][1];
            sum1 += S[n][2] + S[n][3];
        }
        sum0 += __shfl_xor_sync(0xffffffffu, sum0, 1);
        sum0 += __shfl_xor_sync(0xffffffffu, sum0, 2);
        sum1 += __shfl_xor_sync(0xffffffffu, sum1, 1);
        sum1 += __shfl_xor_sync(0xffffffffu, sum1, 2);
        l0 = l0*sc0 + sum0;
        l1 = l1*sc1 + sum1;

        u32 ph_own[2][4], pl_own[2][4];
        #pragma unroll
        for (int kp = 0; kp < 2; kp++) {
            float* sa  = S[2*kp];
            float* sb2 = S[2*kp+1];
            u32 h0 = cvtbf2(sa[0], sa[1]);
            u32 h1 = cvtbf2(sa[2], sa[3]);
            u32 h2 = cvtbf2(sb2[0], sb2[1]);
            u32 h3 = cvtbf2(sb2[2], sb2[3]);
            ph_own[kp][0]=h0; ph_own[kp][1]=h1; ph_own[kp][2]=h2; ph_own[kp][3]=h3;
            pl_own[kp][0] = cvtbf2(sa[0]-blo(h0), sa[1]-bhi(h0));
            pl_own[kp][1] = cvtbf2(sa[2]-blo(h1), sa[3]-bhi(h1));
            pl_own[kp][2] = cvtbf2(sb2[0]-blo(h2), sb2[1]-bhi(h2));
            pl_own[kp][3] = cvtbf2(sb2[2]-blo(h3), sb2[3]-bhi(h3));
        }

        #pragma unroll
        for (int n = 0; n < 16; n++) {
            y[n][0] *= sc0; y[n][1] *= sc0;
            y[n][2] *= sc1; y[n][3] *= sc1;
        }

        #pragma unroll
        for (int kp = 0; kp < 2; kp++) {
            int gr = h*32 + kp*16 + lahalf*8 + la7;
            #pragma unroll
            for (int n8 = 0; n8 < 8; n8++) {
                int gch = 2*n8 + laq;
                u32 gh[4], gl[4];
                ldsm4t(gh, sw16(buf + G_H, gr, gch));
                mma16816(y[2*n8],   ph_own[kp], gh[0], gh[1]);
                mma16816(y[2*n8+1], ph_own[kp], gh[2], gh[3]);
                mma16816(y[2*n8],   pl_own[kp], gh[0], gh[1]);
                mma16816(y[2*n8+1], pl_own[kp], gh[2], gh[3]);
                ldsm4t(gl, sw16(buf + G_L, gr, gch));
                mma16816(y[2*n8],   ph_own[kp], gl[0], gl[1]);
                mma16816(y[2*n8+1], ph_own[kp], gl[2], gl[3]);
            }
        }
        __syncthreads();

        if (jt < 62) {
            u32 nbuf = sb + (u32)cur * BUFSZ;
            size_t jn = (size_t)(jt + 2) * 64 * 64;
            stage_plane_async(nbuf + PH_H, phh + jn, 64, t, 512);
            stage_plane_async(nbuf + PH_L, phl + jn, 64, t, 512);
            stage_plane_async(nbuf + G_H,  ggh + jn, 64, t, 512);
            stage_plane_async(nbuf + G_L,  ggl + jn, 64, t, 512);
            CP_COMMIT();
        }
    }

    // epilogue: exact merge of the two independent softmax halves
    if ((lane & 3) == 0) {
        pm[h*128 + qg0] = m0; pm[h*128 + qg1] = m1;
        ps[h*128 + qg0] = l0; ps[h*128 + qg1] = l1;
    }
    float* ys = (float*)smc;
    float* As = (float*)(smc + S_TH_H);
    for (int i = t; i < OC*IC; i += 512) As[i] = g_A[i];
    __syncthreads();
    float nm0 = fmaxf(pm[qg0], pm[128 + qg0]);
    float nm1 = fmaxf(pm[qg1], pm[128 + qg1]);
    float lt0 = ps[qg0]*fexp(pm[qg0] - nm0) + ps[128 + qg0]*fexp(pm[128 + qg0] - nm0);
    float lt1 = ps[qg1]*fexp(pm[qg1] - nm1) + ps[128 + qg1]*fexp(pm[128 + qg1] - nm1);
    float inv0 = fexp(m0 - nm0) / lt0;
    float inv1 = fexp(m1 - nm1) / lt1;
    if (h == 0) {
        #pragma unroll
        for (int n = 0; n < 16; n++) {
            int c = n*8 + 2*(lane & 3);
            ys[qg0*129 + c]     = y[n][0] * inv0;
            ys[qg0*129 + c + 1] = y[n][1] * inv0;
            ys[qg1*129 + c]     = y[n][2] * inv1;
            ys[qg1*129 + c + 1] = y[n][3] * inv1;
        }
    }
    __syncthreads();
    if (h == 1) {
        #pragma unroll
        for (int n = 0; n < 16; n++) {
            int c = n*8 + 2*(lane & 3);
            ys[qg0*129 + c]     += y[n][0] * inv0;
            ys[qg0*129 + c + 1] += y[n][1] * inv0;
            ys[qg1*129 + c]     += y[n][2] * inv1;
            ys[qg1*129 + c + 1] += y[n][3] * inv1;
        }
    }
    __syncthreads();
    float* ob = out + (size_t)b*OC*NP + n0;
    #pragma unroll
    for (int i = 0; i < 5; i++) {
        int idx = t + i*512;
        int q = idx & 127, o = idx >> 7;
        float acc = 0.f;
        #pragma unroll 8
        for (int c = 0; c < IC; c++) acc = fmaf(As[o*IC+c], ys[q*129+c], acc);
        ob[(size_t)o*NP + q] += acc;
    }
}

extern "C" void kernel_launch(void* const* d_in, const int* in_sizes, int n_in,
                              void* d_out, int out_size)
{
    const float* x1     = (const float*)d_in[0];
    const float* x2     = (const float*)d_in[1];
    const float* w_conv = (const float*)d_in[2];
    const float* w_th   = (const float*)d_in[3];
    const float* w_ph   = (const float*)d_in[4];
    const float* w_g    = (const float*)d_in[5];
    const float* w_W    = (const float*)d_in[6];
    const float* b_W    = (const float*)d_in[7];
    const float* gam    = (const float*)d_in[8];
    const float* bet    = (const float*)d_in[9];
    const float* mean   = (const float*)d_in[10];
    const float* var    = (const float*)d_in[11];
    const float* w_out  = (const float*)d_in[12];
    const float* b_out  = (const float*)d_in[13];
    float* out = (float*)d_out;

    cudaFuncSetAttribute(attn_mma_kernel, cudaFuncAttributeMaxDynamicSharedMemorySize, S_TOTAL);
    cudaFuncSetAttribute(proj_kernel, cudaFuncAttributeMaxDynamicSharedMemorySize, PJ_TOTAL);

    prep_kernel<<<1223, 256>>>(w_conv, w_th, w_ph, w_g, w_W, b_W, gam, bet, mean, var, w_out, b_out);
    prep2_kernel<<<720, 256>>>();
    proj_kernel<<<dim3(32, 3, BB), 256, PJ_TOTAL>>>(x1, x2, out);
    attn_mma_kernel<<<dim3(32, BB), 512, S_TOTAL>>>(out);
}

// round 12
// speedup vs baseline: 3.3231x; 1.0462x over previous
#include <cuda_runtime.h>
#include <cstdint>

typedef unsigned int u32;
typedef unsigned long long u64;

#define BB 8
#define CIN 768
#define NP 4096
#define IC 128
#define MID 256
#define OC 20

// folded weights
__device__ float g_wtpg[3*IC*CIN];
__device__ float g_Cf[OC*CIN];     // residual weights [o][k]
__device__ float g_A[OC*IC];
__device__ float g_cvec[OC];
// pre-split folded weights, bf16 hi/lo planes [3][160][384] (u32 = bf16x2)
// rows 0-127: projection weights; which==0 rows 128-147: C; rest zero
__device__ u32 g_w_h[3*160*384];
__device__ u32 g_w_l[3*160*384];
// projections as bf16 hi/lo planes, [b][n][c] packed bf16x2 (64 u32 per row)
__device__ u32 g_th_h[BB*NP*64];
__device__ u32 g_th_l[BB*NP*64];
__device__ u32 g_ph_h[BB*NP*64];
__device__ u32 g_ph_l[BB*NP*64];
__device__ u32 g_g_h [BB*NP*64];
__device__ u32 g_g_l [BB*NP*64];

__device__ __forceinline__ float fexp(float x){
    x = fmaxf(x, -80.f);
    float t = x * 1.4426950408889634f;
    float f = t + 12582912.f;
    float k = f - 12582912.f;
    float r = t - k;
    float p = 1.3333558e-3f;
    p = fmaf(p, r, 9.6181291e-3f);
    p = fmaf(p, r, 5.5504109e-2f);
    p = fmaf(p, r, 2.4022651e-1f);
    p = fmaf(p, r, 6.9314718e-1f);
    p = fmaf(p, r, 1.f);
    int ki = (int)k;
    return p * __int_as_float((ki + 127) << 23);
}

__device__ __forceinline__ u32 cvtbf2(float a, float b){
    u32 r; asm("cvt.rn.bf16x2.f32 %0, %1, %2;" : "=r"(r) : "f"(b), "f"(a)); return r;
}
__device__ __forceinline__ float blo(u32 u){ return __uint_as_float(u << 16); }
__device__ __forceinline__ float bhi(u32 u){ return __uint_as_float(u & 0xffff0000u); }

__device__ __forceinline__ u32 smem_u32(const void* p){
    u32 a; asm("{ .reg .u64 t; cvta.to.shared.u64 t, %1; cvt.u32.u64 %0, t; }" : "=r"(a) : "l"(p)); return a;
}

// ---------------- mma / ldmatrix ----------------
__device__ __forceinline__ void mma16816(float* d, const u32* a, u32 b0, u32 b1){
    asm volatile("mma.sync.aligned.m16n8k16.row.col.f32.bf16.bf16.f32 "
        "{%0,%1,%2,%3}, {%4,%5,%6,%7}, {%8,%9}, {%0,%1,%2,%3};"
        : "+f"(d[0]), "+f"(d[1]), "+f"(d[2]), "+f"(d[3])
        : "r"(a[0]), "r"(a[1]), "r"(a[2]), "r"(a[3]), "r"(b0), "r"(b1));
}
__device__ __forceinline__ void ldsm4(u32* r, u32 addr){
    asm volatile("ldmatrix.sync.aligned.m8n8.x4.shared.b16 {%0,%1,%2,%3}, [%4];"
        : "=r"(r[0]), "=r"(r[1]), "=r"(r[2]), "=r"(r[3]) : "r"(addr));
}
__device__ __forceinline__ void ldsm4t(u32* r, u32 addr){
    asm volatile("ldmatrix.sync.aligned.m8n8.x4.trans.shared.b16 {%0,%1,%2,%3}, [%4];"
        : "=r"(r[0]), "=r"(r[1]), "=r"(r[2]), "=r"(r[3]) : "r"(addr));
}

// 256B rows (16 chunks of 16B), swizzle chunk ^= (row&7)
__device__ __forceinline__ u32 sw16(u32 base, int row, int ch){
    return base + (u32)row*256u + (u32)((ch ^ (row & 7)) * 16);
}
// 128B rows (8 chunks of 16B)
__device__ __forceinline__ u32 sw8(u32 base, int row, int ch){
    return base + (u32)row*128u + (u32)((ch ^ (row & 7)) * 16);
}

#define CP16(dst, src) asm volatile("cp.async.cg.shared.global [%0], [%1], 16;" :: "r"(dst), "l"(src) : "memory")
#define CP_COMMIT()    asm volatile("cp.async.commit_group;" ::: "memory")
#define CP_WAIT1()     asm volatile("cp.async.wait_group 1;" ::: "memory")
#define CP_WAIT0()     asm volatile("cp.async.wait_group 0;" ::: "memory")

// ---------------- prep ----------------
__global__ void __launch_bounds__(256) prep_kernel(
    const float* __restrict__ wc, const float* __restrict__ wt,
    const float* __restrict__ wp, const float* __restrict__ wg,
    const float* __restrict__ wW, const float* __restrict__ bW,
    const float* __restrict__ gam, const float* __restrict__ bet,
    const float* __restrict__ mean, const float* __restrict__ var,
    const float* __restrict__ wo, const float* __restrict__ bo)
{
    int gid = blockIdx.x*256 + threadIdx.x;
    if (gid < 3*IC*CIN) {
        int r = gid / CIN, k = gid % CIN;
        const float* ws = (r < IC) ? wt : (r < 2*IC) ? wp : wg;
        int rr = r & (IC-1);
        float acc = 0.f;
        for (int m = 0; m < MID; m++) acc = fmaf(ws[rr*MID+m], wc[m*CIN+k], acc);
        g_wtpg[gid] = acc;
        return;
    }
    int idx = gid - 3*IC*CIN;
    if (idx < OC*CIN) {
        int o = idx / CIN, k = idx % CIN;
        float acc = 0.f;
        for (int m = 0; m < MID; m++) acc = fmaf(wo[o*MID+m], wc[m*CIN+k], acc);
        g_Cf[o*CIN + k] = acc;
        return;
    }
    idx -= OC*CIN;
    if (idx < OC*IC) {
        int o = idx / IC, i = idx % IC;
        float acc = 0.f;
        for (int m = 0; m < MID; m++) {
            float inv = gam[m] * rsqrtf(var[m] + 1e-5f);
            acc = fmaf(wo[o*MID+m]*inv, wW[m*IC+i], acc);
        }
        g_A[idx] = acc;
        return;
    }
    idx -= OC*IC;
    if (idx < OC) {
        float acc = bo[idx];
        for (int m = 0; m < MID; m++) {
            float inv = gam[m] * rsqrtf(var[m] + 1e-5f);
            acc += wo[idx*MID+m] * (bW[m]*inv + bet[m] - mean[m]*inv);
        }
        g_cvec[idx] = acc;
    }
}

// pack folded weights (+ resid rows for which==0) into bf16 hi/lo planes
__global__ void __launch_bounds__(256) prep2_kernel()
{
    int gid = blockIdx.x*256 + threadIdx.x;
    if (gid >= 3*160*384) return;
    int which = gid / (160*384);
    int rem = gid % (160*384);
    int r = rem / 384, kk = rem % 384;
    float f0 = 0.f, f1 = 0.f;
    if (r < 128) {
        f0 = g_wtpg[(which*IC + r)*CIN + 2*kk];
        f1 = g_wtpg[(which*IC + r)*CIN + 2*kk + 1];
    } else if (which == 0 && r < 148) {
        f0 = g_Cf[(r-128)*CIN + 2*kk];
        f1 = g_Cf[(r-128)*CIN + 2*kk + 1];
    }
    u32 h = cvtbf2(f0, f1);
    g_w_h[gid] = h;
    g_w_l[gid] = cvtbf2(f0 - blo(h), f1 - bhi(h));
}

// ---------------- tensorized projections + fused residual, cp.async pipelined ----------------
#define PJ_XRAW 81920
#define PJ_XH0  147456
#define PJ_TOTAL 212992
#define WBUF 40960
#define WPL  20480

__global__ void __launch_bounds__(256) proj_kernel(const float* __restrict__ x1,
                                                   const float* __restrict__ x2,
                                                   float* __restrict__ out)
{
    extern __shared__ char smc[];
    u32 sb = smem_u32(smc);
    int t = threadIdx.x, lane = t & 31, w = t >> 5;
    int n0 = blockIdx.x * 128;
    int which = blockIdx.y;
    int b = blockIdx.z;
    const float* xb = (which == 0 ? x1 : x2) + (size_t)b * CIN * NP;
    const u32* wbase_h = g_w_h + (size_t)which * 160 * 384;
    const u32* wbase_l = g_w_l + (size_t)which * 160 * 384;

    int la15 = lane & 15, la7 = lane & 7;
    int lahalf = (lane >> 3) & 1, laq = lane >> 4;

    float acc[16][4];
    #pragma unroll
    for (int n = 0; n < 16; n++)
        #pragma unroll
        for (int i = 0; i < 4; i++) acc[n][i] = 0.f;
    float accr[2][2][4];
    #pragma unroll
    for (int mt = 0; mt < 2; mt++)
        #pragma unroll
        for (int cp = 0; cp < 2; cp++)
            #pragma unroll
            for (int i = 0; i < 4; i++) accr[mt][cp][i] = 0.f;

    #define PJ_STAGE(c_) do { \
        int cur_ = (c_) & 1; int k0_ = (c_) * 64; \
        _Pragma("unroll") \
        for (int i = 0; i < 10; i++) { \
            int e = t + i*256; \
            int p = (i >= 5); \
            int rest = e - p*1280; \
            int ch = rest >> 3, q = rest & 7; \
            u32 dst = sb + (u32)cur_*WBUF + (u32)p*WPL + (u32)ch*128u + (u32)(((q ^ (ch & 7)))*16); \
            const u32* src = (p ? wbase_l : wbase_h) + (size_t)ch*384 + (k0_ >> 1) + q*4; \
            CP16(dst, src); \
        } \
        _Pragma("unroll") \
        for (int i = 0; i < 8; i++) { \
            int e = t + i*256; \
            int r = e >> 5, cc = e & 31; \
            u32 dst = sb + PJ_XRAW + (u32)cur_*32768u + (u32)r*512u + (u32)cc*16u; \
            const float* src = xb + (size_t)(k0_ + r)*NP + n0 + cc*4; \
            CP16(dst, src); \
        } \
        CP_COMMIT(); \
    } while(0)

    PJ_STAGE(0);
    for (int c = 0; c < 12; c++) {
        int cur = c & 1;
        CP_WAIT0();
        __syncthreads();
        if (c < 11) PJ_STAGE(c + 1);

        u32 xh = sb + PJ_XH0 + (u32)cur*32768u;
        u32 xl = xh + 16384u;
        #pragma unroll
        for (int i = 0; i < 8; i++) {
            int e = t + i*256;
            int k = e >> 5, nq = e & 31;
            float4 v = *(const float4*)(smc + PJ_XRAW + cur*32768 + k*512 + nq*16);
            u32 h0 = cvtbf2(v.x, v.y), h1 = cvtbf2(v.z, v.w);
            u32 l0 = cvtbf2(v.x - blo(h0), v.y - bhi(h0));
            u32 l1 = cvtbf2(v.z - blo(h1), v.w - bhi(h1));
            u32 off = (u32)k*256u + (u32)((((nq>>1) ^ (k&7)))*16) + (u32)((nq&1)*8);
            *(uint2*)(smc + (xh - sb) + off) = make_uint2(h0, h1);
            *(uint2*)(smc + (xl - sb) + off) = make_uint2(l0, l1);
        }
        __syncthreads();

        u32 wh = sb + (u32)cur*WBUF, wl = wh + WPL;
        #pragma unroll
        for (int ks = 0; ks < 4; ks++) {
            u32 ah[4], al[4];
            int ar = w*16 + la15, ach = 2*ks + laq;
            ldsm4(ah, sw8(wh, ar, ach));
            ldsm4(al, sw8(wl, ar, ach));
            int kr = ks*16 + lahalf*8 + la7;
            #pragma unroll
            for (int nn = 0; nn < 8; nn++) {
                int bch = 2*nn + laq;
                u32 bh[4], bl[4];
                ldsm4t(bh, sw16(xh, kr, bch));
                mma16816(acc[2*nn],   ah, bh[0], bh[1]);
                mma16816(acc[2*nn+1], ah, bh[2], bh[3]);
                mma16816(acc[2*nn],   al, bh[0], bh[1]);
                mma16816(acc[2*nn+1], al, bh[2], bh[3]);
                ldsm4t(bl, sw16(xl, kr, bch));
                mma16816(acc[2*nn],   ah, bl[0], bl[1]);
                mma16816(acc[2*nn+1], ah, bl[2], bl[3]);
            }
            if (which == 0) {
                u32 bhs[4], bls[4];
                ldsm4t(bhs, sw16(xh, kr, 2*w + laq));
                ldsm4t(bls, sw16(xl, kr, 2*w + laq));
                #pragma unroll
                for (int mt = 0; mt < 2; mt++) {
                    u32 arh[4], arl[4];
                    ldsm4(arh, sw8(wh, 128 + mt*16 + la15, ach));
                    ldsm4(arl, sw8(wl, 128 + mt*16 + la15, ach));
                    mma16816(accr[mt][0], arh, bhs[0], bhs[1]);
                    mma16816(accr[mt][1], arh, bhs[2], bhs[3]);
                    mma16816(accr[mt][0], arl, bhs[0], bhs[1]);
                    mma16816(accr[mt][1], arl, bhs[2], bhs[3]);
                    mma16816(accr[mt][0], arh, bls[0], bls[1]);
                    mma16816(accr[mt][1], arh, bls[2], bls[3]);
                }
            }
        }
    }
    #undef PJ_STAGE

    if (which == 0) {
        float* ob = out + (size_t)b*OC*NP + n0;
        #pragma unroll
        for (int mt = 0; mt < 2; mt++) {
            #pragma unroll
            for (int cp = 0; cp < 2; cp++) {
                int o0 = mt*16 + (lane >> 2);
                int o1 = o0 + 8;
                int col = w*16 + cp*8 + 2*(lane & 3);
                if (o0 < OC) {
                    ob[(size_t)o0*NP + col]     = accr[mt][cp][0] + g_cvec[o0];
                    ob[(size_t)o0*NP + col + 1] = accr[mt][cp][1] + g_cvec[o0];
                }
                if (o1 < OC) {
                    ob[(size_t)o1*NP + col]     = accr[mt][cp][2] + g_cvec[o1];
                    ob[(size_t)o1*NP + col + 1] = accr[mt][cp][3] + g_cvec[o1];
                }
            }
        }
    }

    __syncthreads();
    float* outS = (float*)smc;
    {
        int r = w*16 + (lane >> 2);
        #pragma unroll
        for (int nn = 0; nn < 16; nn++) {
            int n = nn*8 + 2*(lane & 3);
            outS[r*133 + n]         = acc[nn][0];
            outS[r*133 + n + 1]     = acc[nn][1];
            outS[(r+8)*133 + n]     = acc[nn][2];
            outS[(r+8)*133 + n + 1] = acc[nn][3];
        }
    }
    __syncthreads();

    u32* dh = (which==0 ? g_th_h : which==1 ? g_ph_h : g_g_h) + (size_t)b*NP*64;
    u32* dl = (which==0 ? g_th_l : which==1 ? g_ph_l : g_g_l) + (size_t)b*NP*64;
    {
        int n = t >> 1, half = t & 1;
        u32 hb[32], lb[32];
        #pragma unroll
        for (int p = 0; p < 32; p++) {
            int c = half*64 + 2*p;
            float f0 = outS[c*133 + n];
            float f1 = outS[(c+1)*133 + n];
            u32 h = cvtbf2(f0, f1);
            hb[p] = h;
            lb[p] = cvtbf2(f0 - blo(h), f1 - bhi(h));
        }
        u32* ph_ = dh + (size_t)(n0 + n)*64 + half*32;
        u32* pl_ = dl + (size_t)(n0 + n)*64 + half*32;
        #pragma unroll
        for (int q = 0; q < 8; q++) {
            *(uint4*)(ph_ + q*4) = make_uint4(hb[4*q], hb[4*q+1], hb[4*q+2], hb[4*q+3]);
            *(uint4*)(pl_ + q*4) = make_uint4(lb[4*q], lb[4*q+1], lb[4*q+2], lb[4*q+3]);
        }
    }
}

// ---------------- warp-pair MMA flash attention, frozen-reference softmax ----------------
#define PH_H 0
#define PH_L 16384
#define G_H  32768
#define G_L  49152
#define BUFSZ 65536
#define S_TH_H 131072
#define S_TH_L 163840
#define S_PM   196608
#define S_PS   197632
#define S_TOTAL 198656

__device__ __forceinline__ void stage_plane_async(u32 sdst, const u32* __restrict__ src,
                                                  int rows, int t, int nthr){
    for (int idx = t; idx < rows*16; idx += nthr) {
        int r = idx >> 4, ch = idx & 15;
        CP16(sdst + (u32)r*256u + (u32)((ch ^ (r & 7)) * 16), src + (size_t)r*64 + ch*4);
    }
}

__global__ void __launch_bounds__(512) attn_mma_kernel(float* __restrict__ out)
{
    extern __shared__ char smc[];
    u32 sb = smem_u32(smc);
    int t = threadIdx.x, lane = t & 31, w = t >> 5;
    int wp = w >> 1, h = w & 1;
    int b = blockIdx.y;
    int n0 = blockIdx.x * 128;
    size_t bn = (size_t)b * NP;

    float* pm = (float*)(smc + S_PM);
    float* ps = (float*)(smc + S_PS);

    const u32* phh = g_ph_h + bn*64;
    const u32* phl = g_ph_l + bn*64;
    const u32* ggh = g_g_h  + bn*64;
    const u32* ggl = g_g_l  + bn*64;

    stage_plane_async(sb + S_TH_H, g_th_h + (bn + n0)*64, 128, t, 512);
    stage_plane_async(sb + S_TH_L, g_th_l + (bn + n0)*64, 128, t, 512);
    stage_plane_async(sb + PH_H, phh, 64, t, 512);
    stage_plane_async(sb + PH_L, phl, 64, t, 512);
    stage_plane_async(sb + G_H,  ggh, 64, t, 512);
    stage_plane_async(sb + G_L,  ggl, 64, t, 512);
    CP_COMMIT();
    {
        size_t jn = (size_t)64 * 64;
        stage_plane_async(sb + BUFSZ + PH_H, phh + jn, 64, t, 512);
        stage_plane_async(sb + BUFSZ + PH_L, phl + jn, 64, t, 512);
        stage_plane_async(sb + BUFSZ + G_H,  ggh + jn, 64, t, 512);
        stage_plane_async(sb + BUFSZ + G_L,  ggl + jn, 64, t, 512);
        CP_COMMIT();
    }

    float y[16][4];
    #pragma unroll
    for (int n = 0; n < 16; n++)
        #pragma unroll
        for (int i = 0; i < 4; i++) y[n][i] = 0.f;
    float m0 = 0.f, m1 = 0.f;      // frozen reference after tile 0
    float l0 = 0.f, l1 = 0.f;      // per-lane partial sums (reduced at epilogue)

    int la15 = lane & 15, la7 = lane & 7;
    int lahalf = (lane >> 3) & 1, laq = lane >> 4;
    int r0 = lane >> 2;
    int qg0 = wp*16 + r0, qg1 = qg0 + 8;

    for (int jt = 0; jt < 64; jt++) {
        int cur = jt & 1;
        u32 buf = sb + (u32)cur * BUFSZ;
        if (jt < 63) CP_WAIT1(); else CP_WAIT0();
        __syncthreads();

        // ---- QK: S[16q x 32j] (warp's j-half) ----
        float S[4][4];
        #pragma unroll
        for (int n = 0; n < 4; n++)
            #pragma unroll
            for (int i = 0; i < 4; i++) S[n][i] = 0.f;

        #pragma unroll
        for (int k = 0; k < 8; k++) {
            u32 ah[4], al[4];
            int ar = wp*16 + la15, ach = 2*k + laq;
            ldsm4(ah, sw16(sb + S_TH_H, ar, ach));
            ldsm4(al, sw16(sb + S_TH_L, ar, ach));
            #pragma unroll
            for (int n4 = 0; n4 < 2; n4++) {
                int br = h*32 + (n4*2 + laq)*8 + la7;
                int bch = 2*k + lahalf;
                u32 bh[4], bl[4];
                ldsm4(bh, sw16(buf + PH_H, br, bch));
                mma16816(S[2*n4],   ah, bh[0], bh[1]);
                mma16816(S[2*n4+1], ah, bh[2], bh[3]);
                mma16816(S[2*n4],   al, bh[0], bh[1]);
                mma16816(S[2*n4+1], al, bh[2], bh[3]);
                ldsm4(bl, sw16(buf + PH_L, br, bch));
                mma16816(S[2*n4],   ah, bl[0], bl[1]);
                mma16816(S[2*n4+1], ah, bl[2], bl[3]);
            }
        }

        // ---- frozen-reference softmax: set m from tile 0, never rescale ----
        if (jt == 0) {
            float tm0 = -1e30f, tm1 = -1e30f;
            #pragma unroll
            for (int n = 0; n < 4; n++) {
                tm0 = fmaxf(tm0, fmaxf(S[n][0], S[n][1]));
                tm1 = fmaxf(tm1, fmaxf(S[n][2], S[n][3]));
            }
            tm0 = fmaxf(tm0, __shfl_xor_sync(0xffffffffu, tm0, 1));
            tm0 = fmaxf(tm0, __shfl_xor_sync(0xffffffffu, tm0, 2));
            tm1 = fmaxf(tm1, __shfl_xor_sync(0xffffffffu, tm1, 1));
            tm1 = fmaxf(tm1, __shfl_xor_sync(0xffffffffu, tm1, 2));
            m0 = tm0; m1 = tm1;
        }

        #pragma unroll
        for (int n = 0; n < 4; n++) {
            S[n][0] = fexp(S[n][0] - m0);
            S[n][1] = fexp(S[n][1] - m0);
            S[n][2] = fexp(S[n][2] - m1);
            S[n][3] = fexp(S[n][3] - m1);
            l0 += S[n][0] + S[n][1];
            l1 += S[n][2] + S[n][3];
        }

        // ---- P -> bf16 hi/lo own fragments ----
        u32 ph_own[2][4], pl_own[2][4];
        #pragma unroll
        for (int kp = 0; kp < 2; kp++) {
            float* sa  = S[2*kp];
            float* sb2 = S[2*kp+1];
            u32 h0 = cvtbf2(sa[0], sa[1]);
            u32 h1 = cvtbf2(sa[2], sa[3]);
            u32 h2 = cvtbf2(sb2[0], sb2[1]);
            u32 h3 = cvtbf2(sb2[2], sb2[3]);
            ph_own[kp][0]=h0; ph_own[kp][1]=h1; ph_own[kp][2]=h2; ph_own[kp][3]=h3;
            pl_own[kp][0] = cvtbf2(sa[0]-blo(h0), sa[1]-bhi(h0));
            pl_own[kp][1] = cvtbf2(sa[2]-blo(h1), sa[3]-bhi(h1));
            pl_own[kp][2] = cvtbf2(sb2[0]-blo(h2), sb2[1]-bhi(h2));
            pl_own[kp][3] = cvtbf2(sb2[2]-blo(h3), sb2[3]-bhi(h3));
        }

        // ---- PV: y[16q x 128c], own 32 j only, no rescale ----
        #pragma unroll
        for (int kp = 0; kp < 2; kp++) {
            int gr = h*32 + kp*16 + lahalf*8 + la7;
            #pragma unroll
            for (int n8 = 0; n8 < 8; n8++) {
                int gch = 2*n8 + laq;
                u32 gh[4], gl[4];
                ldsm4t(gh, sw16(buf + G_H, gr, gch));
                mma16816(y[2*n8],   ph_own[kp], gh[0], gh[1]);
                mma16816(y[2*n8+1], ph_own[kp], gh[2], gh[3]);
                mma16816(y[2*n8],   pl_own[kp], gh[0], gh[1]);
                mma16816(y[2*n8+1], pl_own[kp], gh[2], gh[3]);
                ldsm4t(gl, sw16(buf + G_L, gr, gch));
                mma16816(y[2*n8],   ph_own[kp], gl[0], gl[1]);
                mma16816(y[2*n8+1], ph_own[kp], gl[2], gl[3]);
            }
        }
        __syncthreads();

        if (jt < 62) {
            u32 nbuf = sb + (u32)cur * BUFSZ;
            size_t jn = (size_t)(jt + 2) * 64 * 64;
            stage_plane_async(nbuf + PH_H, phh + jn, 64, t, 512);
            stage_plane_async(nbuf + PH_L, phl + jn, 64, t, 512);
            stage_plane_async(nbuf + G_H,  ggh + jn, 64, t, 512);
            stage_plane_async(nbuf + G_L,  ggl + jn, 64, t, 512);
            CP_COMMIT();
        }
    }

    // ---- epilogue: reduce l, merge the two independent halves exactly ----
    l0 += __shfl_xor_sync(0xffffffffu, l0, 1);
    l0 += __shfl_xor_sync(0xffffffffu, l0, 2);
    l1 += __shfl_xor_sync(0xffffffffu, l1, 1);
    l1 += __shfl_xor_sync(0xffffffffu, l1, 2);
    if ((lane & 3) == 0) {
        pm[h*128 + qg0] = m0; pm[h*128 + qg1] = m1;
        ps[h*128 + qg0] = l0; ps[h*128 + qg1] = l1;
    }
    float* ys = (float*)smc;
    float* As = (float*)(smc + S_TH_H);
    for (int i = t; i < OC*IC; i += 512) As[i] = g_A[i];
    __syncthreads();
    float nm0 = fmaxf(pm[qg0], pm[128 + qg0]);
    float nm1 = fmaxf(pm[qg1], pm[128 + qg1]);
    float lt0 = ps[qg0]*fexp(pm[qg0] - nm0) + ps[128 + qg0]*fexp(pm[128 + qg0] - nm0);
    float lt1 = ps[qg1]*fexp(pm[qg1] - nm1) + ps[128 + qg1]*fexp(pm[128 + qg1] - nm1);
    float inv0 = fexp(m0 - nm0) / lt0;
    float inv1 = fexp(m1 - nm1) / lt1;
    if (h == 0) {
        #pragma unroll
        for (int n = 0; n < 16; n++) {
            int c = n*8 + 2*(lane & 3);
            ys[qg0*129 + c]     = y[n][0] * inv0;
            ys[qg0*129 + c + 1] = y[n][1] * inv0;
            ys[qg1*129 + c]     = y[n][2] * inv1;
            ys[qg1*129 + c + 1] = y[n][3] * inv1;
        }
    }
    __syncthreads();
    if (h == 1) {
        #pragma unroll
        for (int n = 0; n < 16; n++) {
            int c = n*8 + 2*(lane & 3);
            ys[qg0*129 + c]     += y[n][0] * inv0;
            ys[qg0*129 + c + 1] += y[n][1] * inv0;
            ys[qg1*129 + c]     += y[n][2] * inv1;
            ys[qg1*129 + c + 1] += y[n][3] * inv1;
        }
    }
    __syncthreads();
    float* ob = out + (size_t)b*OC*NP + n0;
    #pragma unroll
    for (int i = 0; i < 5; i++) {
        int idx = t + i*512;
        int q = idx & 127, o = idx >> 7;
        float acc = 0.f;
        #pragma unroll 8
        for (int c = 0; c < IC; c++) acc = fmaf(As[o*IC+c], ys[q*129+c], acc);
        ob[(size_t)o*NP + q] += acc;
    }
}

extern "C" void kernel_launch(void* const* d_in, const int* in_sizes, int n_in,
                              void* d_out, int out_size)
{
    const float* x1     = (const float*)d_in[0];
    const float* x2     = (const float*)d_in[1];
    const float* w_conv = (const float*)d_in[2];
    const float* w_th   = (const float*)d_in[3];
    const float* w_ph   = (const float*)d_in[4];
    const float* w_g    = (const float*)d_in[5];
    const float* w_W    = (const float*)d_in[6];
    const float* b_W    = (const float*)d_in[7];
    const float* gam    = (const float*)d_in[8];
    const float* bet    = (const float*)d_in[9];
    const float* mean   = (const float*)d_in[10];
    const float* var    = (const float*)d_in[11];
    const float* w_out  = (const float*)d_in[12];
    const float* b_out  = (const float*)d_in[13];
    float* out = (float*)d_out;

    cudaFuncSetAttribute(attn_mma_kernel, cudaFuncAttributeMaxDynamicSharedMemorySize, S_TOTAL);
    cudaFuncSetAttribute(proj_kernel, cudaFuncAttributeMaxDynamicSharedMemorySize, PJ_TOTAL);

    prep_kernel<<<1223, 256>>>(w_conv, w_th, w_ph, w_g, w_W, b_W, gam, bet, mean, var, w_out, b_out);
    prep2_kernel<<<720, 256>>>();
    proj_kernel<<<dim3(32, 3, BB), 256, PJ_TOTAL>>>(x1, x2, out);
    attn_mma_kernel<<<dim3(32, BB), 512, S_TOTAL>>>(out);
}